// round 1
// baseline (speedup 1.0000x reference)
#include <cuda_runtime.h>
#include <cuda_bf16.h>
#include <math.h>

#define D_MODEL 2048
#define NHEAD   16
#define DKH     128
#define DFF     5632
#define SEQ     2048
#define BATCH   2
#define M_TOK   (BATCH*SEQ)   // 4096

// ---------------- scratch (no cudaMalloc allowed) ----------------
__device__ float g_xn  [(size_t)M_TOK*D_MODEL];
__device__ float g_q   [(size_t)M_TOK*D_MODEL];
__device__ float g_k   [(size_t)M_TOK*D_MODEL];
__device__ float g_v   [(size_t)M_TOK*D_MODEL];
__device__ float g_ctx [(size_t)M_TOK*D_MODEL];
__device__ float g_xmid[(size_t)M_TOK*D_MODEL];
__device__ float g_ff  [(size_t)M_TOK*DFF];
__device__ float g_rsin[SEQ*64];
__device__ float g_rcos[SEQ*64];

// ---------------- RMSNorm ----------------
__global__ void rmsnorm_kernel(const float* __restrict__ x,
                               const float* __restrict__ g,
                               float* __restrict__ out) {
    int row = blockIdx.x;
    const float* xr = x + (size_t)row * D_MODEL;
    float*       orow = out + (size_t)row * D_MODEL;
    float s = 0.f;
    for (int i = threadIdx.x; i < D_MODEL; i += blockDim.x) {
        float v = xr[i];
        s += v * v;
    }
    __shared__ float red[32];
    for (int o = 16; o; o >>= 1) s += __shfl_down_sync(0xffffffffu, s, o);
    if ((threadIdx.x & 31) == 0) red[threadIdx.x >> 5] = s;
    __syncthreads();
    if (threadIdx.x < 32) {
        float v = (threadIdx.x < (blockDim.x >> 5)) ? red[threadIdx.x] : 0.f;
        for (int o = 16; o; o >>= 1) v += __shfl_down_sync(0xffffffffu, v, o);
        if (threadIdx.x == 0) red[0] = v;
    }
    __syncthreads();
    float rinv = rsqrtf(red[0] * (1.0f / D_MODEL) + 1e-5f);
    for (int i = threadIdx.x; i < D_MODEL; i += blockDim.x)
        orow[i] = xr[i] * g[i] * rinv;
}

// ---------------- SGEMM: C[M,N] = A[M,K] @ W[N,K]^T, templated epilogue ----
// EPI 0: C = acc
// EPI 1: C = res + acc
// EPI 2: C = silu(C_old) * acc   (SwiGLU combine; C_old holds W1 result)
template<int EPI>
__global__ void gemm_nt(const float* __restrict__ A,
                        const float* __restrict__ W,
                        const float* __restrict__ res,
                        float* __restrict__ C,
                        int M, int N, int K) {
    const int BM = 64, BN = 64, BK = 16, LDT = BM + 4; // padded smem rows
    __shared__ float As[BK][LDT];
    __shared__ float Bs[BK][LDT];
    int bm = blockIdx.y * BM, bn = blockIdx.x * BN;
    int t  = threadIdx.x;            // 256 threads
    int tx = t & 15, ty = t >> 4;
    int lr = t >> 2;                 // 0..63 (row within tile)
    int lc = (t & 3) * 4;            // 0,4,8,12 (k offset)
    const float* Aptr = A + (size_t)(bm + lr) * K + lc;
    const float* Wptr = W + (size_t)(bn + lr) * K + lc;
    float acc[4][4] = {};
    for (int k0 = 0; k0 < K; k0 += BK) {
        float4 a = *(const float4*)(Aptr + k0);
        float4 b = *(const float4*)(Wptr + k0);
        As[lc + 0][lr] = a.x; As[lc + 1][lr] = a.y;
        As[lc + 2][lr] = a.z; As[lc + 3][lr] = a.w;
        Bs[lc + 0][lr] = b.x; Bs[lc + 1][lr] = b.y;
        Bs[lc + 2][lr] = b.z; Bs[lc + 3][lr] = b.w;
        __syncthreads();
#pragma unroll
        for (int kk = 0; kk < BK; kk++) {
            float4 am = *(const float4*)&As[kk][ty * 4];
            float4 bm4 = *(const float4*)&Bs[kk][tx * 4];
            float ar[4] = {am.x, am.y, am.z, am.w};
            float br[4] = {bm4.x, bm4.y, bm4.z, bm4.w};
#pragma unroll
            for (int i = 0; i < 4; i++)
#pragma unroll
                for (int j = 0; j < 4; j++)
                    acc[i][j] += ar[i] * br[j];
        }
        __syncthreads();
    }
#pragma unroll
    for (int i = 0; i < 4; i++) {
        int m = bm + ty * 4 + i;
#pragma unroll
        for (int j = 0; j < 4; j++) {
            int n = bn + tx * 4 + j;
            size_t idx = (size_t)m * N + n;
            float v = acc[i][j];
            if (EPI == 1) v += res[idx];
            else if (EPI == 2) {
                float a0 = C[idx];
                v = (a0 / (1.f + __expf(-a0))) * v;
            }
            C[idx] = v;
        }
    }
}

// ---------------- RoPE ----------------
__global__ void rope_table_kernel() {
    int idx = blockIdx.x * blockDim.x + threadIdx.x;
    if (idx >= SEQ * 64) return;
    int j = idx & 63, s = idx >> 6;
    double inv = exp(-(double)j * (9.210340371976184 / 64.0)); // 10000^(-j/64)
    double ang = (double)s * inv;
    g_rsin[idx] = (float)sin(ang);
    g_rcos[idx] = (float)cos(ang);
}

__global__ void rope_apply_kernel(float* __restrict__ Qd, float* __restrict__ Kd) {
    int idx = blockIdx.x * blockDim.x + threadIdx.x;
    if (idx >= M_TOK * NHEAD * 64) return;
    int j    = idx & 63;
    int rest = idx >> 6;
    int h    = rest & (NHEAD - 1);
    int tok  = rest >> 4;
    int s    = tok & (SEQ - 1);
    float sn = g_rsin[(s << 6) | j];
    float cs = g_rcos[(s << 6) | j];
    size_t base = (size_t)tok * D_MODEL + h * DKH + 2 * j;
    float q1 = Qd[base], q2 = Qd[base + 1];
    Qd[base]     = q1 * cs - q2 * sn;
    Qd[base + 1] = q1 * sn + q2 * cs;
    float k1 = Kd[base], k2 = Kd[base + 1];
    Kd[base]     = k1 * cs - k2 * sn;
    Kd[base + 1] = k1 * sn + k2 * cs;
}

// ---------------- Flash attention (causal, online softmax) ----------------
// layout: Q/K/V/O as [B,S,H,dk] flattened to [tok, D_MODEL] with head offset.
// grid: (SEQ/32, BATCH*NHEAD), 256 threads.
#define BQ  32
#define BKT 64
#define LDA (DKH + 4)
__global__ void attn_kernel(const float* __restrict__ Q,
                            const float* __restrict__ K,
                            const float* __restrict__ V,
                            float* __restrict__ O) {
    extern __shared__ float sm[];
    float* Qs = sm;                      // BQ  * LDA
    float* Ks = Qs + BQ * LDA;           // BKT * LDA
    float* Vs = Ks + BKT * LDA;          // BKT * LDA
    float* Ss = Vs + BKT * LDA;          // BQ  * BKT

    int t  = threadIdx.x;
    int bh = blockIdx.y;
    int b  = bh / NHEAD, h = bh % NHEAD;
    int q0 = blockIdx.x * BQ;

    // load Q tile
    for (int i = t; i < BQ * (DKH / 4); i += 256) {
        int q = i / (DKH / 4), d4 = i % (DKH / 4);
        float4 v = *(const float4*)(Q + (size_t)(b * SEQ + q0 + q) * D_MODEL + h * DKH + d4 * 4);
        *(float4*)(Qs + q * LDA + d4 * 4) = v;
    }

    int lane = t & 7;      // 8 lanes per query row
    int q    = t >> 3;     // 0..31
    float o[4][4] = {};    // dims owned: d = lane*4 + 32*i + c
    float m_i = -1e30f, l_i = 0.f;

    int kend = q0 + BQ;    // exclusive (causal)
    for (int k0 = 0; k0 < kend; k0 += BKT) {
        __syncthreads();
        for (int i = t; i < BKT * (DKH / 4); i += 256) {
            int kk = i / (DKH / 4), d4 = i % (DKH / 4);
            size_t g = (size_t)(b * SEQ + k0 + kk) * D_MODEL + h * DKH + d4 * 4;
            *(float4*)(Ks + kk * LDA + d4 * 4) = *(const float4*)(K + g);
            *(float4*)(Vs + kk * LDA + d4 * 4) = *(const float4*)(V + g);
        }
        __syncthreads();

        // scores for k = lane + 8*ii
        float sc[8];
        const float4* qp = (const float4*)(Qs + q * LDA);
#pragma unroll
        for (int ii = 0; ii < 8; ii++) {
            int k = lane + 8 * ii;
            const float4* kp = (const float4*)(Ks + k * LDA);
            float s = 0.f;
#pragma unroll
            for (int d = 0; d < DKH / 4; d++) {
                float4 a = qp[d], bb = kp[d];
                s += a.x * bb.x + a.y * bb.y + a.z * bb.z + a.w * bb.w;
            }
            s *= 0.08838834764831845f;   // 1/sqrt(128)
            if (k0 + k > q0 + q) s = -1e30f;
            sc[ii] = s;
        }
        // row max (butterfly over the 8 lanes of this row)
        float mt = sc[0];
#pragma unroll
        for (int ii = 1; ii < 8; ii++) mt = fmaxf(mt, sc[ii]);
        for (int off = 1; off < 8; off <<= 1)
            mt = fmaxf(mt, __shfl_xor_sync(0xffffffffu, mt, off));
        float mnew = fmaxf(m_i, mt);
        float lsum = 0.f;
#pragma unroll
        for (int ii = 0; ii < 8; ii++) {
            float p = __expf(sc[ii] - mnew);
            Ss[q * BKT + lane + 8 * ii] = p;
            lsum += p;
        }
        for (int off = 1; off < 8; off <<= 1)
            lsum += __shfl_xor_sync(0xffffffffu, lsum, off);
        float alpha = __expf(m_i - mnew);
        l_i = l_i * alpha + lsum;
        m_i = mnew;
#pragma unroll
        for (int i = 0; i < 4; i++)
#pragma unroll
            for (int c = 0; c < 4; c++) o[i][c] *= alpha;
        __syncwarp();
        // O += P @ V
        for (int k = 0; k < BKT; k++) {
            float p = Ss[q * BKT + k];
            const float* vrow = Vs + k * LDA;
#pragma unroll
            for (int i = 0; i < 4; i++) {
                float4 vv = *(const float4*)(vrow + lane * 4 + 32 * i);
                o[i][0] += p * vv.x; o[i][1] += p * vv.y;
                o[i][2] += p * vv.z; o[i][3] += p * vv.w;
            }
        }
        __syncwarp();
    }
    float linv = 1.f / l_i;
    size_t obase = (size_t)(b * SEQ + q0 + q) * D_MODEL + h * DKH;
#pragma unroll
    for (int i = 0; i < 4; i++) {
        float4 vv;
        vv.x = o[i][0] * linv; vv.y = o[i][1] * linv;
        vv.z = o[i][2] * linv; vv.w = o[i][3] * linv;
        *(float4*)(O + obase + lane * 4 + 32 * i) = vv;
    }
}

// ---------------- launch ----------------
extern "C" void kernel_launch(void* const* d_in, const int* in_sizes, int n_in,
                              void* d_out, int out_size) {
    const float* x  = (const float*)d_in[0];
    const float* Wq = (const float*)d_in[1];
    const float* Wk = (const float*)d_in[2];
    const float* Wv = (const float*)d_in[3];
    const float* Wo = (const float*)d_in[4];
    const float* W1 = (const float*)d_in[5];
    const float* W2 = (const float*)d_in[6];
    const float* W3 = (const float*)d_in[7];
    const float* g1 = (const float*)d_in[8];
    const float* g2 = (const float*)d_in[9];
    float* out = (float*)d_out;

    float *xn, *qb, *kb, *vb, *ctx, *xmid, *ffb;
    cudaGetSymbolAddress((void**)&xn,   g_xn);
    cudaGetSymbolAddress((void**)&qb,   g_q);
    cudaGetSymbolAddress((void**)&kb,   g_k);
    cudaGetSymbolAddress((void**)&vb,   g_v);
    cudaGetSymbolAddress((void**)&ctx,  g_ctx);
    cudaGetSymbolAddress((void**)&xmid, g_xmid);
    cudaGetSymbolAddress((void**)&ffb,  g_ff);

    // attn smem
    int attn_smem = (BQ * LDA + 2 * BKT * LDA + BQ * BKT) * (int)sizeof(float);
    cudaFuncSetAttribute(attn_kernel, cudaFuncAttributeMaxDynamicSharedMemorySize, attn_smem);

    dim3 blk(256);
    // 1. RMSNorm 1
    rmsnorm_kernel<<<M_TOK, 256>>>(x, g1, xn);
    // 2-4. Q,K,V projections
    dim3 gqkv(D_MODEL / 64, M_TOK / 64);
    gemm_nt<0><<<gqkv, blk>>>(xn, Wq, nullptr, qb, M_TOK, D_MODEL, D_MODEL);
    gemm_nt<0><<<gqkv, blk>>>(xn, Wk, nullptr, kb, M_TOK, D_MODEL, D_MODEL);
    gemm_nt<0><<<gqkv, blk>>>(xn, Wv, nullptr, vb, M_TOK, D_MODEL, D_MODEL);
    // 5. RoPE table + apply
    rope_table_kernel<<<(SEQ * 64 + 255) / 256, 256>>>();
    rope_apply_kernel<<<(M_TOK * NHEAD * 64 + 255) / 256, 256>>>(qb, kb);
    // 6. attention
    dim3 gattn(SEQ / BQ, BATCH * NHEAD);
    attn_kernel<<<gattn, blk, attn_smem>>>(qb, kb, vb, ctx);
    // 7. Wo projection + residual
    gemm_nt<1><<<gqkv, blk>>>(ctx, Wo, x, xmid, M_TOK, D_MODEL, D_MODEL);
    // 8. RMSNorm 2
    rmsnorm_kernel<<<M_TOK, 256>>>(xmid, g2, xn);
    // 9-10. W1 (a) then W3 (gate) with SwiGLU combine epilogue
    dim3 gff(DFF / 64, M_TOK / 64);
    gemm_nt<0><<<gff, blk>>>(xn, W1, nullptr, ffb, M_TOK, DFF, D_MODEL);
    gemm_nt<2><<<gff, blk>>>(xn, W3, nullptr, ffb, M_TOK, DFF, D_MODEL);
    // 11. W2 projection + residual -> out
    gemm_nt<1><<<gqkv, blk>>>(ffb, W2, xmid, out, M_TOK, D_MODEL, DFF);
}

// round 3
// speedup vs baseline: 3.6530x; 3.6530x over previous
#include <cuda_runtime.h>
#include <cuda_bf16.h>
#include <math.h>
#include <stdint.h>

#define D_MODEL 2048
#define NHEAD   16
#define DKH     128
#define DFF     5632
#define SEQ     2048
#define BATCH   2
#define M_TOK   (BATCH*SEQ)   // 4096

// ---------------- scratch (no cudaMalloc allowed) ----------------
__device__ float g_xn  [(size_t)M_TOK*D_MODEL];
__device__ float g_q   [(size_t)M_TOK*D_MODEL];
__device__ float g_k   [(size_t)M_TOK*D_MODEL];
__device__ float g_v   [(size_t)M_TOK*D_MODEL];
__device__ float g_ctx [(size_t)M_TOK*D_MODEL];
__device__ float g_xmid[(size_t)M_TOK*D_MODEL];
__device__ float g_ff  [(size_t)M_TOK*DFF];
__device__ float g_rsin[SEQ*64];
__device__ float g_rcos[SEQ*64];

// ================= tf32 helpers (sm_80+ ISA, works on plain sm_103) =========
__device__ __forceinline__ uint32_t f2tf32(float x) {
    uint32_t r;
    asm("cvt.rna.tf32.f32 %0, %1;" : "=r"(r) : "f"(x));
    return r;
}

__device__ __forceinline__ void mma_tf32(float* d, const uint32_t* a, const uint32_t* b) {
    asm volatile(
        "mma.sync.aligned.m16n8k8.row.col.f32.tf32.tf32.f32 "
        "{%0,%1,%2,%3}, {%4,%5,%6,%7}, {%8,%9}, {%0,%1,%2,%3};"
        : "+f"(d[0]), "+f"(d[1]), "+f"(d[2]), "+f"(d[3])
        : "r"(a[0]), "r"(a[1]), "r"(a[2]), "r"(a[3]),
          "r"(b[0]), "r"(b[1]));
}

// ================= tf32 tensor-core GEMM ====================================
// C[M,N] = A[M,K] @ W[N,K]^T  (both K-major fp32, converted to tf32)
// EPI 0: C = acc; EPI 1: C = res + acc; EPI 2: C = silu(C_old) * acc
// CTA tile 128x128, BK=32. 256 threads = 8 warps (2 m x 4 n), warp tile 64x32.
#define LDS_A 36   // 32 + 4 pad -> conflict-free fragment loads

template<int EPI>
__global__ __launch_bounds__(256) void gemm_mma(
        const float* __restrict__ A,
        const float* __restrict__ W,
        const float* __restrict__ res,
        float* __restrict__ C,
        int M, int N, int K) {
    __shared__ uint32_t As[128 * LDS_A];
    __shared__ uint32_t Bs[128 * LDS_A];

    int tid  = threadIdx.x;
    int lane = tid & 31, wid = tid >> 5;
    int wm = wid >> 2, wn = wid & 3;         // warp grid 2x4
    int bm = blockIdx.y * 128, bn = blockIdx.x * 128;

    int lrow = tid >> 3;                     // 0..31 (row stride 32 across i)
    int lcol = (tid & 7) * 4;                // 0,4,..,28

    const float* Ag = A + (size_t)(bm + lrow) * K + lcol;
    const float* Wg = W + (size_t)(bn + lrow) * K + lcol;

    float  acc[4][4][4] = {};
    float4 Ar[4], Br[4];

    int nk = K >> 5;                          // K/32 tiles
    // prefetch tile 0
#pragma unroll
    for (int i = 0; i < 4; i++) {
        Ar[i] = *(const float4*)(Ag + (size_t)i * 32 * K);
        Br[i] = *(const float4*)(Wg + (size_t)i * 32 * K);
    }

    // store regs -> smem (with fp32->tf32 rna convert)
    auto sts_tiles = [&]() {
#pragma unroll
        for (int i = 0; i < 4; i++) {
            uint32_t* pa = &As[(lrow + i * 32) * LDS_A + lcol];
            pa[0] = f2tf32(Ar[i].x); pa[1] = f2tf32(Ar[i].y);
            pa[2] = f2tf32(Ar[i].z); pa[3] = f2tf32(Ar[i].w);
            uint32_t* pb = &Bs[(lrow + i * 32) * LDS_A + lcol];
            pb[0] = f2tf32(Br[i].x); pb[1] = f2tf32(Br[i].y);
            pb[2] = f2tf32(Br[i].z); pb[3] = f2tf32(Br[i].w);
        }
    };
    sts_tiles();
    __syncthreads();

    int qr = lane >> 2;                       // 0..7 (group id)
    int qc = lane & 3;                        // 0..3 (thread in group)

    for (int kt = 0; kt < nk; kt++) {
        if (kt + 1 < nk) {
            const float* a2 = Ag + (size_t)(kt + 1) * 32;
            const float* w2 = Wg + (size_t)(kt + 1) * 32;
#pragma unroll
            for (int i = 0; i < 4; i++) {
                Ar[i] = *(const float4*)(a2 + (size_t)i * 32 * K);
                Br[i] = *(const float4*)(w2 + (size_t)i * 32 * K);
            }
        }
#pragma unroll
        for (int ks = 0; ks < 4; ks++) {
            int c = ks * 8 + qc;
            uint32_t af[4][4], bf[4][2];
#pragma unroll
            for (int mt = 0; mt < 4; mt++) {
                int r = wm * 64 + mt * 16 + qr;
                af[mt][0] = As[r * LDS_A + c];
                af[mt][1] = As[(r + 8) * LDS_A + c];
                af[mt][2] = As[r * LDS_A + c + 4];
                af[mt][3] = As[(r + 8) * LDS_A + c + 4];
            }
#pragma unroll
            for (int nt = 0; nt < 4; nt++) {
                int n = wn * 32 + nt * 8 + qr;
                bf[nt][0] = Bs[n * LDS_A + c];
                bf[nt][1] = Bs[n * LDS_A + c + 4];
            }
#pragma unroll
            for (int mt = 0; mt < 4; mt++)
#pragma unroll
                for (int nt = 0; nt < 4; nt++)
                    mma_tf32(acc[mt][nt], af[mt], bf[nt]);
        }
        __syncthreads();
        if (kt + 1 < nk) {
            sts_tiles();
            __syncthreads();
        }
    }

    // epilogue: each thread owns 2 rows x 2 cols per (mt,nt) -> float2 stores
#pragma unroll
    for (int mt = 0; mt < 4; mt++) {
        int r0 = bm + wm * 64 + mt * 16 + qr;
#pragma unroll
        for (int nt = 0; nt < 4; nt++) {
            int cc = bn + wn * 32 + nt * 8 + 2 * qc;
            size_t i0 = (size_t)r0 * N + cc;
            size_t i1 = (size_t)(r0 + 8) * N + cc;
            float2 v0 = make_float2(acc[mt][nt][0], acc[mt][nt][1]);
            float2 v1 = make_float2(acc[mt][nt][2], acc[mt][nt][3]);
            if (EPI == 1) {
                float2 rr0 = *(const float2*)(res + i0);
                float2 rr1 = *(const float2*)(res + i1);
                v0.x += rr0.x; v0.y += rr0.y;
                v1.x += rr1.x; v1.y += rr1.y;
            } else if (EPI == 2) {
                float2 a0 = *(const float2*)(C + i0);
                float2 a1 = *(const float2*)(C + i1);
                v0.x *= a0.x / (1.f + __expf(-a0.x));
                v0.y *= a0.y / (1.f + __expf(-a0.y));
                v1.x *= a1.x / (1.f + __expf(-a1.x));
                v1.y *= a1.y / (1.f + __expf(-a1.y));
            }
            *(float2*)(C + i0) = v0;
            *(float2*)(C + i1) = v1;
        }
    }
}

// ---------------- RMSNorm ----------------
__global__ void rmsnorm_kernel(const float* __restrict__ x,
                               const float* __restrict__ g,
                               float* __restrict__ out) {
    int row = blockIdx.x;
    const float* xr = x + (size_t)row * D_MODEL;
    float*       orow = out + (size_t)row * D_MODEL;
    float s = 0.f;
    for (int i = threadIdx.x; i < D_MODEL; i += blockDim.x) {
        float v = xr[i];
        s += v * v;
    }
    __shared__ float red[32];
    for (int o = 16; o; o >>= 1) s += __shfl_down_sync(0xffffffffu, s, o);
    if ((threadIdx.x & 31) == 0) red[threadIdx.x >> 5] = s;
    __syncthreads();
    if (threadIdx.x < 32) {
        float v = (threadIdx.x < (blockDim.x >> 5)) ? red[threadIdx.x] : 0.f;
        for (int o = 16; o; o >>= 1) v += __shfl_down_sync(0xffffffffu, v, o);
        if (threadIdx.x == 0) red[0] = v;
    }
    __syncthreads();
    float rinv = rsqrtf(red[0] * (1.0f / D_MODEL) + 1e-5f);
    for (int i = threadIdx.x; i < D_MODEL; i += blockDim.x)
        orow[i] = xr[i] * g[i] * rinv;
}

// ---------------- RoPE ----------------
__global__ void rope_table_kernel() {
    int idx = blockIdx.x * blockDim.x + threadIdx.x;
    if (idx >= SEQ * 64) return;
    int j = idx & 63, s = idx >> 6;
    double inv = exp(-(double)j * (9.210340371976184 / 64.0)); // 10000^(-j/64)
    double ang = (double)s * inv;
    g_rsin[idx] = (float)sin(ang);
    g_rcos[idx] = (float)cos(ang);
}

__global__ void rope_apply_kernel(float* __restrict__ Qd, float* __restrict__ Kd) {
    int idx = blockIdx.x * blockDim.x + threadIdx.x;
    if (idx >= M_TOK * NHEAD * 64) return;
    int j    = idx & 63;
    int rest = idx >> 6;
    int h    = rest & (NHEAD - 1);
    int tok  = rest >> 4;
    int s    = tok & (SEQ - 1);
    float sn = g_rsin[(s << 6) | j];
    float cs = g_rcos[(s << 6) | j];
    size_t base = (size_t)tok * D_MODEL + h * DKH + 2 * j;
    float q1 = Qd[base], q2 = Qd[base + 1];
    Qd[base]     = q1 * cs - q2 * sn;
    Qd[base + 1] = q1 * sn + q2 * cs;
    float k1 = Kd[base], k2 = Kd[base + 1];
    Kd[base]     = k1 * cs - k2 * sn;
    Kd[base + 1] = k1 * sn + k2 * cs;
}

// ---------------- Flash attention (causal, online softmax) ----------------
#define BQ  32
#define BKT 64
#define LDA (DKH + 4)
__global__ void attn_kernel(const float* __restrict__ Q,
                            const float* __restrict__ K,
                            const float* __restrict__ V,
                            float* __restrict__ O) {
    extern __shared__ float smf[];
    float* Qs = smf;
    float* Ks = Qs + BQ * LDA;
    float* Vs = Ks + BKT * LDA;
    float* Ss = Vs + BKT * LDA;

    int t  = threadIdx.x;
    int bh = blockIdx.y;
    int b  = bh / NHEAD, h = bh % NHEAD;
    int q0 = blockIdx.x * BQ;

    for (int i = t; i < BQ * (DKH / 4); i += 256) {
        int q = i / (DKH / 4), d4 = i % (DKH / 4);
        float4 v = *(const float4*)(Q + (size_t)(b * SEQ + q0 + q) * D_MODEL + h * DKH + d4 * 4);
        *(float4*)(Qs + q * LDA + d4 * 4) = v;
    }

    int lane = t & 7;
    int q    = t >> 3;
    float o[4][4] = {};
    float m_i = -1e30f, l_i = 0.f;

    int kend = q0 + BQ;
    for (int k0 = 0; k0 < kend; k0 += BKT) {
        __syncthreads();
        for (int i = t; i < BKT * (DKH / 4); i += 256) {
            int kk = i / (DKH / 4), d4 = i % (DKH / 4);
            size_t g = (size_t)(b * SEQ + k0 + kk) * D_MODEL + h * DKH + d4 * 4;
            *(float4*)(Ks + kk * LDA + d4 * 4) = *(const float4*)(K + g);
            *(float4*)(Vs + kk * LDA + d4 * 4) = *(const float4*)(V + g);
        }
        __syncthreads();

        float sc[8];
        const float4* qp = (const float4*)(Qs + q * LDA);
#pragma unroll
        for (int ii = 0; ii < 8; ii++) {
            int k = lane + 8 * ii;
            const float4* kp = (const float4*)(Ks + k * LDA);
            float s = 0.f;
#pragma unroll
            for (int d = 0; d < DKH / 4; d++) {
                float4 a = qp[d], bb = kp[d];
                s += a.x * bb.x + a.y * bb.y + a.z * bb.z + a.w * bb.w;
            }
            s *= 0.08838834764831845f;
            if (k0 + k > q0 + q) s = -1e30f;
            sc[ii] = s;
        }
        float mt = sc[0];
#pragma unroll
        for (int ii = 1; ii < 8; ii++) mt = fmaxf(mt, sc[ii]);
        for (int off = 1; off < 8; off <<= 1)
            mt = fmaxf(mt, __shfl_xor_sync(0xffffffffu, mt, off));
        float mnew = fmaxf(m_i, mt);
        float lsum = 0.f;
#pragma unroll
        for (int ii = 0; ii < 8; ii++) {
            float p = __expf(sc[ii] - mnew);
            Ss[q * BKT + lane + 8 * ii] = p;
            lsum += p;
        }
        for (int off = 1; off < 8; off <<= 1)
            lsum += __shfl_xor_sync(0xffffffffu, lsum, off);
        float alpha = __expf(m_i - mnew);
        l_i = l_i * alpha + lsum;
        m_i = mnew;
#pragma unroll
        for (int i = 0; i < 4; i++)
#pragma unroll
            for (int c = 0; c < 4; c++) o[i][c] *= alpha;
        __syncwarp();
        for (int k = 0; k < BKT; k++) {
            float p = Ss[q * BKT + k];
            const float* vrow = Vs + k * LDA;
#pragma unroll
            for (int i = 0; i < 4; i++) {
                float4 vv = *(const float4*)(vrow + lane * 4 + 32 * i);
                o[i][0] += p * vv.x; o[i][1] += p * vv.y;
                o[i][2] += p * vv.z; o[i][3] += p * vv.w;
            }
        }
        __syncwarp();
    }
    float linv = 1.f / l_i;
    size_t obase = (size_t)(b * SEQ + q0 + q) * D_MODEL + h * DKH;
#pragma unroll
    for (int i = 0; i < 4; i++) {
        float4 vv;
        vv.x = o[i][0] * linv; vv.y = o[i][1] * linv;
        vv.z = o[i][2] * linv; vv.w = o[i][3] * linv;
        *(float4*)(O + obase + lane * 4 + 32 * i) = vv;
    }
}

// ---------------- launch ----------------
extern "C" void kernel_launch(void* const* d_in, const int* in_sizes, int n_in,
                              void* d_out, int out_size) {
    const float* x  = (const float*)d_in[0];
    const float* Wq = (const float*)d_in[1];
    const float* Wk = (const float*)d_in[2];
    const float* Wv = (const float*)d_in[3];
    const float* Wo = (const float*)d_in[4];
    const float* W1 = (const float*)d_in[5];
    const float* W2 = (const float*)d_in[6];
    const float* W3 = (const float*)d_in[7];
    const float* g1 = (const float*)d_in[8];
    const float* g2 = (const float*)d_in[9];
    float* out = (float*)d_out;

    float *xn, *qb, *kb, *vb, *ctx, *xmid, *ffb;
    cudaGetSymbolAddress((void**)&xn,   g_xn);
    cudaGetSymbolAddress((void**)&qb,   g_q);
    cudaGetSymbolAddress((void**)&kb,   g_k);
    cudaGetSymbolAddress((void**)&vb,   g_v);
    cudaGetSymbolAddress((void**)&ctx,  g_ctx);
    cudaGetSymbolAddress((void**)&xmid, g_xmid);
    cudaGetSymbolAddress((void**)&ffb,  g_ff);

    int attn_smem = (BQ * LDA + 2 * BKT * LDA + BQ * BKT) * (int)sizeof(float);
    cudaFuncSetAttribute(attn_kernel, cudaFuncAttributeMaxDynamicSharedMemorySize, attn_smem);

    dim3 blk(256);
    // 1. RMSNorm 1
    rmsnorm_kernel<<<M_TOK, 256>>>(x, g1, xn);
    // 2-4. Q,K,V projections (tf32 mma.sync)
    dim3 gqkv(D_MODEL / 128, M_TOK / 128);
    gemm_mma<0><<<gqkv, blk>>>(xn, Wq, nullptr, qb, M_TOK, D_MODEL, D_MODEL);
    gemm_mma<0><<<gqkv, blk>>>(xn, Wk, nullptr, kb, M_TOK, D_MODEL, D_MODEL);
    gemm_mma<0><<<gqkv, blk>>>(xn, Wv, nullptr, vb, M_TOK, D_MODEL, D_MODEL);
    // 5. RoPE table + apply
    rope_table_kernel<<<(SEQ * 64 + 255) / 256, 256>>>();
    rope_apply_kernel<<<(M_TOK * NHEAD * 64 + 255) / 256, 256>>>(qb, kb);
    // 6. attention
    dim3 gattn(SEQ / BQ, BATCH * NHEAD);
    attn_kernel<<<gattn, blk, attn_smem>>>(qb, kb, vb, ctx);
    // 7. Wo projection + residual
    gemm_mma<1><<<gqkv, blk>>>(ctx, Wo, x, xmid, M_TOK, D_MODEL, D_MODEL);
    // 8. RMSNorm 2
    rmsnorm_kernel<<<M_TOK, 256>>>(xmid, g2, xn);
    // 9-10. W1 then W3 with SwiGLU combine epilogue
    dim3 gff(DFF / 128, M_TOK / 128);
    gemm_mma<0><<<gff, blk>>>(xn, W1, nullptr, ffb, M_TOK, DFF, D_MODEL);
    gemm_mma<2><<<gff, blk>>>(xn, W3, nullptr, ffb, M_TOK, DFF, D_MODEL);
    // 11. W2 projection + residual -> out
    gemm_mma<1><<<gqkv, blk>>>(ffb, W2, xmid, out, M_TOK, D_MODEL, DFF);
}

// round 4
// speedup vs baseline: 6.4702x; 1.7712x over previous
#include <cuda_runtime.h>
#include <cuda_bf16.h>
#include <math.h>
#include <stdint.h>

#define D_MODEL 2048
#define NHEAD   16
#define DKH     128
#define DFF     5632
#define SEQ     2048
#define BATCH   2
#define M_TOK   (BATCH*SEQ)   // 4096

// ---------------- scratch ----------------
__device__ float g_xn  [(size_t)M_TOK*D_MODEL];
__device__ float g_q   [(size_t)M_TOK*D_MODEL];
__device__ float g_k   [(size_t)M_TOK*D_MODEL];
__device__ float g_v   [(size_t)M_TOK*D_MODEL];
__device__ float g_ctx [(size_t)M_TOK*D_MODEL];
__device__ float g_xmid[(size_t)M_TOK*D_MODEL];
__device__ float g_ff  [(size_t)M_TOK*DFF];
__device__ float g_rsin[SEQ*64];
__device__ float g_rcos[SEQ*64];

// ================= helpers =================
__device__ __forceinline__ uint32_t f2tf32(float x) {
    uint32_t r;
    asm("cvt.rna.tf32.f32 %0, %1;" : "=r"(r) : "f"(x));
    return r;
}
__device__ __forceinline__ void mma_tf32(float* d, const uint32_t* a, const uint32_t* b) {
    asm volatile(
        "mma.sync.aligned.m16n8k8.row.col.f32.tf32.tf32.f32 "
        "{%0,%1,%2,%3}, {%4,%5,%6,%7}, {%8,%9}, {%0,%1,%2,%3};"
        : "+f"(d[0]), "+f"(d[1]), "+f"(d[2]), "+f"(d[3])
        : "r"(a[0]), "r"(a[1]), "r"(a[2]), "r"(a[3]),
          "r"(b[0]), "r"(b[1]));
}
__device__ __forceinline__ uint32_t smem_u32(const void* p) {
    uint32_t a;
    asm("{ .reg .u64 t; cvta.to.shared.u64 t, %1; cvt.u32.u64 %0, t; }"
        : "=r"(a) : "l"(p));
    return a;
}
__device__ __forceinline__ void cp_async16(uint32_t dst, const void* src) {
    asm volatile("cp.async.cg.shared.global [%0], [%1], 16;" :: "r"(dst), "l"(src));
}
#define CP_COMMIT()  asm volatile("cp.async.commit_group;" ::: "memory")
#define CP_WAIT(N)   asm volatile("cp.async.wait_group %0;" :: "n"(N) : "memory")

// ================= tf32 GEMM, 3-stage cp.async pipeline ====================
// C[M,N] = A[M,K] @ W[N,K]^T ; EPI 0: C=acc; 1: C=res+acc; 2: C=silu(C_old)*acc
// CTA 128x128, BK=32, 256 threads = 8 warps (2m x 4n), warp tile 64x32.
#define LDS_A  36
#define GSTG   3
#define GEMM_SMEM (GSTG*2*128*LDS_A*4)

template<int EPI>
__device__ __forceinline__ void gemm_body(
        const float* __restrict__ A,
        const float* __restrict__ W,
        const float* __restrict__ res,
        float* __restrict__ C,
        int M, int N, int K) {
    extern __shared__ float smf[];
    float* As = smf;                       // [GSTG][128][LDS_A]
    float* Bs = smf + GSTG * 128 * LDS_A;

    int tid  = threadIdx.x;
    int lane = tid & 31, wid = tid >> 5;
    int wm = wid >> 2, wn = wid & 3;
    int bm = blockIdx.y * 128, bn = blockIdx.x * 128;

    int lrow = tid >> 3;                   // 0..31
    int lcol = (tid & 7) * 4;              // 0..28

    const float* Ag = A + (size_t)(bm + lrow) * K + lcol;
    const float* Wg = W + (size_t)(bn + lrow) * K + lcol;

    uint32_t as_base = smem_u32(As);
    uint32_t bs_base = smem_u32(Bs);

    auto issue_stage = [&](int tile, int stg) {
        uint32_t soff = (uint32_t)stg * 128 * LDS_A * 4;
        const float* a2 = Ag + (size_t)tile * 32;
        const float* w2 = Wg + (size_t)tile * 32;
#pragma unroll
        for (int i = 0; i < 4; i++) {
            uint32_t d = (uint32_t)((lrow + i * 32) * LDS_A + lcol) * 4;
            cp_async16(as_base + soff + d, a2 + (size_t)i * 32 * K);
            cp_async16(bs_base + soff + d, w2 + (size_t)i * 32 * K);
        }
    };

    int nk = K >> 5;
    issue_stage(0, 0); CP_COMMIT();
    issue_stage(1, 1); CP_COMMIT();

    float acc[4][4][4] = {};
    int qr = lane >> 2, qc = lane & 3;

    int stg = 0;
    for (int kt = 0; kt < nk; kt++) {
        CP_WAIT(1);
        __syncthreads();
        const float* AsS = As + stg * 128 * LDS_A;
        const float* BsS = Bs + stg * 128 * LDS_A;
#pragma unroll
        for (int ks = 0; ks < 4; ks++) {
            int c = ks * 8 + qc;
            uint32_t af[4][4], bf[4][2];
#pragma unroll
            for (int mt = 0; mt < 4; mt++) {
                int r = wm * 64 + mt * 16 + qr;
                af[mt][0] = f2tf32(AsS[r * LDS_A + c]);
                af[mt][1] = f2tf32(AsS[(r + 8) * LDS_A + c]);
                af[mt][2] = f2tf32(AsS[r * LDS_A + c + 4]);
                af[mt][3] = f2tf32(AsS[(r + 8) * LDS_A + c + 4]);
            }
#pragma unroll
            for (int nt = 0; nt < 4; nt++) {
                int n = wn * 32 + nt * 8 + qr;
                bf[nt][0] = f2tf32(BsS[n * LDS_A + c]);
                bf[nt][1] = f2tf32(BsS[n * LDS_A + c + 4]);
            }
#pragma unroll
            for (int mt = 0; mt < 4; mt++)
#pragma unroll
                for (int nt = 0; nt < 4; nt++)
                    mma_tf32(acc[mt][nt], af[mt], bf[nt]);
        }
        // issue tile kt+2 into the stage just freed (stg-1 mod 3)
        int nstg = stg + 2; if (nstg >= GSTG) nstg -= GSTG;
        if (kt + 2 < nk) issue_stage(kt + 2, nstg);
        CP_COMMIT();
        stg = stg + 1 == GSTG ? 0 : stg + 1;
    }

#pragma unroll
    for (int mt = 0; mt < 4; mt++) {
        int r0 = bm + wm * 64 + mt * 16 + qr;
#pragma unroll
        for (int nt = 0; nt < 4; nt++) {
            int cc = bn + wn * 32 + nt * 8 + 2 * qc;
            size_t i0 = (size_t)r0 * N + cc;
            size_t i1 = (size_t)(r0 + 8) * N + cc;
            float2 v0 = make_float2(acc[mt][nt][0], acc[mt][nt][1]);
            float2 v1 = make_float2(acc[mt][nt][2], acc[mt][nt][3]);
            if (EPI == 1) {
                float2 rr0 = *(const float2*)(res + i0);
                float2 rr1 = *(const float2*)(res + i1);
                v0.x += rr0.x; v0.y += rr0.y;
                v1.x += rr1.x; v1.y += rr1.y;
            } else if (EPI == 2) {
                float2 a0 = *(const float2*)(C + i0);
                float2 a1 = *(const float2*)(C + i1);
                v0.x *= a0.x / (1.f + __expf(-a0.x));
                v0.y *= a0.y / (1.f + __expf(-a0.y));
                v1.x *= a1.x / (1.f + __expf(-a1.x));
                v1.y *= a1.y / (1.f + __expf(-a1.y));
            }
            *(float2*)(C + i0) = v0;
            *(float2*)(C + i1) = v1;
        }
    }
}

template<int EPI>
__global__ __launch_bounds__(256) void gemm_mma(
        const float* __restrict__ A, const float* __restrict__ W,
        const float* __restrict__ res, float* __restrict__ C,
        int M, int N, int K) {
    gemm_body<EPI>(A, W, res, C, M, N, K);
}

// fused QKV: blockIdx.z selects weight/output
__global__ __launch_bounds__(256) void gemm_qkv(
        const float* __restrict__ A,
        const float* __restrict__ Wq, const float* __restrict__ Wk,
        const float* __restrict__ Wv,
        float* __restrict__ q, float* __restrict__ k, float* __restrict__ v) {
    const float* W = blockIdx.z == 0 ? Wq : (blockIdx.z == 1 ? Wk : Wv);
    float* C = blockIdx.z == 0 ? q : (blockIdx.z == 1 ? k : v);
    gemm_body<0>(A, W, nullptr, C, M_TOK, D_MODEL, D_MODEL);
}

// ---------------- RMSNorm ----------------
__global__ void rmsnorm_kernel(const float* __restrict__ x,
                               const float* __restrict__ g,
                               float* __restrict__ out) {
    int row = blockIdx.x;
    const float* xr = x + (size_t)row * D_MODEL;
    float*       orow = out + (size_t)row * D_MODEL;
    float s = 0.f;
    for (int i = threadIdx.x; i < D_MODEL; i += blockDim.x) {
        float v = xr[i]; s += v * v;
    }
    __shared__ float red[32];
    for (int o = 16; o; o >>= 1) s += __shfl_down_sync(0xffffffffu, s, o);
    if ((threadIdx.x & 31) == 0) red[threadIdx.x >> 5] = s;
    __syncthreads();
    if (threadIdx.x < 32) {
        float v = (threadIdx.x < (blockDim.x >> 5)) ? red[threadIdx.x] : 0.f;
        for (int o = 16; o; o >>= 1) v += __shfl_down_sync(0xffffffffu, v, o);
        if (threadIdx.x == 0) red[0] = v;
    }
    __syncthreads();
    float rinv = rsqrtf(red[0] * (1.0f / D_MODEL) + 1e-5f);
    for (int i = threadIdx.x; i < D_MODEL; i += blockDim.x)
        orow[i] = xr[i] * g[i] * rinv;
}

// ---------------- RoPE ----------------
__global__ void rope_table_kernel() {
    int idx = blockIdx.x * blockDim.x + threadIdx.x;
    if (idx >= SEQ * 64) return;
    int j = idx & 63, s = idx >> 6;
    double inv = exp(-(double)j * (9.210340371976184 / 64.0));
    double ang = (double)s * inv;
    g_rsin[idx] = (float)sin(ang);
    g_rcos[idx] = (float)cos(ang);
}
__global__ void rope_apply_kernel(float* __restrict__ Qd, float* __restrict__ Kd) {
    int idx = blockIdx.x * blockDim.x + threadIdx.x;
    if (idx >= M_TOK * NHEAD * 64) return;
    int j    = idx & 63;
    int rest = idx >> 6;
    int h    = rest & (NHEAD - 1);
    int tok  = rest >> 4;
    int s    = tok & (SEQ - 1);
    float sn = g_rsin[(s << 6) | j];
    float cs = g_rcos[(s << 6) | j];
    size_t base = (size_t)tok * D_MODEL + h * DKH + 2 * j;
    float q1 = Qd[base], q2 = Qd[base + 1];
    Qd[base]     = q1 * cs - q2 * sn;
    Qd[base + 1] = q1 * sn + q2 * cs;
    float k1 = Kd[base], k2 = Kd[base + 1];
    Kd[base]     = k1 * cs - k2 * sn;
    Kd[base + 1] = k1 * sn + k2 * cs;
}

// ---------------- Tensor-core flash attention (causal) ----------------
// BQ=64, BK=64, 128 threads (4 warps, warp w owns q rows [w*16, w*16+16)).
// Q/K/V smem tiles LD=136 (conflict-free), P tile LD=68. K/V 2-stage cp.async.
#define ALD 136
#define PLD 68
#define ATT_SMEM ((64*ALD + 2*2*64*ALD + 64*PLD) * 4)

__global__ __launch_bounds__(128) void attn_mma(
        const float* __restrict__ Q,
        const float* __restrict__ K,
        const float* __restrict__ V,
        float* __restrict__ O) {
    extern __shared__ float smf[];
    float* Qs = smf;                          // 64*ALD
    float* Ks = Qs + 64 * ALD;                // 2 stages
    float* Vs = Ks + 2 * 64 * ALD;            // 2 stages
    float* Ps = Vs + 2 * 64 * ALD;            // 64*PLD

    int tid = threadIdx.x;
    int lane = tid & 31, wid = tid >> 5;
    int qr = lane >> 2, qc = lane & 3;
    int bh = blockIdx.y;
    int b = bh >> 4, h = bh & 15;
    int q0 = blockIdx.x * 64;
    int nkb = blockIdx.x + 1;

    uint32_t ks_base = smem_u32(Ks);
    uint32_t vs_base = smem_u32(Vs);

    // load Q tile (plain)
    for (int i = tid; i < 64 * 32; i += 128) {
        int r = i >> 5, c4 = i & 31;
        float4 v = *(const float4*)(Q + (size_t)(b * SEQ + q0 + r) * D_MODEL + h * DKH + c4 * 4);
        *(float4*)(Qs + r * ALD + c4 * 4) = v;
    }

    auto issue_kv = [&](int kb, int stg) {
        uint32_t soff = (uint32_t)stg * 64 * ALD * 4;
#pragma unroll
        for (int i = 0; i < 16; i++) {
            int idx = tid + i * 128;
            int r = idx >> 5, c4 = idx & 31;
            size_t g = (size_t)(b * SEQ + kb * 64 + r) * D_MODEL + h * DKH + c4 * 4;
            uint32_t d = (uint32_t)(r * ALD + c4 * 4) * 4;
            cp_async16(ks_base + soff + d, K + g);
            cp_async16(vs_base + soff + d, V + g);
        }
    };

    issue_kv(0, 0); CP_COMMIT();

    float o[16][4] = {};
    float m0 = -1e30f, m1 = -1e30f, l0 = 0.f, l1 = 0.f;
    const float scale = 0.08838834764831845f;  // 1/sqrt(128)

    for (int kb = 0; kb < nkb; kb++) {
        if (kb + 1 < nkb) issue_kv(kb + 1, (kb + 1) & 1);
        CP_COMMIT();
        CP_WAIT(1);
        __syncthreads();
        const float* KsS = Ks + (kb & 1) * 64 * ALD;
        const float* VsS = Vs + (kb & 1) * 64 * ALD;

        // S = Q K^T (warp: 16 q-rows x 64 k-cols)
        float s[8][4] = {};
#pragma unroll
        for (int ks = 0; ks < 16; ks++) {
            int c = ks * 8 + qc;
            int r = wid * 16 + qr;
            uint32_t af[4];
            af[0] = f2tf32(Qs[r * ALD + c]);
            af[1] = f2tf32(Qs[(r + 8) * ALD + c]);
            af[2] = f2tf32(Qs[r * ALD + c + 4]);
            af[3] = f2tf32(Qs[(r + 8) * ALD + c + 4]);
#pragma unroll
            for (int nt = 0; nt < 8; nt++) {
                int n = nt * 8 + qr;
                uint32_t bf[2];
                bf[0] = f2tf32(KsS[n * ALD + c]);
                bf[1] = f2tf32(KsS[n * ALD + c + 4]);
                mma_tf32(s[nt], af, bf);
            }
        }

        // mask + online softmax
        bool diag = (kb == blockIdx.x);
        int row0 = q0 + wid * 16 + qr, row1 = row0 + 8;
        float mt0 = -1e30f, mt1 = -1e30f;
#pragma unroll
        for (int nt = 0; nt < 8; nt++) {
            int col = kb * 64 + nt * 8 + 2 * qc;
            s[nt][0] *= scale; s[nt][1] *= scale;
            s[nt][2] *= scale; s[nt][3] *= scale;
            if (diag) {
                if (col > row0)     s[nt][0] = -1e30f;
                if (col + 1 > row0) s[nt][1] = -1e30f;
                if (col > row1)     s[nt][2] = -1e30f;
                if (col + 1 > row1) s[nt][3] = -1e30f;
            }
            mt0 = fmaxf(mt0, fmaxf(s[nt][0], s[nt][1]));
            mt1 = fmaxf(mt1, fmaxf(s[nt][2], s[nt][3]));
        }
#pragma unroll
        for (int off = 1; off < 4; off <<= 1) {
            mt0 = fmaxf(mt0, __shfl_xor_sync(0xffffffffu, mt0, off));
            mt1 = fmaxf(mt1, __shfl_xor_sync(0xffffffffu, mt1, off));
        }
        float mn0 = fmaxf(m0, mt0), mn1 = fmaxf(m1, mt1);
        float ls0 = 0.f, ls1 = 0.f;
        int prow = wid * 16 + qr;
#pragma unroll
        for (int nt = 0; nt < 8; nt++) {
            float p0 = __expf(s[nt][0] - mn0);
            float p1 = __expf(s[nt][1] - mn0);
            float p2 = __expf(s[nt][2] - mn1);
            float p3 = __expf(s[nt][3] - mn1);
            ls0 += p0 + p1; ls1 += p2 + p3;
            *(float2*)(Ps + prow * PLD + nt * 8 + 2 * qc)       = make_float2(p0, p1);
            *(float2*)(Ps + (prow + 8) * PLD + nt * 8 + 2 * qc) = make_float2(p2, p3);
        }
#pragma unroll
        for (int off = 1; off < 4; off <<= 1) {
            ls0 += __shfl_xor_sync(0xffffffffu, ls0, off);
            ls1 += __shfl_xor_sync(0xffffffffu, ls1, off);
        }
        float al0 = __expf(m0 - mn0), al1 = __expf(m1 - mn1);
        l0 = l0 * al0 + ls0; l1 = l1 * al1 + ls1;
        m0 = mn0; m1 = mn1;
#pragma unroll
        for (int nt = 0; nt < 16; nt++) {
            o[nt][0] *= al0; o[nt][1] *= al0;
            o[nt][2] *= al1; o[nt][3] *= al1;
        }
        __syncwarp();

        // O += P V  (A = P from smem, B = V)
#pragma unroll
        for (int ks = 0; ks < 8; ks++) {
            int c = ks * 8 + qc;
            int r = wid * 16 + qr;
            uint32_t af[4];
            af[0] = f2tf32(Ps[r * PLD + c]);
            af[1] = f2tf32(Ps[(r + 8) * PLD + c]);
            af[2] = f2tf32(Ps[r * PLD + c + 4]);
            af[3] = f2tf32(Ps[(r + 8) * PLD + c + 4]);
#pragma unroll
            for (int nt = 0; nt < 16; nt++) {
                int n = nt * 8 + qr;
                uint32_t bf[2];
                bf[0] = f2tf32(VsS[c * ALD + n]);
                bf[1] = f2tf32(VsS[(c + 4) * ALD + n]);
                mma_tf32(o[nt], af, bf);
            }
        }
        __syncthreads();
    }

    float i0 = 1.f / l0, i1 = 1.f / l1;
    int r0 = b * SEQ + q0 + wid * 16 + qr;
#pragma unroll
    for (int nt = 0; nt < 16; nt++) {
        int cc = h * DKH + nt * 8 + 2 * qc;
        *(float2*)(O + (size_t)r0 * D_MODEL + cc) =
            make_float2(o[nt][0] * i0, o[nt][1] * i0);
        *(float2*)(O + (size_t)(r0 + 8) * D_MODEL + cc) =
            make_float2(o[nt][2] * i1, o[nt][3] * i1);
    }
}

// ---------------- launch ----------------
extern "C" void kernel_launch(void* const* d_in, const int* in_sizes, int n_in,
                              void* d_out, int out_size) {
    const float* x  = (const float*)d_in[0];
    const float* Wq = (const float*)d_in[1];
    const float* Wk = (const float*)d_in[2];
    const float* Wv = (const float*)d_in[3];
    const float* Wo = (const float*)d_in[4];
    const float* W1 = (const float*)d_in[5];
    const float* W2 = (const float*)d_in[6];
    const float* W3 = (const float*)d_in[7];
    const float* g1 = (const float*)d_in[8];
    const float* g2 = (const float*)d_in[9];
    float* out = (float*)d_out;

    float *xn, *qb, *kb, *vb, *ctx, *xmid, *ffb;
    cudaGetSymbolAddress((void**)&xn,   g_xn);
    cudaGetSymbolAddress((void**)&qb,   g_q);
    cudaGetSymbolAddress((void**)&kb,   g_k);
    cudaGetSymbolAddress((void**)&vb,   g_v);
    cudaGetSymbolAddress((void**)&ctx,  g_ctx);
    cudaGetSymbolAddress((void**)&xmid, g_xmid);
    cudaGetSymbolAddress((void**)&ffb,  g_ff);

    static int configured = 0;
    if (!configured) {
        cudaFuncSetAttribute(gemm_mma<0>, cudaFuncAttributeMaxDynamicSharedMemorySize, GEMM_SMEM);
        cudaFuncSetAttribute(gemm_mma<1>, cudaFuncAttributeMaxDynamicSharedMemorySize, GEMM_SMEM);
        cudaFuncSetAttribute(gemm_mma<2>, cudaFuncAttributeMaxDynamicSharedMemorySize, GEMM_SMEM);
        cudaFuncSetAttribute(gemm_qkv,    cudaFuncAttributeMaxDynamicSharedMemorySize, GEMM_SMEM);
        cudaFuncSetAttribute(attn_mma,    cudaFuncAttributeMaxDynamicSharedMemorySize, ATT_SMEM);
        configured = 1;
    }

    dim3 blk(256);
    rmsnorm_kernel<<<M_TOK, 256>>>(x, g1, xn);
    dim3 gq(D_MODEL / 128, M_TOK / 128, 3);
    gemm_qkv<<<gq, blk, GEMM_SMEM>>>(xn, Wq, Wk, Wv, qb, kb, vb);
    rope_table_kernel<<<(SEQ * 64 + 255) / 256, 256>>>();
    rope_apply_kernel<<<(M_TOK * NHEAD * 64 + 255) / 256, 256>>>(qb, kb);
    dim3 gattn(SEQ / 64, BATCH * NHEAD);
    attn_mma<<<gattn, 128, ATT_SMEM>>>(qb, kb, vb, ctx);
    dim3 gqkv(D_MODEL / 128, M_TOK / 128);
    gemm_mma<1><<<gqkv, blk, GEMM_SMEM>>>(ctx, Wo, x, xmid, M_TOK, D_MODEL, D_MODEL);
    rmsnorm_kernel<<<M_TOK, 256>>>(xmid, g2, xn);
    dim3 gff(DFF / 128, M_TOK / 128);
    gemm_mma<0><<<gff, blk, GEMM_SMEM>>>(xn, W1, nullptr, ffb, M_TOK, DFF, D_MODEL);
    gemm_mma<2><<<gff, blk, GEMM_SMEM>>>(xn, W3, nullptr, ffb, M_TOK, DFF, D_MODEL);
    gemm_mma<1><<<gqkv, blk, GEMM_SMEM>>>(ffb, W2, xmid, out, M_TOK, D_MODEL, DFF);
}

// round 5
// speedup vs baseline: 6.6917x; 1.0342x over previous
#include <cuda_runtime.h>
#include <cuda_bf16.h>
#include <math.h>
#include <stdint.h>

#define D_MODEL 2048
#define NHEAD   16
#define DKH     128
#define DFF     5632
#define SEQ     2048
#define BATCH   2
#define M_TOK   (BATCH*SEQ)   // 4096

// ---------------- scratch ----------------
__device__ float g_xn  [(size_t)M_TOK*D_MODEL];
__device__ float g_q   [(size_t)M_TOK*D_MODEL];
__device__ float g_k   [(size_t)M_TOK*D_MODEL];
__device__ float g_v   [(size_t)M_TOK*D_MODEL];
__device__ float g_ctx [(size_t)M_TOK*D_MODEL];
__device__ float g_xmid[(size_t)M_TOK*D_MODEL];
__device__ float g_ff  [(size_t)M_TOK*DFF];
__device__ float g_rsin[SEQ*64];
__device__ float g_rcos[SEQ*64];

// ================= helpers =================
__device__ __forceinline__ uint32_t f2tf32(float x) {
    uint32_t r;
    asm("cvt.rna.tf32.f32 %0, %1;" : "=r"(r) : "f"(x));
    return r;
}
__device__ __forceinline__ void mma_tf32(float* d, const uint32_t* a, const uint32_t* b) {
    asm volatile(
        "mma.sync.aligned.m16n8k8.row.col.f32.tf32.tf32.f32 "
        "{%0,%1,%2,%3}, {%4,%5,%6,%7}, {%8,%9}, {%0,%1,%2,%3};"
        : "+f"(d[0]), "+f"(d[1]), "+f"(d[2]), "+f"(d[3])
        : "r"(a[0]), "r"(a[1]), "r"(a[2]), "r"(a[3]),
          "r"(b[0]), "r"(b[1]));
}
__device__ __forceinline__ uint32_t smem_u32(const void* p) {
    uint32_t a;
    asm("{ .reg .u64 t; cvta.to.shared.u64 t, %1; cvt.u32.u64 %0, t; }"
        : "=r"(a) : "l"(p));
    return a;
}
__device__ __forceinline__ void cp_async16(uint32_t dst, const void* src) {
    asm volatile("cp.async.cg.shared.global [%0], [%1], 16;" :: "r"(dst), "l"(src));
}
#define CP_COMMIT()  asm volatile("cp.async.commit_group;" ::: "memory")
#define CP_WAIT(N)   asm volatile("cp.async.wait_group %0;" :: "n"(N) : "memory")

// ================= tf32 GEMM, 256x128 CTA tile, 3-stage cp.async ============
// C[M,N] = A[M,K] @ W[N,K]^T ; EPI 0: C=acc; 1: C=res+acc; 2: C=silu(C_old)*acc
// 256 threads = 8 warps (4m x 2n), warp tile 64x64, BK=32.
#define GBM 256
#define GBN 128
#define LDS_A  36
#define GSTG   3
#define GEMM_SMEM (GSTG*(GBM+GBN)*LDS_A*4)

template<int EPI>
__device__ __forceinline__ void gemm_body(
        const float* __restrict__ A,
        const float* __restrict__ W,
        const float* __restrict__ res,
        float* __restrict__ C,
        int M, int N, int K) {
    extern __shared__ float smf[];
    float* As = smf;                         // [GSTG][GBM][LDS_A]
    float* Bs = smf + GSTG * GBM * LDS_A;    // [GSTG][GBN][LDS_A]

    int tid  = threadIdx.x;
    int lane = tid & 31, wid = tid >> 5;
    int wm = wid >> 1, wn = wid & 1;
    int bm = blockIdx.y * GBM, bn = blockIdx.x * GBN;

    int lrow = tid >> 3;                     // 0..31
    int lcol = (tid & 7) * 4;                // 0..28

    const float* Ag = A + (size_t)(bm + lrow) * K + lcol;
    const float* Wg = W + (size_t)(bn + lrow) * K + lcol;

    uint32_t as_base = smem_u32(As);
    uint32_t bs_base = smem_u32(Bs);

    auto issue_stage = [&](int tile, int stg) {
        uint32_t aoff = (uint32_t)stg * GBM * LDS_A * 4;
        uint32_t boff = (uint32_t)stg * GBN * LDS_A * 4;
        const float* a2 = Ag + (size_t)tile * 32;
        const float* w2 = Wg + (size_t)tile * 32;
#pragma unroll
        for (int i = 0; i < 8; i++) {
            uint32_t d = (uint32_t)((lrow + i * 32) * LDS_A + lcol) * 4;
            cp_async16(as_base + aoff + d, a2 + (size_t)i * 32 * K);
        }
#pragma unroll
        for (int i = 0; i < 4; i++) {
            uint32_t d = (uint32_t)((lrow + i * 32) * LDS_A + lcol) * 4;
            cp_async16(bs_base + boff + d, w2 + (size_t)i * 32 * K);
        }
    };

    int nk = K >> 5;
    issue_stage(0, 0); CP_COMMIT();
    issue_stage(1, 1); CP_COMMIT();

    float acc[4][8][4] = {};
    int qr = lane >> 2, qc = lane & 3;

    int stg = 0;
    for (int kt = 0; kt < nk; kt++) {
        CP_WAIT(1);
        __syncthreads();
        const float* AsS = As + stg * GBM * LDS_A;
        const float* BsS = Bs + stg * GBN * LDS_A;
#pragma unroll
        for (int ks = 0; ks < 4; ks++) {
            int c = ks * 8 + qc;
            uint32_t af[4][4], bf[8][2];
#pragma unroll
            for (int mt = 0; mt < 4; mt++) {
                int r = wm * 64 + mt * 16 + qr;
                af[mt][0] = f2tf32(AsS[r * LDS_A + c]);
                af[mt][1] = f2tf32(AsS[(r + 8) * LDS_A + c]);
                af[mt][2] = f2tf32(AsS[r * LDS_A + c + 4]);
                af[mt][3] = f2tf32(AsS[(r + 8) * LDS_A + c + 4]);
            }
#pragma unroll
            for (int nt = 0; nt < 8; nt++) {
                int n = wn * 64 + nt * 8 + qr;
                bf[nt][0] = f2tf32(BsS[n * LDS_A + c]);
                bf[nt][1] = f2tf32(BsS[n * LDS_A + c + 4]);
            }
#pragma unroll
            for (int mt = 0; mt < 4; mt++)
#pragma unroll
                for (int nt = 0; nt < 8; nt++)
                    mma_tf32(acc[mt][nt], af[mt], bf[nt]);
        }
        int nstg = stg + 2; if (nstg >= GSTG) nstg -= GSTG;
        if (kt + 2 < nk) issue_stage(kt + 2, nstg);
        CP_COMMIT();
        stg = stg + 1 == GSTG ? 0 : stg + 1;
    }

#pragma unroll
    for (int mt = 0; mt < 4; mt++) {
        int r0 = bm + wm * 64 + mt * 16 + qr;
#pragma unroll
        for (int nt = 0; nt < 8; nt++) {
            int cc = bn + wn * 64 + nt * 8 + 2 * qc;
            size_t i0 = (size_t)r0 * N + cc;
            size_t i1 = (size_t)(r0 + 8) * N + cc;
            float2 v0 = make_float2(acc[mt][nt][0], acc[mt][nt][1]);
            float2 v1 = make_float2(acc[mt][nt][2], acc[mt][nt][3]);
            if (EPI == 1) {
                float2 rr0 = *(const float2*)(res + i0);
                float2 rr1 = *(const float2*)(res + i1);
                v0.x += rr0.x; v0.y += rr0.y;
                v1.x += rr1.x; v1.y += rr1.y;
            } else if (EPI == 2) {
                float2 a0 = *(const float2*)(C + i0);
                float2 a1 = *(const float2*)(C + i1);
                v0.x *= a0.x / (1.f + __expf(-a0.x));
                v0.y *= a0.y / (1.f + __expf(-a0.y));
                v1.x *= a1.x / (1.f + __expf(-a1.x));
                v1.y *= a1.y / (1.f + __expf(-a1.y));
            }
            *(float2*)(C + i0) = v0;
            *(float2*)(C + i1) = v1;
        }
    }
}

template<int EPI>
__global__ __launch_bounds__(256) void gemm_mma(
        const float* __restrict__ A, const float* __restrict__ W,
        const float* __restrict__ res, float* __restrict__ C,
        int M, int N, int K) {
    gemm_body<EPI>(A, W, res, C, M, N, K);
}

__global__ __launch_bounds__(256) void gemm_qkv(
        const float* __restrict__ A,
        const float* __restrict__ Wq, const float* __restrict__ Wk,
        const float* __restrict__ Wv,
        float* __restrict__ q, float* __restrict__ k, float* __restrict__ v) {
    const float* W = blockIdx.z == 0 ? Wq : (blockIdx.z == 1 ? Wk : Wv);
    float* C = blockIdx.z == 0 ? q : (blockIdx.z == 1 ? k : v);
    gemm_body<0>(A, W, nullptr, C, M_TOK, D_MODEL, D_MODEL);
}

// ---------------- RMSNorm ----------------
__global__ void rmsnorm_kernel(const float* __restrict__ x,
                               const float* __restrict__ g,
                               float* __restrict__ out) {
    int row = blockIdx.x;
    const float* xr = x + (size_t)row * D_MODEL;
    float*       orow = out + (size_t)row * D_MODEL;
    float s = 0.f;
    for (int i = threadIdx.x; i < D_MODEL; i += blockDim.x) {
        float v = xr[i]; s += v * v;
    }
    __shared__ float red[32];
    for (int o = 16; o; o >>= 1) s += __shfl_down_sync(0xffffffffu, s, o);
    if ((threadIdx.x & 31) == 0) red[threadIdx.x >> 5] = s;
    __syncthreads();
    if (threadIdx.x < 32) {
        float v = (threadIdx.x < (blockDim.x >> 5)) ? red[threadIdx.x] : 0.f;
        for (int o = 16; o; o >>= 1) v += __shfl_down_sync(0xffffffffu, v, o);
        if (threadIdx.x == 0) red[0] = v;
    }
    __syncthreads();
    float rinv = rsqrtf(red[0] * (1.0f / D_MODEL) + 1e-5f);
    for (int i = threadIdx.x; i < D_MODEL; i += blockDim.x)
        orow[i] = xr[i] * g[i] * rinv;
}

// ---------------- RoPE ----------------
__global__ void rope_table_kernel() {
    int idx = blockIdx.x * blockDim.x + threadIdx.x;
    if (idx >= SEQ * 64) return;
    int j = idx & 63, s = idx >> 6;
    double inv = exp(-(double)j * (9.210340371976184 / 64.0));
    double ang = (double)s * inv;
    g_rsin[idx] = (float)sin(ang);
    g_rcos[idx] = (float)cos(ang);
}
__global__ void rope_apply_kernel(float* __restrict__ Qd, float* __restrict__ Kd) {
    int idx = blockIdx.x * blockDim.x + threadIdx.x;
    if (idx >= M_TOK * NHEAD * 64) return;
    int j    = idx & 63;
    int rest = idx >> 6;
    int h    = rest & (NHEAD - 1);
    int tok  = rest >> 4;
    int s    = tok & (SEQ - 1);
    float sn = g_rsin[(s << 6) | j];
    float cs = g_rcos[(s << 6) | j];
    size_t base = (size_t)tok * D_MODEL + h * DKH + 2 * j;
    float q1 = Qd[base], q2 = Qd[base + 1];
    Qd[base]     = q1 * cs - q2 * sn;
    Qd[base + 1] = q1 * sn + q2 * cs;
    float k1 = Kd[base], k2 = Kd[base + 1];
    Kd[base]     = k1 * cs - k2 * sn;
    Kd[base + 1] = k1 * sn + k2 * cs;
}

// ---------------- Tensor-core flash attention (causal) ----------------
// BQ=128, BK=64, 256 threads (8 warps, warp w owns q rows [w*16, w*16+16)).
// Q fragments register-resident. K LD=132, V LD=136 (conflict-free), P LD=68.
#define KLD 132
#define VLD 136
#define PLD 68
#define ATT_SMEM ((2*64*KLD + 2*64*VLD + 128*PLD) * 4)

__global__ __launch_bounds__(256) void attn_mma(
        const float* __restrict__ Q,
        const float* __restrict__ K,
        const float* __restrict__ V,
        float* __restrict__ O) {
    extern __shared__ float smf[];
    float* Ks = smf;                          // 2 stages x 64 x KLD
    float* Vs = Ks + 2 * 64 * KLD;            // 2 stages x 64 x VLD
    float* Ps = Vs + 2 * 64 * VLD;            // 128 x PLD

    int tid = threadIdx.x;
    int lane = tid & 31, wid = tid >> 5;
    int qr = lane >> 2, qc = lane & 3;
    int bh = blockIdx.y;
    int b = bh >> 4, h = bh & 15;
    int q0 = blockIdx.x * 128;
    int nkb = 2 * blockIdx.x + 2;

    uint32_t ks_base = smem_u32(Ks);
    uint32_t vs_base = smem_u32(Vs);

    // ---- stage Q through Ks stage0, extract register-resident fragments ----
    uint32_t afq[16][4];
    for (int half = 0; half < 2; half++) {
        for (int i = tid; i < 64 * 32; i += 256) {
            int r = i >> 5, c4 = i & 31;
            float4 v = *(const float4*)(Q + (size_t)(b * SEQ + q0 + half * 64 + r) * D_MODEL
                                          + h * DKH + c4 * 4);
            *(float4*)(Ks + r * KLD + c4 * 4) = v;
        }
        __syncthreads();
        if ((wid >> 2) == half) {
            int r = (wid & 3) * 16 + qr;
#pragma unroll
            for (int ks = 0; ks < 16; ks++) {
                int c = ks * 8 + qc;
                afq[ks][0] = f2tf32(Ks[r * KLD + c]);
                afq[ks][1] = f2tf32(Ks[(r + 8) * KLD + c]);
                afq[ks][2] = f2tf32(Ks[r * KLD + c + 4]);
                afq[ks][3] = f2tf32(Ks[(r + 8) * KLD + c + 4]);
            }
        }
        __syncthreads();
    }

    auto issue_kv = [&](int kb, int stg) {
        uint32_t koff = (uint32_t)stg * 64 * KLD * 4;
        uint32_t voff = (uint32_t)stg * 64 * VLD * 4;
#pragma unroll
        for (int i = 0; i < 8; i++) {
            int idx = tid + i * 256;
            int r = idx >> 5, c4 = idx & 31;
            size_t g = (size_t)(b * SEQ + kb * 64 + r) * D_MODEL + h * DKH + c4 * 4;
            cp_async16(ks_base + koff + (uint32_t)(r * KLD + c4 * 4) * 4, K + g);
            cp_async16(vs_base + voff + (uint32_t)(r * VLD + c4 * 4) * 4, V + g);
        }
    };

    issue_kv(0, 0); CP_COMMIT();

    float o[16][4] = {};
    float m0 = -1e30f, m1 = -1e30f, l0 = 0.f, l1 = 0.f;
    const float scale = 0.08838834764831845f;  // 1/sqrt(128)

    for (int kb = 0; kb < nkb; kb++) {
        if (kb + 1 < nkb) issue_kv(kb + 1, (kb + 1) & 1);
        CP_COMMIT();
        CP_WAIT(1);
        __syncthreads();
        const float* KsS = Ks + (kb & 1) * 64 * KLD;
        const float* VsS = Vs + (kb & 1) * 64 * VLD;

        // S = Q K^T (warp: 16 q-rows x 64 k-cols), Q frags from registers
        float s[8][4] = {};
#pragma unroll
        for (int ks = 0; ks < 16; ks++) {
            int c = ks * 8 + qc;
#pragma unroll
            for (int nt = 0; nt < 8; nt++) {
                int n = nt * 8 + qr;
                uint32_t bf[2];
                bf[0] = f2tf32(KsS[n * KLD + c]);
                bf[1] = f2tf32(KsS[n * KLD + c + 4]);
                mma_tf32(s[nt], afq[ks], bf);
            }
        }

        // mask + online softmax
        bool diag = (kb >= 2 * (int)blockIdx.x);
        int row0 = q0 + wid * 16 + qr, row1 = row0 + 8;
        float mt0 = -1e30f, mt1 = -1e30f;
#pragma unroll
        for (int nt = 0; nt < 8; nt++) {
            int col = kb * 64 + nt * 8 + 2 * qc;
            s[nt][0] *= scale; s[nt][1] *= scale;
            s[nt][2] *= scale; s[nt][3] *= scale;
            if (diag) {
                if (col > row0)     s[nt][0] = -1e30f;
                if (col + 1 > row0) s[nt][1] = -1e30f;
                if (col > row1)     s[nt][2] = -1e30f;
                if (col + 1 > row1) s[nt][3] = -1e30f;
            }
            mt0 = fmaxf(mt0, fmaxf(s[nt][0], s[nt][1]));
            mt1 = fmaxf(mt1, fmaxf(s[nt][2], s[nt][3]));
        }
#pragma unroll
        for (int off = 1; off < 4; off <<= 1) {
            mt0 = fmaxf(mt0, __shfl_xor_sync(0xffffffffu, mt0, off));
            mt1 = fmaxf(mt1, __shfl_xor_sync(0xffffffffu, mt1, off));
        }
        float mn0 = fmaxf(m0, mt0), mn1 = fmaxf(m1, mt1);
        float ls0 = 0.f, ls1 = 0.f;
        int prow = wid * 16 + qr;
#pragma unroll
        for (int nt = 0; nt < 8; nt++) {
            float p0 = __expf(s[nt][0] - mn0);
            float p1 = __expf(s[nt][1] - mn0);
            float p2 = __expf(s[nt][2] - mn1);
            float p3 = __expf(s[nt][3] - mn1);
            ls0 += p0 + p1; ls1 += p2 + p3;
            *(float2*)(Ps + prow * PLD + nt * 8 + 2 * qc)       = make_float2(p0, p1);
            *(float2*)(Ps + (prow + 8) * PLD + nt * 8 + 2 * qc) = make_float2(p2, p3);
        }
#pragma unroll
        for (int off = 1; off < 4; off <<= 1) {
            ls0 += __shfl_xor_sync(0xffffffffu, ls0, off);
            ls1 += __shfl_xor_sync(0xffffffffu, ls1, off);
        }
        float al0 = __expf(m0 - mn0), al1 = __expf(m1 - mn1);
        l0 = l0 * al0 + ls0; l1 = l1 * al1 + ls1;
        m0 = mn0; m1 = mn1;
#pragma unroll
        for (int nt = 0; nt < 16; nt++) {
            o[nt][0] *= al0; o[nt][1] *= al0;
            o[nt][2] *= al1; o[nt][3] *= al1;
        }
        __syncwarp();

        // O += P V
#pragma unroll
        for (int ks = 0; ks < 8; ks++) {
            int c = ks * 8 + qc;
            int r = wid * 16 + qr;
            uint32_t af[4];
            af[0] = f2tf32(Ps[r * PLD + c]);
            af[1] = f2tf32(Ps[(r + 8) * PLD + c]);
            af[2] = f2tf32(Ps[r * PLD + c + 4]);
            af[3] = f2tf32(Ps[(r + 8) * PLD + c + 4]);
#pragma unroll
            for (int nt = 0; nt < 16; nt++) {
                int n = nt * 8 + qr;
                uint32_t bf[2];
                bf[0] = f2tf32(VsS[c * VLD + n]);
                bf[1] = f2tf32(VsS[(c + 4) * VLD + n]);
                mma_tf32(o[nt], af, bf);
            }
        }
        __syncthreads();
    }

    float i0 = 1.f / l0, i1 = 1.f / l1;
    int r0 = b * SEQ + q0 + wid * 16 + qr;
#pragma unroll
    for (int nt = 0; nt < 16; nt++) {
        int cc = h * DKH + nt * 8 + 2 * qc;
        *(float2*)(O + (size_t)r0 * D_MODEL + cc) =
            make_float2(o[nt][0] * i0, o[nt][1] * i0);
        *(float2*)(O + (size_t)(r0 + 8) * D_MODEL + cc) =
            make_float2(o[nt][2] * i1, o[nt][3] * i1);
    }
}

// ---------------- launch ----------------
extern "C" void kernel_launch(void* const* d_in, const int* in_sizes, int n_in,
                              void* d_out, int out_size) {
    const float* x  = (const float*)d_in[0];
    const float* Wq = (const float*)d_in[1];
    const float* Wk = (const float*)d_in[2];
    const float* Wv = (const float*)d_in[3];
    const float* Wo = (const float*)d_in[4];
    const float* W1 = (const float*)d_in[5];
    const float* W2 = (const float*)d_in[6];
    const float* W3 = (const float*)d_in[7];
    const float* g1 = (const float*)d_in[8];
    const float* g2 = (const float*)d_in[9];
    float* out = (float*)d_out;

    float *xn, *qb, *kb, *vb, *ctx, *xmid, *ffb;
    cudaGetSymbolAddress((void**)&xn,   g_xn);
    cudaGetSymbolAddress((void**)&qb,   g_q);
    cudaGetSymbolAddress((void**)&kb,   g_k);
    cudaGetSymbolAddress((void**)&vb,   g_v);
    cudaGetSymbolAddress((void**)&ctx,  g_ctx);
    cudaGetSymbolAddress((void**)&xmid, g_xmid);
    cudaGetSymbolAddress((void**)&ffb,  g_ff);

    cudaFuncSetAttribute(gemm_mma<0>, cudaFuncAttributeMaxDynamicSharedMemorySize, GEMM_SMEM);
    cudaFuncSetAttribute(gemm_mma<1>, cudaFuncAttributeMaxDynamicSharedMemorySize, GEMM_SMEM);
    cudaFuncSetAttribute(gemm_mma<2>, cudaFuncAttributeMaxDynamicSharedMemorySize, GEMM_SMEM);
    cudaFuncSetAttribute(gemm_qkv,    cudaFuncAttributeMaxDynamicSharedMemorySize, GEMM_SMEM);
    cudaFuncSetAttribute(attn_mma,    cudaFuncAttributeMaxDynamicSharedMemorySize, ATT_SMEM);

    dim3 blk(256);
    rmsnorm_kernel<<<M_TOK, 256>>>(x, g1, xn);
    dim3 gq(D_MODEL / GBN, M_TOK / GBM, 3);
    gemm_qkv<<<gq, blk, GEMM_SMEM>>>(xn, Wq, Wk, Wv, qb, kb, vb);
    rope_table_kernel<<<(SEQ * 64 + 255) / 256, 256>>>();
    rope_apply_kernel<<<(M_TOK * NHEAD * 64 + 255) / 256, 256>>>(qb, kb);
    dim3 gattn(SEQ / 128, BATCH * NHEAD);
    attn_mma<<<gattn, blk, ATT_SMEM>>>(qb, kb, vb, ctx);
    dim3 gqkv(D_MODEL / GBN, M_TOK / GBM);
    gemm_mma<1><<<gqkv, blk, GEMM_SMEM>>>(ctx, Wo, x, xmid, M_TOK, D_MODEL, D_MODEL);
    rmsnorm_kernel<<<M_TOK, 256>>>(xmid, g2, xn);
    dim3 gff(DFF / GBN, M_TOK / GBM);
    gemm_mma<0><<<gff, blk, GEMM_SMEM>>>(xn, W1, nullptr, ffb, M_TOK, DFF, D_MODEL);
    gemm_mma<2><<<gff, blk, GEMM_SMEM>>>(xn, W3, nullptr, ffb, M_TOK, DFF, D_MODEL);
    gemm_mma<1><<<gqkv, blk, GEMM_SMEM>>>(ffb, W2, xmid, out, M_TOK, D_MODEL, DFF);
}

// round 6
// speedup vs baseline: 10.7421x; 1.6053x over previous
#include <cuda_runtime.h>
#include <cuda_fp16.h>
#include <math.h>
#include <stdint.h>

#define D_MODEL 2048
#define NHEAD   16
#define DKH     128
#define DFF     5632
#define SEQ     2048
#define BATCH   2
#define M_TOK   (BATCH*SEQ)   // 4096

// ---------------- scratch ----------------
__device__ float  g_q   [(size_t)M_TOK*D_MODEL];
__device__ float  g_k   [(size_t)M_TOK*D_MODEL];
__device__ float  g_v   [(size_t)M_TOK*D_MODEL];
__device__ float  g_xmid[(size_t)M_TOK*D_MODEL];
__device__ float  g_ff  [(size_t)M_TOK*DFF];
__device__ __half g_xn_h [(size_t)M_TOK*D_MODEL];
__device__ __half g_ctx_h[(size_t)M_TOK*D_MODEL];
__device__ __half g_ff_h [(size_t)M_TOK*DFF];
__device__ __half g_wq[(size_t)D_MODEL*D_MODEL];
__device__ __half g_wk[(size_t)D_MODEL*D_MODEL];
__device__ __half g_wv[(size_t)D_MODEL*D_MODEL];
__device__ __half g_wo[(size_t)D_MODEL*D_MODEL];
__device__ __half g_w1[(size_t)DFF*D_MODEL];
__device__ __half g_w2[(size_t)D_MODEL*DFF];
__device__ __half g_w3[(size_t)DFF*D_MODEL];
__device__ float  g_rsin[SEQ*64];
__device__ float  g_rcos[SEQ*64];

// ================= helpers =================
__device__ __forceinline__ uint32_t f2tf32(float x) {
    uint32_t r;
    asm("cvt.rna.tf32.f32 %0, %1;" : "=r"(r) : "f"(x));
    return r;
}
__device__ __forceinline__ void mma_tf32(float* d, const uint32_t* a, const uint32_t* b) {
    asm volatile(
        "mma.sync.aligned.m16n8k8.row.col.f32.tf32.tf32.f32 "
        "{%0,%1,%2,%3}, {%4,%5,%6,%7}, {%8,%9}, {%0,%1,%2,%3};"
        : "+f"(d[0]), "+f"(d[1]), "+f"(d[2]), "+f"(d[3])
        : "r"(a[0]), "r"(a[1]), "r"(a[2]), "r"(a[3]),
          "r"(b[0]), "r"(b[1]));
}
__device__ __forceinline__ void mma_f16(float* d, const uint32_t* a, const uint32_t* b) {
    asm volatile(
        "mma.sync.aligned.m16n8k16.row.col.f32.f16.f16.f32 "
        "{%0,%1,%2,%3}, {%4,%5,%6,%7}, {%8,%9}, {%0,%1,%2,%3};"
        : "+f"(d[0]), "+f"(d[1]), "+f"(d[2]), "+f"(d[3])
        : "r"(a[0]), "r"(a[1]), "r"(a[2]), "r"(a[3]),
          "r"(b[0]), "r"(b[1]));
}
__device__ __forceinline__ uint32_t smem_u32(const void* p) {
    uint32_t a;
    asm("{ .reg .u64 t; cvta.to.shared.u64 t, %1; cvt.u32.u64 %0, t; }"
        : "=r"(a) : "l"(p));
    return a;
}
__device__ __forceinline__ void cp_async16(uint32_t dst, const void* src) {
    asm volatile("cp.async.cg.shared.global [%0], [%1], 16;" :: "r"(dst), "l"(src));
}
#define CP_COMMIT()  asm volatile("cp.async.commit_group;" ::: "memory")
#define CP_WAIT(N)   asm volatile("cp.async.wait_group %0;" :: "n"(N) : "memory")

// ---------------- fp32 -> fp16 convert ----------------
__global__ void f2h_kernel(const float4* __restrict__ in, __half2* __restrict__ out, int n4) {
    int i = blockIdx.x * blockDim.x + threadIdx.x;
    if (i >= n4) return;
    float4 v = in[i];
    out[2 * i]     = __floats2half2_rn(v.x, v.y);
    out[2 * i + 1] = __floats2half2_rn(v.z, v.w);
}

// ================= fp16 GEMM, 256x128 CTA tile, 3-stage cp.async ============
// C[M,N] = A[M,K] @ W[N,K]^T  (half inputs, fp32 accumulate)
// EPI 0: fp32 C = acc; 1: fp32 C = res + acc; 2: half C = silu(res) * acc
// 256 threads = 8 warps (4m x 2n), warp tile 64x64, BK=32 (2 k16 steps).
#define GBM 256
#define GBN 128
#define LDH  40                   // halfs per smem row (32 + 8 pad)
#define LDH2 20                   // uint32 per row
#define GSTG 3
#define GEMM_SMEM (GSTG*(GBM+GBN)*LDH*2)

template<int EPI>
__device__ __forceinline__ void gemm_body(
        const __half* __restrict__ A,
        const __half* __restrict__ W,
        const float* __restrict__ res,
        void* __restrict__ CO,
        int M, int N, int K) {
    extern __shared__ char smc[];
    __half* As = (__half*)smc;                       // [GSTG][GBM][LDH]
    __half* Bs = As + GSTG * GBM * LDH;              // [GSTG][GBN][LDH]

    int tid  = threadIdx.x;
    int lane = tid & 31, wid = tid >> 5;
    int wm = wid >> 1, wn = wid & 1;
    int bm = blockIdx.y * GBM, bn = blockIdx.x * GBN;

    uint32_t as_base = smem_u32(As);
    uint32_t bs_base = smem_u32(Bs);

    auto issue_stage = [&](int tile, int stg) {
        uint32_t aoff = (uint32_t)stg * GBM * LDH * 2;
        uint32_t boff = (uint32_t)stg * GBN * LDH * 2;
        const __half* a2 = A + (size_t)bm * K + tile * 32;
        const __half* w2 = W + (size_t)bn * K + tile * 32;
#pragma unroll
        for (int i = 0; i < 4; i++) {
            int idx = tid + i * 256;          // 0..1023
            int r = idx >> 2, c = (idx & 3) * 8;
            cp_async16(as_base + aoff + (uint32_t)(r * LDH + c) * 2,
                       a2 + (size_t)r * K + c);
        }
#pragma unroll
        for (int i = 0; i < 2; i++) {
            int idx = tid + i * 256;          // 0..511
            int r = idx >> 2, c = (idx & 3) * 8;
            cp_async16(bs_base + boff + (uint32_t)(r * LDH + c) * 2,
                       w2 + (size_t)r * K + c);
        }
    };

    int nk = K >> 5;
    issue_stage(0, 0); CP_COMMIT();
    issue_stage(1, 1); CP_COMMIT();

    float acc[4][8][4] = {};
    int qr = lane >> 2, qc = lane & 3;

    int stg = 0;
    for (int kt = 0; kt < nk; kt++) {
        CP_WAIT(1);
        __syncthreads();
        const uint32_t* A32 = (const uint32_t*)(As + stg * GBM * LDH);
        const uint32_t* B32 = (const uint32_t*)(Bs + stg * GBN * LDH);
#pragma unroll
        for (int ks = 0; ks < 2; ks++) {
            int cb = ks * 8 + qc;             // uint32 column base
            uint32_t af[4][4], bf[8][2];
#pragma unroll
            for (int mt = 0; mt < 4; mt++) {
                int r = wm * 64 + mt * 16 + qr;
                af[mt][0] = A32[r * LDH2 + cb];
                af[mt][1] = A32[(r + 8) * LDH2 + cb];
                af[mt][2] = A32[r * LDH2 + cb + 4];
                af[mt][3] = A32[(r + 8) * LDH2 + cb + 4];
            }
#pragma unroll
            for (int nt = 0; nt < 8; nt++) {
                int n = wn * 64 + nt * 8 + qr;
                bf[nt][0] = B32[n * LDH2 + cb];
                bf[nt][1] = B32[n * LDH2 + cb + 4];
            }
#pragma unroll
            for (int mt = 0; mt < 4; mt++)
#pragma unroll
                for (int nt = 0; nt < 8; nt++)
                    mma_f16(acc[mt][nt], af[mt], bf[nt]);
        }
        int nstg = stg + 2; if (nstg >= GSTG) nstg -= GSTG;
        if (kt + 2 < nk) issue_stage(kt + 2, nstg);
        CP_COMMIT();
        stg = stg + 1 == GSTG ? 0 : stg + 1;
    }

#pragma unroll
    for (int mt = 0; mt < 4; mt++) {
        int r0 = bm + wm * 64 + mt * 16 + qr;
#pragma unroll
        for (int nt = 0; nt < 8; nt++) {
            int cc = bn + wn * 64 + nt * 8 + 2 * qc;
            size_t i0 = (size_t)r0 * N + cc;
            size_t i1 = (size_t)(r0 + 8) * N + cc;
            if (EPI == 0) {
                float* C = (float*)CO;
                *(float2*)(C + i0) = make_float2(acc[mt][nt][0], acc[mt][nt][1]);
                *(float2*)(C + i1) = make_float2(acc[mt][nt][2], acc[mt][nt][3]);
            } else if (EPI == 1) {
                float* C = (float*)CO;
                float2 rr0 = *(const float2*)(res + i0);
                float2 rr1 = *(const float2*)(res + i1);
                *(float2*)(C + i0) = make_float2(acc[mt][nt][0] + rr0.x,
                                                 acc[mt][nt][1] + rr0.y);
                *(float2*)(C + i1) = make_float2(acc[mt][nt][2] + rr1.x,
                                                 acc[mt][nt][3] + rr1.y);
            } else {
                __half* C = (__half*)CO;
                float2 a0 = *(const float2*)(res + i0);
                float2 a1 = *(const float2*)(res + i1);
                float v0 = acc[mt][nt][0] * (a0.x / (1.f + __expf(-a0.x)));
                float v1 = acc[mt][nt][1] * (a0.y / (1.f + __expf(-a0.y)));
                float v2 = acc[mt][nt][2] * (a1.x / (1.f + __expf(-a1.x)));
                float v3 = acc[mt][nt][3] * (a1.y / (1.f + __expf(-a1.y)));
                *(__half2*)(C + i0) = __floats2half2_rn(v0, v1);
                *(__half2*)(C + i1) = __floats2half2_rn(v2, v3);
            }
        }
    }
}

template<int EPI>
__global__ __launch_bounds__(256) void gemm_mma(
        const __half* __restrict__ A, const __half* __restrict__ W,
        const float* __restrict__ res, void* __restrict__ CO,
        int M, int N, int K) {
    gemm_body<EPI>(A, W, res, CO, M, N, K);
}

__global__ __launch_bounds__(256) void gemm_qkv(
        const __half* __restrict__ A,
        float* __restrict__ q, float* __restrict__ k, float* __restrict__ v) {
    const __half* W = blockIdx.z == 0 ? g_wq : (blockIdx.z == 1 ? g_wk : g_wv);
    float* C = blockIdx.z == 0 ? q : (blockIdx.z == 1 ? k : v);
    gemm_body<0>(A, W, nullptr, C, M_TOK, D_MODEL, D_MODEL);
}

// ---------------- RMSNorm (writes half) ----------------
__global__ void rmsnorm_kernel(const float* __restrict__ x,
                               const float* __restrict__ g,
                               __half* __restrict__ out) {
    int row = blockIdx.x;
    const float* xr = x + (size_t)row * D_MODEL;
    __half*      orow = out + (size_t)row * D_MODEL;
    float s = 0.f;
    for (int i = threadIdx.x; i < D_MODEL; i += blockDim.x) {
        float v = xr[i]; s += v * v;
    }
    __shared__ float red[32];
    for (int o = 16; o; o >>= 1) s += __shfl_down_sync(0xffffffffu, s, o);
    if ((threadIdx.x & 31) == 0) red[threadIdx.x >> 5] = s;
    __syncthreads();
    if (threadIdx.x < 32) {
        float v = (threadIdx.x < (blockDim.x >> 5)) ? red[threadIdx.x] : 0.f;
        for (int o = 16; o; o >>= 1) v += __shfl_down_sync(0xffffffffu, v, o);
        if (threadIdx.x == 0) red[0] = v;
    }
    __syncthreads();
    float rinv = rsqrtf(red[0] * (1.0f / D_MODEL) + 1e-5f);
    for (int i = threadIdx.x; i < D_MODEL; i += blockDim.x)
        orow[i] = __float2half(xr[i] * g[i] * rinv);
}

// ---------------- RoPE ----------------
__global__ void rope_table_kernel() {
    int idx = blockIdx.x * blockDim.x + threadIdx.x;
    if (idx >= SEQ * 64) return;
    int j = idx & 63, s = idx >> 6;
    double inv = exp(-(double)j * (9.210340371976184 / 64.0));
    double ang = (double)s * inv;
    g_rsin[idx] = (float)sin(ang);
    g_rcos[idx] = (float)cos(ang);
}
__global__ void rope_apply_kernel(float* __restrict__ Qd, float* __restrict__ Kd) {
    int idx = blockIdx.x * blockDim.x + threadIdx.x;
    if (idx >= M_TOK * NHEAD * 64) return;
    int j    = idx & 63;
    int rest = idx >> 6;
    int h    = rest & (NHEAD - 1);
    int tok  = rest >> 4;
    int s    = tok & (SEQ - 1);
    float sn = g_rsin[(s << 6) | j];
    float cs = g_rcos[(s << 6) | j];
    size_t base = (size_t)tok * D_MODEL + h * DKH + 2 * j;
    float q1 = Qd[base], q2 = Qd[base + 1];
    Qd[base]     = q1 * cs - q2 * sn;
    Qd[base + 1] = q1 * sn + q2 * cs;
    float k1 = Kd[base], k2 = Kd[base + 1];
    Kd[base]     = k1 * cs - k2 * sn;
    Kd[base + 1] = k1 * sn + k2 * cs;
}

// ---------------- Tensor-core flash attention (causal, tf32) ----------------
// BQ=128, BK=64, 256 threads (8 warps). Output written as half (ctx_h).
#define KLD 132
#define VLD 136
#define PLD 68
#define ATT_SMEM ((2*64*KLD + 2*64*VLD + 128*PLD) * 4)

__global__ __launch_bounds__(256) void attn_mma(
        const float* __restrict__ Q,
        const float* __restrict__ K,
        const float* __restrict__ V,
        __half* __restrict__ O) {
    extern __shared__ float smf[];
    float* Ks = smf;
    float* Vs = Ks + 2 * 64 * KLD;
    float* Ps = Vs + 2 * 64 * VLD;

    int tid = threadIdx.x;
    int lane = tid & 31, wid = tid >> 5;
    int qr = lane >> 2, qc = lane & 3;
    int bh = blockIdx.y;
    int b = bh >> 4, h = bh & 15;
    int q0 = blockIdx.x * 128;
    int nkb = 2 * blockIdx.x + 2;

    uint32_t ks_base = smem_u32(Ks);
    uint32_t vs_base = smem_u32(Vs);

    // stage Q through Ks stage0, extract register-resident fragments
    uint32_t afq[16][4];
    for (int half_ = 0; half_ < 2; half_++) {
        for (int i = tid; i < 64 * 32; i += 256) {
            int r = i >> 5, c4 = i & 31;
            float4 v = *(const float4*)(Q + (size_t)(b * SEQ + q0 + half_ * 64 + r) * D_MODEL
                                          + h * DKH + c4 * 4);
            *(float4*)(Ks + r * KLD + c4 * 4) = v;
        }
        __syncthreads();
        if ((wid >> 2) == half_) {
            int r = (wid & 3) * 16 + qr;
#pragma unroll
            for (int ks = 0; ks < 16; ks++) {
                int c = ks * 8 + qc;
                afq[ks][0] = f2tf32(Ks[r * KLD + c]);
                afq[ks][1] = f2tf32(Ks[(r + 8) * KLD + c]);
                afq[ks][2] = f2tf32(Ks[r * KLD + c + 4]);
                afq[ks][3] = f2tf32(Ks[(r + 8) * KLD + c + 4]);
            }
        }
        __syncthreads();
    }

    auto issue_kv = [&](int kb, int stg) {
        uint32_t koff = (uint32_t)stg * 64 * KLD * 4;
        uint32_t voff = (uint32_t)stg * 64 * VLD * 4;
#pragma unroll
        for (int i = 0; i < 8; i++) {
            int idx = tid + i * 256;
            int r = idx >> 5, c4 = idx & 31;
            size_t g = (size_t)(b * SEQ + kb * 64 + r) * D_MODEL + h * DKH + c4 * 4;
            cp_async16(ks_base + koff + (uint32_t)(r * KLD + c4 * 4) * 4, K + g);
            cp_async16(vs_base + voff + (uint32_t)(r * VLD + c4 * 4) * 4, V + g);
        }
    };

    issue_kv(0, 0); CP_COMMIT();

    float o[16][4] = {};
    float m0 = -1e30f, m1 = -1e30f, l0 = 0.f, l1 = 0.f;
    const float scale = 0.08838834764831845f;

    for (int kb = 0; kb < nkb; kb++) {
        if (kb + 1 < nkb) issue_kv(kb + 1, (kb + 1) & 1);
        CP_COMMIT();
        CP_WAIT(1);
        __syncthreads();
        const float* KsS = Ks + (kb & 1) * 64 * KLD;
        const float* VsS = Vs + (kb & 1) * 64 * VLD;

        float s[8][4] = {};
#pragma unroll
        for (int ks = 0; ks < 16; ks++) {
            int c = ks * 8 + qc;
#pragma unroll
            for (int nt = 0; nt < 8; nt++) {
                int n = nt * 8 + qr;
                uint32_t bf[2];
                bf[0] = f2tf32(KsS[n * KLD + c]);
                bf[1] = f2tf32(KsS[n * KLD + c + 4]);
                mma_tf32(s[nt], afq[ks], bf);
            }
        }

        bool diag = (kb >= 2 * (int)blockIdx.x);
        int row0 = q0 + wid * 16 + qr, row1 = row0 + 8;
        float mt0 = -1e30f, mt1 = -1e30f;
#pragma unroll
        for (int nt = 0; nt < 8; nt++) {
            int col = kb * 64 + nt * 8 + 2 * qc;
            s[nt][0] *= scale; s[nt][1] *= scale;
            s[nt][2] *= scale; s[nt][3] *= scale;
            if (diag) {
                if (col > row0)     s[nt][0] = -1e30f;
                if (col + 1 > row0) s[nt][1] = -1e30f;
                if (col > row1)     s[nt][2] = -1e30f;
                if (col + 1 > row1) s[nt][3] = -1e30f;
            }
            mt0 = fmaxf(mt0, fmaxf(s[nt][0], s[nt][1]));
            mt1 = fmaxf(mt1, fmaxf(s[nt][2], s[nt][3]));
        }
#pragma unroll
        for (int off = 1; off < 4; off <<= 1) {
            mt0 = fmaxf(mt0, __shfl_xor_sync(0xffffffffu, mt0, off));
            mt1 = fmaxf(mt1, __shfl_xor_sync(0xffffffffu, mt1, off));
        }
        float mn0 = fmaxf(m0, mt0), mn1 = fmaxf(m1, mt1);
        float ls0 = 0.f, ls1 = 0.f;
        int prow = wid * 16 + qr;
#pragma unroll
        for (int nt = 0; nt < 8; nt++) {
            float p0 = __expf(s[nt][0] - mn0);
            float p1 = __expf(s[nt][1] - mn0);
            float p2 = __expf(s[nt][2] - mn1);
            float p3 = __expf(s[nt][3] - mn1);
            ls0 += p0 + p1; ls1 += p2 + p3;
            *(float2*)(Ps + prow * PLD + nt * 8 + 2 * qc)       = make_float2(p0, p1);
            *(float2*)(Ps + (prow + 8) * PLD + nt * 8 + 2 * qc) = make_float2(p2, p3);
        }
#pragma unroll
        for (int off = 1; off < 4; off <<= 1) {
            ls0 += __shfl_xor_sync(0xffffffffu, ls0, off);
            ls1 += __shfl_xor_sync(0xffffffffu, ls1, off);
        }
        float al0 = __expf(m0 - mn0), al1 = __expf(m1 - mn1);
        l0 = l0 * al0 + ls0; l1 = l1 * al1 + ls1;
        m0 = mn0; m1 = mn1;
#pragma unroll
        for (int nt = 0; nt < 16; nt++) {
            o[nt][0] *= al0; o[nt][1] *= al0;
            o[nt][2] *= al1; o[nt][3] *= al1;
        }
        __syncwarp();

#pragma unroll
        for (int ks = 0; ks < 8; ks++) {
            int c = ks * 8 + qc;
            int r = wid * 16 + qr;
            uint32_t af[4];
            af[0] = f2tf32(Ps[r * PLD + c]);
            af[1] = f2tf32(Ps[(r + 8) * PLD + c]);
            af[2] = f2tf32(Ps[r * PLD + c + 4]);
            af[3] = f2tf32(Ps[(r + 8) * PLD + c + 4]);
#pragma unroll
            for (int nt = 0; nt < 16; nt++) {
                int n = nt * 8 + qr;
                uint32_t bf[2];
                bf[0] = f2tf32(VsS[c * VLD + n]);
                bf[1] = f2tf32(VsS[(c + 4) * VLD + n]);
                mma_tf32(o[nt], af, bf);
            }
        }
        __syncthreads();
    }

    float i0 = 1.f / l0, i1 = 1.f / l1;
    int r0 = b * SEQ + q0 + wid * 16 + qr;
#pragma unroll
    for (int nt = 0; nt < 16; nt++) {
        int cc = h * DKH + nt * 8 + 2 * qc;
        *(__half2*)(O + (size_t)r0 * D_MODEL + cc) =
            __floats2half2_rn(o[nt][0] * i0, o[nt][1] * i0);
        *(__half2*)(O + (size_t)(r0 + 8) * D_MODEL + cc) =
            __floats2half2_rn(o[nt][2] * i1, o[nt][3] * i1);
    }
}

// ---------------- launch ----------------
extern "C" void kernel_launch(void* const* d_in, const int* in_sizes, int n_in,
                              void* d_out, int out_size) {
    const float* x  = (const float*)d_in[0];
    const float* Wq = (const float*)d_in[1];
    const float* Wk = (const float*)d_in[2];
    const float* Wv = (const float*)d_in[3];
    const float* Wo = (const float*)d_in[4];
    const float* W1 = (const float*)d_in[5];
    const float* W2 = (const float*)d_in[6];
    const float* W3 = (const float*)d_in[7];
    const float* g1 = (const float*)d_in[8];
    const float* g2 = (const float*)d_in[9];
    float* out = (float*)d_out;

    float *qb, *kb, *vb, *xmid, *ffb;
    __half *xnh, *ctxh, *ffh, *wqh, *wkh, *wvh, *woh, *w1h, *w2h, *w3h;
    cudaGetSymbolAddress((void**)&qb,   g_q);
    cudaGetSymbolAddress((void**)&kb,   g_k);
    cudaGetSymbolAddress((void**)&vb,   g_v);
    cudaGetSymbolAddress((void**)&xmid, g_xmid);
    cudaGetSymbolAddress((void**)&ffb,  g_ff);
    cudaGetSymbolAddress((void**)&xnh,  g_xn_h);
    cudaGetSymbolAddress((void**)&ctxh, g_ctx_h);
    cudaGetSymbolAddress((void**)&ffh,  g_ff_h);
    cudaGetSymbolAddress((void**)&wqh,  g_wq);
    cudaGetSymbolAddress((void**)&wkh,  g_wk);
    cudaGetSymbolAddress((void**)&wvh,  g_wv);
    cudaGetSymbolAddress((void**)&woh,  g_wo);
    cudaGetSymbolAddress((void**)&w1h,  g_w1);
    cudaGetSymbolAddress((void**)&w2h,  g_w2);
    cudaGetSymbolAddress((void**)&w3h,  g_w3);

    cudaFuncSetAttribute(gemm_mma<0>, cudaFuncAttributeMaxDynamicSharedMemorySize, GEMM_SMEM);
    cudaFuncSetAttribute(gemm_mma<1>, cudaFuncAttributeMaxDynamicSharedMemorySize, GEMM_SMEM);
    cudaFuncSetAttribute(gemm_mma<2>, cudaFuncAttributeMaxDynamicSharedMemorySize, GEMM_SMEM);
    cudaFuncSetAttribute(gemm_qkv,    cudaFuncAttributeMaxDynamicSharedMemorySize, GEMM_SMEM);
    cudaFuncSetAttribute(attn_mma,    cudaFuncAttributeMaxDynamicSharedMemorySize, ATT_SMEM);

    // weight conversion (once per call; bandwidth-bound, ~40us total)
    const int CT = 256;
    int nDM = D_MODEL * D_MODEL / 4, nFF = DFF * D_MODEL / 4;
    f2h_kernel<<<(nDM + CT - 1) / CT, CT>>>((const float4*)Wq, (__half2*)wqh, nDM);
    f2h_kernel<<<(nDM + CT - 1) / CT, CT>>>((const float4*)Wk, (__half2*)wkh, nDM);
    f2h_kernel<<<(nDM + CT - 1) / CT, CT>>>((const float4*)Wv, (__half2*)wvh, nDM);
    f2h_kernel<<<(nDM + CT - 1) / CT, CT>>>((const float4*)Wo, (__half2*)woh, nDM);
    f2h_kernel<<<(nFF + CT - 1) / CT, CT>>>((const float4*)W1, (__half2*)w1h, nFF);
    f2h_kernel<<<(nFF + CT - 1) / CT, CT>>>((const float4*)W2, (__half2*)w2h, nFF);
    f2h_kernel<<<(nFF + CT - 1) / CT, CT>>>((const float4*)W3, (__half2*)w3h, nFF);

    dim3 blk(256);
    rmsnorm_kernel<<<M_TOK, 256>>>(x, g1, xnh);
    dim3 gq(D_MODEL / GBN, M_TOK / GBM, 3);
    gemm_qkv<<<gq, blk, GEMM_SMEM>>>(xnh, qb, kb, vb);
    rope_table_kernel<<<(SEQ * 64 + 255) / 256, 256>>>();
    rope_apply_kernel<<<(M_TOK * NHEAD * 64 + 255) / 256, 256>>>(qb, kb);
    dim3 gattn(SEQ / 128, BATCH * NHEAD);
    attn_mma<<<gattn, blk, ATT_SMEM>>>(qb, kb, vb, ctxh);
    dim3 gqkv(D_MODEL / GBN, M_TOK / GBM);
    gemm_mma<1><<<gqkv, blk, GEMM_SMEM>>>(ctxh, woh, x, xmid, M_TOK, D_MODEL, D_MODEL);
    rmsnorm_kernel<<<M_TOK, 256>>>(xmid, g2, xnh);
    dim3 gff(DFF / GBN, M_TOK / GBM);
    gemm_mma<0><<<gff, blk, GEMM_SMEM>>>(xnh, w1h, nullptr, ffb, M_TOK, DFF, D_MODEL);
    gemm_mma<2><<<gff, blk, GEMM_SMEM>>>(xnh, w3h, ffb, ffh, M_TOK, DFF, D_MODEL);
    gemm_mma<1><<<gqkv, blk, GEMM_SMEM>>>(ffh, w2h, xmid, out, M_TOK, D_MODEL, DFF);
}

// round 7
// speedup vs baseline: 11.8482x; 1.1030x over previous
#include <cuda_runtime.h>
#include <cuda_fp16.h>
#include <math.h>
#include <stdint.h>

#define D_MODEL 2048
#define NHEAD   16
#define DKH     128
#define DFF     5632
#define SEQ     2048
#define BATCH   2
#define M_TOK   (BATCH*SEQ)   // 4096

// ---------------- scratch ----------------
__device__ float  g_xmid[(size_t)M_TOK*D_MODEL];
__device__ float  g_ff  [(size_t)M_TOK*DFF];
__device__ __half g_xn_h [(size_t)M_TOK*D_MODEL];
__device__ __half g_ctx_h[(size_t)M_TOK*D_MODEL];
__device__ __half g_ff_h [(size_t)M_TOK*DFF];
__device__ __half g_qh[(size_t)M_TOK*D_MODEL];
__device__ __half g_kh[(size_t)M_TOK*D_MODEL];
__device__ __half g_vh[(size_t)M_TOK*D_MODEL];
__device__ __half g_wq[(size_t)D_MODEL*D_MODEL];
__device__ __half g_wk[(size_t)D_MODEL*D_MODEL];
__device__ __half g_wv[(size_t)D_MODEL*D_MODEL];
__device__ __half g_wo[(size_t)D_MODEL*D_MODEL];
__device__ __half g_w1[(size_t)DFF*D_MODEL];
__device__ __half g_w2[(size_t)D_MODEL*DFF];
__device__ __half g_w3[(size_t)DFF*D_MODEL];
__device__ float  g_rsin[SEQ*64];
__device__ float  g_rcos[SEQ*64];

// ================= helpers =================
__device__ __forceinline__ void mma_f16(float* d, const uint32_t* a, const uint32_t* b) {
    asm volatile(
        "mma.sync.aligned.m16n8k16.row.col.f32.f16.f16.f32 "
        "{%0,%1,%2,%3}, {%4,%5,%6,%7}, {%8,%9}, {%0,%1,%2,%3};"
        : "+f"(d[0]), "+f"(d[1]), "+f"(d[2]), "+f"(d[3])
        : "r"(a[0]), "r"(a[1]), "r"(a[2]), "r"(a[3]),
          "r"(b[0]), "r"(b[1]));
}
__device__ __forceinline__ uint32_t smem_u32(const void* p) {
    uint32_t a;
    asm("{ .reg .u64 t; cvta.to.shared.u64 t, %1; cvt.u32.u64 %0, t; }"
        : "=r"(a) : "l"(p));
    return a;
}
__device__ __forceinline__ void cp_async16(uint32_t dst, const void* src) {
    asm volatile("cp.async.cg.shared.global [%0], [%1], 16;" :: "r"(dst), "l"(src));
}
#define CP_COMMIT()  asm volatile("cp.async.commit_group;" ::: "memory")
#define CP_WAIT(N)   asm volatile("cp.async.wait_group %0;" :: "n"(N) : "memory")

__device__ __forceinline__ void ldsm_x4(uint32_t* r, uint32_t a) {
    asm volatile("ldmatrix.sync.aligned.m8n8.x4.shared.b16 {%0,%1,%2,%3}, [%4];"
                 : "=r"(r[0]), "=r"(r[1]), "=r"(r[2]), "=r"(r[3]) : "r"(a));
}
__device__ __forceinline__ void ldsm_x4_t(uint32_t* r, uint32_t a) {
    asm volatile("ldmatrix.sync.aligned.m8n8.x4.trans.shared.b16 {%0,%1,%2,%3}, [%4];"
                 : "=r"(r[0]), "=r"(r[1]), "=r"(r[2]), "=r"(r[3]) : "r"(a));
}

// ---------------- fp32 -> fp16 convert ----------------
__global__ void f2h_kernel(const float4* __restrict__ in, __half2* __restrict__ out, int n4) {
    int i = blockIdx.x * blockDim.x + threadIdx.x;
    if (i >= n4) return;
    float4 v = in[i];
    out[2 * i]     = __floats2half2_rn(v.x, v.y);
    out[2 * i + 1] = __floats2half2_rn(v.z, v.w);
}

// ================= fp16 GEMM, 256x128 CTA tile, 3-stage cp.async ============
// C[M,N] = A[M,K] @ W[N,K]^T  (half in, fp32 accumulate)
// EPI 0: fp32 C=acc; 1: fp32 C=res+acc; 2: half C=silu(res)*acc;
// EPI 3: half C=acc with optional RoPE rotation (ropef)
#define GBM 256
#define GBN 128
#define LDH  40
#define LDH2 20
#define GSTG 3
#define GEMM_SMEM (GSTG*(GBM+GBN)*LDH*2)

template<int EPI>
__device__ __forceinline__ void gemm_body(
        const __half* __restrict__ A,
        const __half* __restrict__ W,
        const float* __restrict__ res,
        void* __restrict__ CO,
        int M, int N, int K, int ropef) {
    extern __shared__ char smc[];
    __half* As = (__half*)smc;
    __half* Bs = As + GSTG * GBM * LDH;

    int tid  = threadIdx.x;
    int lane = tid & 31, wid = tid >> 5;
    int wm = wid >> 1, wn = wid & 1;
    int bm = blockIdx.y * GBM, bn = blockIdx.x * GBN;

    uint32_t as_base = smem_u32(As);
    uint32_t bs_base = smem_u32(Bs);

    auto issue_stage = [&](int tile, int stg) {
        uint32_t aoff = (uint32_t)stg * GBM * LDH * 2;
        uint32_t boff = (uint32_t)stg * GBN * LDH * 2;
        const __half* a2 = A + (size_t)bm * K + tile * 32;
        const __half* w2 = W + (size_t)bn * K + tile * 32;
#pragma unroll
        for (int i = 0; i < 4; i++) {
            int idx = tid + i * 256;
            int r = idx >> 2, c = (idx & 3) * 8;
            cp_async16(as_base + aoff + (uint32_t)(r * LDH + c) * 2,
                       a2 + (size_t)r * K + c);
        }
#pragma unroll
        for (int i = 0; i < 2; i++) {
            int idx = tid + i * 256;
            int r = idx >> 2, c = (idx & 3) * 8;
            cp_async16(bs_base + boff + (uint32_t)(r * LDH + c) * 2,
                       w2 + (size_t)r * K + c);
        }
    };

    int nk = K >> 5;
    issue_stage(0, 0); CP_COMMIT();
    issue_stage(1, 1); CP_COMMIT();

    float acc[4][8][4] = {};
    int qr = lane >> 2, qc = lane & 3;

    int stg = 0;
    for (int kt = 0; kt < nk; kt++) {
        CP_WAIT(1);
        __syncthreads();
        const uint32_t* A32 = (const uint32_t*)(As + stg * GBM * LDH);
        const uint32_t* B32 = (const uint32_t*)(Bs + stg * GBN * LDH);
#pragma unroll
        for (int ks = 0; ks < 2; ks++) {
            int cb = ks * 8 + qc;
            uint32_t af[4][4], bf[8][2];
#pragma unroll
            for (int mt = 0; mt < 4; mt++) {
                int r = wm * 64 + mt * 16 + qr;
                af[mt][0] = A32[r * LDH2 + cb];
                af[mt][1] = A32[(r + 8) * LDH2 + cb];
                af[mt][2] = A32[r * LDH2 + cb + 4];
                af[mt][3] = A32[(r + 8) * LDH2 + cb + 4];
            }
#pragma unroll
            for (int nt = 0; nt < 8; nt++) {
                int n = wn * 64 + nt * 8 + qr;
                bf[nt][0] = B32[n * LDH2 + cb];
                bf[nt][1] = B32[n * LDH2 + cb + 4];
            }
#pragma unroll
            for (int mt = 0; mt < 4; mt++)
#pragma unroll
                for (int nt = 0; nt < 8; nt++)
                    mma_f16(acc[mt][nt], af[mt], bf[nt]);
        }
        int nstg = stg + 2; if (nstg >= GSTG) nstg -= GSTG;
        if (kt + 2 < nk) issue_stage(kt + 2, nstg);
        CP_COMMIT();
        stg = stg + 1 == GSTG ? 0 : stg + 1;
    }

#pragma unroll
    for (int mt = 0; mt < 4; mt++) {
        int r0 = bm + wm * 64 + mt * 16 + qr;
#pragma unroll
        for (int nt = 0; nt < 8; nt++) {
            int cc = bn + wn * 64 + nt * 8 + 2 * qc;
            size_t i0 = (size_t)r0 * N + cc;
            size_t i1 = (size_t)(r0 + 8) * N + cc;
            if (EPI == 0) {
                float* C = (float*)CO;
                *(float2*)(C + i0) = make_float2(acc[mt][nt][0], acc[mt][nt][1]);
                *(float2*)(C + i1) = make_float2(acc[mt][nt][2], acc[mt][nt][3]);
            } else if (EPI == 1) {
                float* C = (float*)CO;
                float2 rr0 = *(const float2*)(res + i0);
                float2 rr1 = *(const float2*)(res + i1);
                *(float2*)(C + i0) = make_float2(acc[mt][nt][0] + rr0.x,
                                                 acc[mt][nt][1] + rr0.y);
                *(float2*)(C + i1) = make_float2(acc[mt][nt][2] + rr1.x,
                                                 acc[mt][nt][3] + rr1.y);
            } else if (EPI == 2) {
                __half* C = (__half*)CO;
                float2 a0 = *(const float2*)(res + i0);
                float2 a1 = *(const float2*)(res + i1);
                float v0 = acc[mt][nt][0] * (a0.x / (1.f + __expf(-a0.x)));
                float v1 = acc[mt][nt][1] * (a0.y / (1.f + __expf(-a0.y)));
                float v2 = acc[mt][nt][2] * (a1.x / (1.f + __expf(-a1.x)));
                float v3 = acc[mt][nt][3] * (a1.y / (1.f + __expf(-a1.y)));
                *(__half2*)(C + i0) = __floats2half2_rn(v0, v1);
                *(__half2*)(C + i1) = __floats2half2_rn(v2, v3);
            } else {
                __half* C = (__half*)CO;
                float a0 = acc[mt][nt][0], a1 = acc[mt][nt][1];
                float a2 = acc[mt][nt][2], a3 = acc[mt][nt][3];
                if (ropef) {
                    int s0 = r0 & (SEQ - 1), s1 = (r0 + 8) & (SEQ - 1);
                    int j  = (cc & 127) >> 1;
                    float sn0 = g_rsin[s0 * 64 + j], cs0 = g_rcos[s0 * 64 + j];
                    float sn1 = g_rsin[s1 * 64 + j], cs1 = g_rcos[s1 * 64 + j];
                    *(__half2*)(C + i0) = __floats2half2_rn(a0 * cs0 - a1 * sn0,
                                                            a0 * sn0 + a1 * cs0);
                    *(__half2*)(C + i1) = __floats2half2_rn(a2 * cs1 - a3 * sn1,
                                                            a2 * sn1 + a3 * cs1);
                } else {
                    *(__half2*)(C + i0) = __floats2half2_rn(a0, a1);
                    *(__half2*)(C + i1) = __floats2half2_rn(a2, a3);
                }
            }
        }
    }
}

template<int EPI>
__global__ __launch_bounds__(256) void gemm_mma(
        const __half* __restrict__ A, const __half* __restrict__ W,
        const float* __restrict__ res, void* __restrict__ CO,
        int M, int N, int K) {
    gemm_body<EPI>(A, W, res, CO, M, N, K, 0);
}

__global__ __launch_bounds__(256) void gemm_qkv(const __half* __restrict__ A) {
    int z = blockIdx.z;
    const __half* W = z == 0 ? g_wq : (z == 1 ? g_wk : g_wv);
    __half* C = z == 0 ? g_qh : (z == 1 ? g_kh : g_vh);
    gemm_body<3>(A, W, nullptr, C, M_TOK, D_MODEL, D_MODEL, z < 2);
}

// ---------------- RMSNorm (writes half) ----------------
__global__ void rmsnorm_kernel(const float* __restrict__ x,
                               const float* __restrict__ g,
                               __half* __restrict__ out) {
    int row = blockIdx.x;
    const float* xr = x + (size_t)row * D_MODEL;
    __half*      orow = out + (size_t)row * D_MODEL;
    float s = 0.f;
    for (int i = threadIdx.x; i < D_MODEL; i += blockDim.x) {
        float v = xr[i]; s += v * v;
    }
    __shared__ float red[32];
    for (int o = 16; o; o >>= 1) s += __shfl_down_sync(0xffffffffu, s, o);
    if ((threadIdx.x & 31) == 0) red[threadIdx.x >> 5] = s;
    __syncthreads();
    if (threadIdx.x < 32) {
        float v = (threadIdx.x < (blockDim.x >> 5)) ? red[threadIdx.x] : 0.f;
        for (int o = 16; o; o >>= 1) v += __shfl_down_sync(0xffffffffu, v, o);
        if (threadIdx.x == 0) red[0] = v;
    }
    __syncthreads();
    float rinv = rsqrtf(red[0] * (1.0f / D_MODEL) + 1e-5f);
    for (int i = threadIdx.x; i < D_MODEL; i += blockDim.x)
        orow[i] = __float2half(xr[i] * g[i] * rinv);
}

// ---------------- RoPE tables ----------------
__global__ void rope_table_kernel() {
    int idx = blockIdx.x * blockDim.x + threadIdx.x;
    if (idx >= SEQ * 64) return;
    int j = idx & 63, s = idx >> 6;
    double inv = exp(-(double)j * (9.210340371976184 / 64.0));
    double ang = (double)s * inv;
    g_rsin[idx] = (float)sin(ang);
    g_rcos[idx] = (float)cos(ang);
}

// ---------------- fp16 tensor-core flash attention (causal) ----------------
// BQ=128, BK=64, 256 threads (8 warps, warp w owns q rows [w*16, w*16+16)).
// Q/K/P fragments via ldmatrix (non-trans), V via ldmatrix.trans.
#define QLD 136     // halfs per Q-stage row
#define KLH 136     // halfs per K/V smem row (128 + 8)
#define PLH 72      // halfs per P row (64 + 8)
#define ATT_SMEM ((2*64*KLH + 2*64*KLH + 128*PLH) * 2)

__global__ __launch_bounds__(256) void attn_f16(
        const __half* __restrict__ Q,
        const __half* __restrict__ K,
        const __half* __restrict__ V,
        __half* __restrict__ O) {
    extern __shared__ __half smh[];
    __half* Qst = smh;                    // staging, overlaps K/V/P
    __half* Ksm = smh;                    // 2 x 64 x KLH
    __half* Vsm = Ksm + 2 * 64 * KLH;     // 2 x 64 x KLH
    __half* Psm = Vsm + 2 * 64 * KLH;     // 128 x PLH

    int tid = threadIdx.x;
    int lane = tid & 31, wid = tid >> 5;
    int qr = lane >> 2, qc = lane & 3;
    int bh = blockIdx.y;
    int b = bh >> 4, h = bh & 15;
    int q0 = blockIdx.x * 128;
    int nkb = 2 * blockIdx.x + 2;
    int m4 = lane >> 3;                   // ldmatrix matrix id
    int r8 = lane & 7;                    // ldmatrix row-in-matrix

    // ---- stage Q, extract register A-fragments ----
    for (int i = tid; i < 128 * 16; i += 256) {
        int r = i >> 4, c8 = (i & 15) * 8;
        *(uint4*)(Qst + r * QLD + c8) =
            *(const uint4*)(Q + (size_t)(b * SEQ + q0 + r) * D_MODEL + h * DKH + c8);
    }
    __syncthreads();
    uint32_t afq[8][4];
    {
        uint32_t qb_ = smem_u32(Qst);
        int row = wid * 16 + (m4 & 1) * 8 + r8;
#pragma unroll
        for (int ks = 0; ks < 8; ks++)
            ldsm_x4(afq[ks], qb_ + (uint32_t)(row * QLD + ks * 16 + (m4 >> 1) * 8) * 2);
    }
    __syncthreads();

    uint32_t ks_base = smem_u32(Ksm);
    uint32_t vs_base = smem_u32(Vsm);
    auto issue_kv = [&](int kb, int stg) {
        uint32_t off = (uint32_t)stg * 64 * KLH * 2;
#pragma unroll
        for (int i = 0; i < 4; i++) {
            int idx = tid + i * 256;
            int r = idx >> 4, c8 = (idx & 15) * 8;
            size_t g = (size_t)(b * SEQ + kb * 64 + r) * D_MODEL + h * DKH + c8;
            uint32_t d = (uint32_t)(r * KLH + c8) * 2;
            cp_async16(ks_base + off + d, K + g);
            cp_async16(vs_base + off + d, V + g);
        }
    };

    issue_kv(0, 0); CP_COMMIT();

    float o[16][4] = {};
    float m0 = -1e30f, m1 = -1e30f, l0 = 0.f, l1 = 0.f;
    const float scale = 0.08838834764831845f;   // 1/sqrt(128)

    for (int kb = 0; kb < nkb; kb++) {
        if (kb + 1 < nkb) issue_kv(kb + 1, (kb + 1) & 1);
        CP_COMMIT();
        CP_WAIT(1);
        __syncthreads();
        uint32_t kst = ks_base + (uint32_t)(kb & 1) * 64 * KLH * 2;
        uint32_t vst = vs_base + (uint32_t)(kb & 1) * 64 * KLH * 2;

        // ---- S = Q K^T ----
        float s[8][4] = {};
#pragma unroll
        for (int c2 = 0; c2 < 4; c2++) {         // k32 chunks
#pragma unroll
            for (int n0 = 0; n0 < 8; n0++) {     // key groups of 8
                uint32_t kf[4];
                ldsm_x4(kf, kst + (uint32_t)((n0 * 8 + r8) * KLH + c2 * 32 + m4 * 8) * 2);
                mma_f16(s[n0], afq[2 * c2],     kf);
                mma_f16(s[n0], afq[2 * c2 + 1], kf + 2);
            }
        }

        // ---- mask + online softmax ----
        bool diag = (kb >= 2 * (int)blockIdx.x);
        int row0 = q0 + wid * 16 + qr, row1 = row0 + 8;
        float mt0 = -1e30f, mt1 = -1e30f;
#pragma unroll
        for (int nt = 0; nt < 8; nt++) {
            int col = kb * 64 + nt * 8 + 2 * qc;
            s[nt][0] *= scale; s[nt][1] *= scale;
            s[nt][2] *= scale; s[nt][3] *= scale;
            if (diag) {
                if (col > row0)     s[nt][0] = -1e30f;
                if (col + 1 > row0) s[nt][1] = -1e30f;
                if (col > row1)     s[nt][2] = -1e30f;
                if (col + 1 > row1) s[nt][3] = -1e30f;
            }
            mt0 = fmaxf(mt0, fmaxf(s[nt][0], s[nt][1]));
            mt1 = fmaxf(mt1, fmaxf(s[nt][2], s[nt][3]));
        }
#pragma unroll
        for (int off = 1; off < 4; off <<= 1) {
            mt0 = fmaxf(mt0, __shfl_xor_sync(0xffffffffu, mt0, off));
            mt1 = fmaxf(mt1, __shfl_xor_sync(0xffffffffu, mt1, off));
        }
        float mn0 = fmaxf(m0, mt0), mn1 = fmaxf(m1, mt1);
        float ls0 = 0.f, ls1 = 0.f;
        int prow = wid * 16 + qr;
#pragma unroll
        for (int nt = 0; nt < 8; nt++) {
            __half2 h01 = __floats2half2_rn(__expf(s[nt][0] - mn0), __expf(s[nt][1] - mn0));
            __half2 h23 = __floats2half2_rn(__expf(s[nt][2] - mn1), __expf(s[nt][3] - mn1));
            float2 f01 = __half22float2(h01), f23 = __half22float2(h23);
            ls0 += f01.x + f01.y; ls1 += f23.x + f23.y;
            *(__half2*)(Psm + prow * PLH + nt * 8 + 2 * qc)       = h01;
            *(__half2*)(Psm + (prow + 8) * PLH + nt * 8 + 2 * qc) = h23;
        }
#pragma unroll
        for (int off = 1; off < 4; off <<= 1) {
            ls0 += __shfl_xor_sync(0xffffffffu, ls0, off);
            ls1 += __shfl_xor_sync(0xffffffffu, ls1, off);
        }
        float al0 = __expf(m0 - mn0), al1 = __expf(m1 - mn1);
        l0 = l0 * al0 + ls0; l1 = l1 * al1 + ls1;
        m0 = mn0; m1 = mn1;
#pragma unroll
        for (int nt = 0; nt < 16; nt++) {
            o[nt][0] *= al0; o[nt][1] *= al0;
            o[nt][2] *= al1; o[nt][3] *= al1;
        }
        __syncwarp();

        // ---- O += P V ----
        uint32_t afp[4][4];
        {
            uint32_t pb = smem_u32(Psm);
            int row = wid * 16 + (m4 & 1) * 8 + r8;
#pragma unroll
            for (int ks = 0; ks < 4; ks++)
                ldsm_x4(afp[ks], pb + (uint32_t)(row * PLH + ks * 16 + (m4 >> 1) * 8) * 2);
        }
#pragma unroll
        for (int ks = 0; ks < 4; ks++) {          // key16 chunks
#pragma unroll
            for (int g = 0; g < 8; g++) {         // d16 groups
                uint32_t vf[4];
                ldsm_x4_t(vf, vst + (uint32_t)((ks * 16 + (m4 & 1) * 8 + r8) * KLH
                                               + g * 16 + (m4 >> 1) * 8) * 2);
                mma_f16(o[2 * g],     afp[ks], vf);
                mma_f16(o[2 * g + 1], afp[ks], vf + 2);
            }
        }
        __syncthreads();
    }

    float i0 = 1.f / l0, i1 = 1.f / l1;
    int r0 = b * SEQ + q0 + wid * 16 + qr;
#pragma unroll
    for (int nt = 0; nt < 16; nt++) {
        int cc = h * DKH + nt * 8 + 2 * qc;
        *(__half2*)(O + (size_t)r0 * D_MODEL + cc) =
            __floats2half2_rn(o[nt][0] * i0, o[nt][1] * i0);
        *(__half2*)(O + (size_t)(r0 + 8) * D_MODEL + cc) =
            __floats2half2_rn(o[nt][2] * i1, o[nt][3] * i1);
    }
}

// ---------------- launch ----------------
extern "C" void kernel_launch(void* const* d_in, const int* in_sizes, int n_in,
                              void* d_out, int out_size) {
    const float* x  = (const float*)d_in[0];
    const float* Wq = (const float*)d_in[1];
    const float* Wk = (const float*)d_in[2];
    const float* Wv = (const float*)d_in[3];
    const float* Wo = (const float*)d_in[4];
    const float* W1 = (const float*)d_in[5];
    const float* W2 = (const float*)d_in[6];
    const float* W3 = (const float*)d_in[7];
    const float* g1 = (const float*)d_in[8];
    const float* g2 = (const float*)d_in[9];
    float* out = (float*)d_out;

    float *xmid, *ffb;
    __half *xnh, *ctxh, *ffh, *qh, *kh, *vh;
    __half *wqh, *wkh, *wvh, *woh, *w1h, *w2h, *w3h;
    cudaGetSymbolAddress((void**)&xmid, g_xmid);
    cudaGetSymbolAddress((void**)&ffb,  g_ff);
    cudaGetSymbolAddress((void**)&xnh,  g_xn_h);
    cudaGetSymbolAddress((void**)&ctxh, g_ctx_h);
    cudaGetSymbolAddress((void**)&ffh,  g_ff_h);
    cudaGetSymbolAddress((void**)&qh,   g_qh);
    cudaGetSymbolAddress((void**)&kh,   g_kh);
    cudaGetSymbolAddress((void**)&vh,   g_vh);
    cudaGetSymbolAddress((void**)&wqh,  g_wq);
    cudaGetSymbolAddress((void**)&wkh,  g_wk);
    cudaGetSymbolAddress((void**)&wvh,  g_wv);
    cudaGetSymbolAddress((void**)&woh,  g_wo);
    cudaGetSymbolAddress((void**)&w1h,  g_w1);
    cudaGetSymbolAddress((void**)&w2h,  g_w2);
    cudaGetSymbolAddress((void**)&w3h,  g_w3);

    cudaFuncSetAttribute(gemm_mma<0>, cudaFuncAttributeMaxDynamicSharedMemorySize, GEMM_SMEM);
    cudaFuncSetAttribute(gemm_mma<1>, cudaFuncAttributeMaxDynamicSharedMemorySize, GEMM_SMEM);
    cudaFuncSetAttribute(gemm_mma<2>, cudaFuncAttributeMaxDynamicSharedMemorySize, GEMM_SMEM);
    cudaFuncSetAttribute(gemm_qkv,    cudaFuncAttributeMaxDynamicSharedMemorySize, GEMM_SMEM);
    cudaFuncSetAttribute(attn_f16,    cudaFuncAttributeMaxDynamicSharedMemorySize, ATT_SMEM);

    // weight conversion (once per call; ~45us, bandwidth-bound)
    const int CT = 256;
    int nDM = D_MODEL * D_MODEL / 4, nFF = DFF * D_MODEL / 4;
    f2h_kernel<<<(nDM + CT - 1) / CT, CT>>>((const float4*)Wq, (__half2*)wqh, nDM);
    f2h_kernel<<<(nDM + CT - 1) / CT, CT>>>((const float4*)Wk, (__half2*)wkh, nDM);
    f2h_kernel<<<(nDM + CT - 1) / CT, CT>>>((const float4*)Wv, (__half2*)wvh, nDM);
    f2h_kernel<<<(nDM + CT - 1) / CT, CT>>>((const float4*)Wo, (__half2*)woh, nDM);
    f2h_kernel<<<(nFF + CT - 1) / CT, CT>>>((const float4*)W1, (__half2*)w1h, nFF);
    f2h_kernel<<<(nFF + CT - 1) / CT, CT>>>((const float4*)W2, (__half2*)w2h, nFF);
    f2h_kernel<<<(nFF + CT - 1) / CT, CT>>>((const float4*)W3, (__half2*)w3h, nFF);

    dim3 blk(256);
    rope_table_kernel<<<(SEQ * 64 + 255) / 256, 256>>>();
    rmsnorm_kernel<<<M_TOK, 256>>>(x, g1, xnh);
    dim3 gq(D_MODEL / GBN, M_TOK / GBM, 3);
    gemm_qkv<<<gq, blk, GEMM_SMEM>>>(xnh);          // writes half Q/K/V, RoPE fused
    dim3 gattn(SEQ / 128, BATCH * NHEAD);
    attn_f16<<<gattn, blk, ATT_SMEM>>>(qh, kh, vh, ctxh);
    dim3 gqkv(D_MODEL / GBN, M_TOK / GBM);
    gemm_mma<1><<<gqkv, blk, GEMM_SMEM>>>(ctxh, woh, x, xmid, M_TOK, D_MODEL, D_MODEL);
    rmsnorm_kernel<<<M_TOK, 256>>>(xmid, g2, xnh);
    dim3 gff(DFF / GBN, M_TOK / GBM);
    gemm_mma<0><<<gff, blk, GEMM_SMEM>>>(xnh, w1h, nullptr, ffb, M_TOK, DFF, D_MODEL);
    gemm_mma<2><<<gff, blk, GEMM_SMEM>>>(xnh, w3h, ffb, ffh, M_TOK, DFF, D_MODEL);
    gemm_mma<1><<<gqkv, blk, GEMM_SMEM>>>(ffh, w2h, xmid, out, M_TOK, D_MODEL, DFF);
}

// round 8
// speedup vs baseline: 12.0665x; 1.0184x over previous
#include <cuda_runtime.h>
#include <cuda_fp16.h>
#include <math.h>
#include <stdint.h>

#define D_MODEL 2048
#define NHEAD   16
#define DKH     128
#define DFF     5632
#define SEQ     2048
#define BATCH   2
#define M_TOK   (BATCH*SEQ)   // 4096

// ---------------- scratch ----------------
__device__ float  g_xmid[(size_t)M_TOK*D_MODEL];
__device__ float  g_ff  [(size_t)M_TOK*DFF];
__device__ __half g_xn_h [(size_t)M_TOK*D_MODEL];
__device__ __half g_ctx_h[(size_t)M_TOK*D_MODEL];
__device__ __half g_ff_h [(size_t)M_TOK*DFF];
__device__ __half g_qh[(size_t)M_TOK*D_MODEL];
__device__ __half g_kh[(size_t)M_TOK*D_MODEL];
__device__ __half g_vh[(size_t)M_TOK*D_MODEL];
__device__ __half g_wq[(size_t)D_MODEL*D_MODEL];
__device__ __half g_wk[(size_t)D_MODEL*D_MODEL];
__device__ __half g_wv[(size_t)D_MODEL*D_MODEL];
__device__ __half g_wo[(size_t)D_MODEL*D_MODEL];
__device__ __half g_w1[(size_t)DFF*D_MODEL];
__device__ __half g_w2[(size_t)D_MODEL*DFF];
__device__ __half g_w3[(size_t)DFF*D_MODEL];
__device__ float  g_rsin[SEQ*64];
__device__ float  g_rcos[SEQ*64];

// ================= helpers =================
__device__ __forceinline__ void mma_f16(float* d, const uint32_t* a, const uint32_t* b) {
    asm volatile(
        "mma.sync.aligned.m16n8k16.row.col.f32.f16.f16.f32 "
        "{%0,%1,%2,%3}, {%4,%5,%6,%7}, {%8,%9}, {%0,%1,%2,%3};"
        : "+f"(d[0]), "+f"(d[1]), "+f"(d[2]), "+f"(d[3])
        : "r"(a[0]), "r"(a[1]), "r"(a[2]), "r"(a[3]),
          "r"(b[0]), "r"(b[1]));
}
__device__ __forceinline__ uint32_t smem_u32(const void* p) {
    uint32_t a;
    asm("{ .reg .u64 t; cvta.to.shared.u64 t, %1; cvt.u32.u64 %0, t; }"
        : "=r"(a) : "l"(p));
    return a;
}
__device__ __forceinline__ void cp_async16(uint32_t dst, const void* src) {
    asm volatile("cp.async.cg.shared.global [%0], [%1], 16;" :: "r"(dst), "l"(src));
}
#define CP_COMMIT()  asm volatile("cp.async.commit_group;" ::: "memory")
#define CP_WAIT(N)   asm volatile("cp.async.wait_group %0;" :: "n"(N) : "memory")

__device__ __forceinline__ void ldsm_x4(uint32_t* r, uint32_t a) {
    asm volatile("ldmatrix.sync.aligned.m8n8.x4.shared.b16 {%0,%1,%2,%3}, [%4];"
                 : "=r"(r[0]), "=r"(r[1]), "=r"(r[2]), "=r"(r[3]) : "r"(a));
}
__device__ __forceinline__ void ldsm_x4_t(uint32_t* r, uint32_t a) {
    asm volatile("ldmatrix.sync.aligned.m8n8.x4.trans.shared.b16 {%0,%1,%2,%3}, [%4];"
                 : "=r"(r[0]), "=r"(r[1]), "=r"(r[2]), "=r"(r[3]) : "r"(a));
}

// ---------------- fp32 -> fp16 convert ----------------
__global__ void f2h_kernel(const float4* __restrict__ in, __half2* __restrict__ out, int n4) {
    int i = blockIdx.x * blockDim.x + threadIdx.x;
    if (i >= n4) return;
    float4 v = in[i];
    out[2 * i]     = __floats2half2_rn(v.x, v.y);
    out[2 * i + 1] = __floats2half2_rn(v.z, v.w);
}

// ================= fp16 GEMM, 256x128 CTA tile, 3-stage cp.async ============
// C[M,N] = A[M,K] @ W[N,K]^T  (half in, fp32 accumulate)
// EPI 0: fp32 C=acc; 1: fp32 C=res+acc; 2: half C=silu(res)*acc;
// EPI 3: half C=acc with optional RoPE rotation (ropef)
#define GBM 256
#define GBN 128
#define LDH  40
#define LDH2 20
#define GSTG 3
#define GEMM_SMEM (GSTG*(GBM+GBN)*LDH*2)

template<int EPI>
__device__ __forceinline__ void gemm_body(
        const __half* __restrict__ A,
        const __half* __restrict__ W,
        const float* __restrict__ res,
        void* __restrict__ CO,
        int M, int N, int K, int ropef) {
    extern __shared__ char smc[];
    __half* As = (__half*)smc;
    __half* Bs = As + GSTG * GBM * LDH;

    int tid  = threadIdx.x;
    int lane = tid & 31, wid = tid >> 5;
    int wm = wid >> 1, wn = wid & 1;
    int bm = blockIdx.y * GBM, bn = blockIdx.x * GBN;

    uint32_t as_base = smem_u32(As);
    uint32_t bs_base = smem_u32(Bs);

    auto issue_stage = [&](int tile, int stg) {
        uint32_t aoff = (uint32_t)stg * GBM * LDH * 2;
        uint32_t boff = (uint32_t)stg * GBN * LDH * 2;
        const __half* a2 = A + (size_t)bm * K + tile * 32;
        const __half* w2 = W + (size_t)bn * K + tile * 32;
#pragma unroll
        for (int i = 0; i < 4; i++) {
            int idx = tid + i * 256;
            int r = idx >> 2, c = (idx & 3) * 8;
            cp_async16(as_base + aoff + (uint32_t)(r * LDH + c) * 2,
                       a2 + (size_t)r * K + c);
        }
#pragma unroll
        for (int i = 0; i < 2; i++) {
            int idx = tid + i * 256;
            int r = idx >> 2, c = (idx & 3) * 8;
            cp_async16(bs_base + boff + (uint32_t)(r * LDH + c) * 2,
                       w2 + (size_t)r * K + c);
        }
    };

    int nk = K >> 5;
    issue_stage(0, 0); CP_COMMIT();
    issue_stage(1, 1); CP_COMMIT();

    float acc[4][8][4] = {};
    int qr = lane >> 2, qc = lane & 3;

    int stg = 0;
    for (int kt = 0; kt < nk; kt++) {
        CP_WAIT(1);
        __syncthreads();
        const uint32_t* A32 = (const uint32_t*)(As + stg * GBM * LDH);
        const uint32_t* B32 = (const uint32_t*)(Bs + stg * GBN * LDH);
#pragma unroll
        for (int ks = 0; ks < 2; ks++) {
            int cb = ks * 8 + qc;
            uint32_t af[4][4], bf[8][2];
#pragma unroll
            for (int mt = 0; mt < 4; mt++) {
                int r = wm * 64 + mt * 16 + qr;
                af[mt][0] = A32[r * LDH2 + cb];
                af[mt][1] = A32[(r + 8) * LDH2 + cb];
                af[mt][2] = A32[r * LDH2 + cb + 4];
                af[mt][3] = A32[(r + 8) * LDH2 + cb + 4];
            }
#pragma unroll
            for (int nt = 0; nt < 8; nt++) {
                int n = wn * 64 + nt * 8 + qr;
                bf[nt][0] = B32[n * LDH2 + cb];
                bf[nt][1] = B32[n * LDH2 + cb + 4];
            }
#pragma unroll
            for (int mt = 0; mt < 4; mt++)
#pragma unroll
                for (int nt = 0; nt < 8; nt++)
                    mma_f16(acc[mt][nt], af[mt], bf[nt]);
        }
        int nstg = stg + 2; if (nstg >= GSTG) nstg -= GSTG;
        if (kt + 2 < nk) issue_stage(kt + 2, nstg);
        CP_COMMIT();
        stg = stg + 1 == GSTG ? 0 : stg + 1;
    }

#pragma unroll
    for (int mt = 0; mt < 4; mt++) {
        int r0 = bm + wm * 64 + mt * 16 + qr;
#pragma unroll
        for (int nt = 0; nt < 8; nt++) {
            int cc = bn + wn * 64 + nt * 8 + 2 * qc;
            size_t i0 = (size_t)r0 * N + cc;
            size_t i1 = (size_t)(r0 + 8) * N + cc;
            if (EPI == 0) {
                float* C = (float*)CO;
                *(float2*)(C + i0) = make_float2(acc[mt][nt][0], acc[mt][nt][1]);
                *(float2*)(C + i1) = make_float2(acc[mt][nt][2], acc[mt][nt][3]);
            } else if (EPI == 1) {
                float* C = (float*)CO;
                float2 rr0 = *(const float2*)(res + i0);
                float2 rr1 = *(const float2*)(res + i1);
                *(float2*)(C + i0) = make_float2(acc[mt][nt][0] + rr0.x,
                                                 acc[mt][nt][1] + rr0.y);
                *(float2*)(C + i1) = make_float2(acc[mt][nt][2] + rr1.x,
                                                 acc[mt][nt][3] + rr1.y);
            } else if (EPI == 2) {
                __half* C = (__half*)CO;
                float2 a0 = *(const float2*)(res + i0);
                float2 a1 = *(const float2*)(res + i1);
                float v0 = acc[mt][nt][0] * (a0.x / (1.f + __expf(-a0.x)));
                float v1 = acc[mt][nt][1] * (a0.y / (1.f + __expf(-a0.y)));
                float v2 = acc[mt][nt][2] * (a1.x / (1.f + __expf(-a1.x)));
                float v3 = acc[mt][nt][3] * (a1.y / (1.f + __expf(-a1.y)));
                *(__half2*)(C + i0) = __floats2half2_rn(v0, v1);
                *(__half2*)(C + i1) = __floats2half2_rn(v2, v3);
            } else {
                __half* C = (__half*)CO;
                float a0 = acc[mt][nt][0], a1 = acc[mt][nt][1];
                float a2 = acc[mt][nt][2], a3 = acc[mt][nt][3];
                if (ropef) {
                    int s0 = r0 & (SEQ - 1), s1 = (r0 + 8) & (SEQ - 1);
                    int j  = (cc & 127) >> 1;
                    float sn0 = g_rsin[s0 * 64 + j], cs0 = g_rcos[s0 * 64 + j];
                    float sn1 = g_rsin[s1 * 64 + j], cs1 = g_rcos[s1 * 64 + j];
                    *(__half2*)(C + i0) = __floats2half2_rn(a0 * cs0 - a1 * sn0,
                                                            a0 * sn0 + a1 * cs0);
                    *(__half2*)(C + i1) = __floats2half2_rn(a2 * cs1 - a3 * sn1,
                                                            a2 * sn1 + a3 * cs1);
                } else {
                    *(__half2*)(C + i0) = __floats2half2_rn(a0, a1);
                    *(__half2*)(C + i1) = __floats2half2_rn(a2, a3);
                }
            }
        }
    }
}

template<int EPI>
__global__ __launch_bounds__(256) void gemm_mma(
        const __half* __restrict__ A, const __half* __restrict__ W,
        const float* __restrict__ res, void* __restrict__ CO,
        int M, int N, int K) {
    gemm_body<EPI>(A, W, res, CO, M, N, K, 0);
}

__global__ __launch_bounds__(256) void gemm_qkv(const __half* __restrict__ A) {
    int z = blockIdx.z;
    const __half* W = z == 0 ? g_wq : (z == 1 ? g_wk : g_wv);
    __half* C = z == 0 ? g_qh : (z == 1 ? g_kh : g_vh);
    gemm_body<3>(A, W, nullptr, C, M_TOK, D_MODEL, D_MODEL, z < 2);
}

// ---------------- RMSNorm (writes half) ----------------
__global__ void rmsnorm_kernel(const float* __restrict__ x,
                               const float* __restrict__ g,
                               __half* __restrict__ out) {
    int row = blockIdx.x;
    const float* xr = x + (size_t)row * D_MODEL;
    __half*      orow = out + (size_t)row * D_MODEL;
    float s = 0.f;
    for (int i = threadIdx.x; i < D_MODEL; i += blockDim.x) {
        float v = xr[i]; s += v * v;
    }
    __shared__ float red[32];
    for (int o = 16; o; o >>= 1) s += __shfl_down_sync(0xffffffffu, s, o);
    if ((threadIdx.x & 31) == 0) red[threadIdx.x >> 5] = s;
    __syncthreads();
    if (threadIdx.x < 32) {
        float v = (threadIdx.x < (blockDim.x >> 5)) ? red[threadIdx.x] : 0.f;
        for (int o = 16; o; o >>= 1) v += __shfl_down_sync(0xffffffffu, v, o);
        if (threadIdx.x == 0) red[0] = v;
    }
    __syncthreads();
    float rinv = rsqrtf(red[0] * (1.0f / D_MODEL) + 1e-5f);
    for (int i = threadIdx.x; i < D_MODEL; i += blockDim.x)
        orow[i] = __float2half(xr[i] * g[i] * rinv);
}

// ---------------- RoPE tables ----------------
__global__ void rope_table_kernel() {
    int idx = blockIdx.x * blockDim.x + threadIdx.x;
    if (idx >= SEQ * 64) return;
    int j = idx & 63, s = idx >> 6;
    double inv = exp(-(double)j * (9.210340371976184 / 64.0));
    double ang = (double)s * inv;
    g_rsin[idx] = (float)sin(ang);
    g_rcos[idx] = (float)cos(ang);
}

// ---------------- fp16 tensor-core flash attention (causal) ----------------
// BQ=128, BK=64, 256 threads (8 warps). Heavy-first q-block order.
// Q/K/P fragments via ldmatrix (non-trans), V via ldmatrix.trans.
#define QLD 136
#define KLH 136
#define PLH 72
#define ATT_SMEM ((2*64*KLH + 2*64*KLH + 128*PLH) * 2)

__global__ __launch_bounds__(256) void attn_f16(
        const __half* __restrict__ Q,
        const __half* __restrict__ K,
        const __half* __restrict__ V,
        __half* __restrict__ O) {
    extern __shared__ __half smh[];
    __half* Qst = smh;                    // staging, overlaps K/V/P
    __half* Ksm = smh;                    // 2 x 64 x KLH
    __half* Vsm = Ksm + 2 * 64 * KLH;     // 2 x 64 x KLH
    __half* Psm = Vsm + 2 * 64 * KLH;     // 128 x PLH

    int tid = threadIdx.x;
    int lane = tid & 31, wid = tid >> 5;
    int qr = lane >> 2, qc = lane & 3;
    int bh = blockIdx.y;
    int b = bh >> 4, h = bh & 15;
    int qblk = gridDim.x - 1 - blockIdx.x;   // heavy-first scheduling
    int q0 = qblk * 128;
    int nkb = 2 * qblk + 2;
    int m4 = lane >> 3;
    int r8 = lane & 7;

    // ---- stage Q, extract register A-fragments ----
    for (int i = tid; i < 128 * 16; i += 256) {
        int r = i >> 4, c8 = (i & 15) * 8;
        *(uint4*)(Qst + r * QLD + c8) =
            *(const uint4*)(Q + (size_t)(b * SEQ + q0 + r) * D_MODEL + h * DKH + c8);
    }
    __syncthreads();
    uint32_t afq[8][4];
    {
        uint32_t qb_ = smem_u32(Qst);
        int row = wid * 16 + (m4 & 1) * 8 + r8;
#pragma unroll
        for (int ks = 0; ks < 8; ks++)
            ldsm_x4(afq[ks], qb_ + (uint32_t)(row * QLD + ks * 16 + (m4 >> 1) * 8) * 2);
    }
    __syncthreads();

    uint32_t ks_base = smem_u32(Ksm);
    uint32_t vs_base = smem_u32(Vsm);
    auto issue_kv = [&](int kb, int stg) {
        uint32_t off = (uint32_t)stg * 64 * KLH * 2;
#pragma unroll
        for (int i = 0; i < 4; i++) {
            int idx = tid + i * 256;
            int r = idx >> 4, c8 = (idx & 15) * 8;
            size_t g = (size_t)(b * SEQ + kb * 64 + r) * D_MODEL + h * DKH + c8;
            uint32_t d = (uint32_t)(r * KLH + c8) * 2;
            cp_async16(ks_base + off + d, K + g);
            cp_async16(vs_base + off + d, V + g);
        }
    };

    issue_kv(0, 0); CP_COMMIT();

    float o[16][4] = {};
    float m0 = -1e30f, m1 = -1e30f, l0 = 0.f, l1 = 0.f;
    const float scale = 0.08838834764831845f;   // 1/sqrt(128)

    for (int kb = 0; kb < nkb; kb++) {
        CP_WAIT(0);
        __syncthreads();                 // single barrier per k-tile
        if (kb + 1 < nkb) issue_kv(kb + 1, (kb + 1) & 1);
        CP_COMMIT();
        uint32_t kst = ks_base + (uint32_t)(kb & 1) * 64 * KLH * 2;
        uint32_t vst = vs_base + (uint32_t)(kb & 1) * 64 * KLH * 2;

        // ---- S = Q K^T ----
        float s[8][4] = {};
#pragma unroll
        for (int c2 = 0; c2 < 4; c2++) {
#pragma unroll
            for (int n0 = 0; n0 < 8; n0++) {
                uint32_t kf[4];
                ldsm_x4(kf, kst + (uint32_t)((n0 * 8 + r8) * KLH + c2 * 32 + m4 * 8) * 2);
                mma_f16(s[n0], afq[2 * c2],     kf);
                mma_f16(s[n0], afq[2 * c2 + 1], kf + 2);
            }
        }

        // ---- mask + online softmax ----
        bool diag = (kb >= 2 * qblk);
        int row0 = q0 + wid * 16 + qr, row1 = row0 + 8;
        float mt0 = -1e30f, mt1 = -1e30f;
#pragma unroll
        for (int nt = 0; nt < 8; nt++) {
            int col = kb * 64 + nt * 8 + 2 * qc;
            s[nt][0] *= scale; s[nt][1] *= scale;
            s[nt][2] *= scale; s[nt][3] *= scale;
            if (diag) {
                if (col > row0)     s[nt][0] = -1e30f;
                if (col + 1 > row0) s[nt][1] = -1e30f;
                if (col > row1)     s[nt][2] = -1e30f;
                if (col + 1 > row1) s[nt][3] = -1e30f;
            }
            mt0 = fmaxf(mt0, fmaxf(s[nt][0], s[nt][1]));
            mt1 = fmaxf(mt1, fmaxf(s[nt][2], s[nt][3]));
        }
#pragma unroll
        for (int off = 1; off < 4; off <<= 1) {
            mt0 = fmaxf(mt0, __shfl_xor_sync(0xffffffffu, mt0, off));
            mt1 = fmaxf(mt1, __shfl_xor_sync(0xffffffffu, mt1, off));
        }
        float mn0 = fmaxf(m0, mt0), mn1 = fmaxf(m1, mt1);
        float ls0 = 0.f, ls1 = 0.f;
        int prow = wid * 16 + qr;
#pragma unroll
        for (int nt = 0; nt < 8; nt++) {
            __half2 h01 = __floats2half2_rn(__expf(s[nt][0] - mn0), __expf(s[nt][1] - mn0));
            __half2 h23 = __floats2half2_rn(__expf(s[nt][2] - mn1), __expf(s[nt][3] - mn1));
            float2 f01 = __half22float2(h01), f23 = __half22float2(h23);
            ls0 += f01.x + f01.y; ls1 += f23.x + f23.y;
            *(__half2*)(Psm + prow * PLH + nt * 8 + 2 * qc)       = h01;
            *(__half2*)(Psm + (prow + 8) * PLH + nt * 8 + 2 * qc) = h23;
        }
#pragma unroll
        for (int off = 1; off < 4; off <<= 1) {
            ls0 += __shfl_xor_sync(0xffffffffu, ls0, off);
            ls1 += __shfl_xor_sync(0xffffffffu, ls1, off);
        }
        float al0 = __expf(m0 - mn0), al1 = __expf(m1 - mn1);
        l0 = l0 * al0 + ls0; l1 = l1 * al1 + ls1;
        m0 = mn0; m1 = mn1;
#pragma unroll
        for (int nt = 0; nt < 16; nt++) {
            o[nt][0] *= al0; o[nt][1] *= al0;
            o[nt][2] *= al1; o[nt][3] *= al1;
        }
        __syncwarp();

        // ---- O += P V ----
        uint32_t afp[4][4];
        {
            uint32_t pb = smem_u32(Psm);
            int row = wid * 16 + (m4 & 1) * 8 + r8;
#pragma unroll
            for (int ks = 0; ks < 4; ks++)
                ldsm_x4(afp[ks], pb + (uint32_t)(row * PLH + ks * 16 + (m4 >> 1) * 8) * 2);
        }
#pragma unroll
        for (int ks = 0; ks < 4; ks++) {
#pragma unroll
            for (int g = 0; g < 8; g++) {
                uint32_t vf[4];
                ldsm_x4_t(vf, vst + (uint32_t)((ks * 16 + (m4 & 1) * 8 + r8) * KLH
                                               + g * 16 + (m4 >> 1) * 8) * 2);
                mma_f16(o[2 * g],     afp[ks], vf);
                mma_f16(o[2 * g + 1], afp[ks], vf + 2);
            }
        }
    }

    float i0 = 1.f / l0, i1 = 1.f / l1;
    int r0 = b * SEQ + q0 + wid * 16 + qr;
#pragma unroll
    for (int nt = 0; nt < 16; nt++) {
        int cc = h * DKH + nt * 8 + 2 * qc;
        *(__half2*)(O + (size_t)r0 * D_MODEL + cc) =
            __floats2half2_rn(o[nt][0] * i0, o[nt][1] * i0);
        *(__half2*)(O + (size_t)(r0 + 8) * D_MODEL + cc) =
            __floats2half2_rn(o[nt][2] * i1, o[nt][3] * i1);
    }
}

// ---------------- launch ----------------
extern "C" void kernel_launch(void* const* d_in, const int* in_sizes, int n_in,
                              void* d_out, int out_size) {
    const float* x  = (const float*)d_in[0];
    const float* Wq = (const float*)d_in[1];
    const float* Wk = (const float*)d_in[2];
    const float* Wv = (const float*)d_in[3];
    const float* Wo = (const float*)d_in[4];
    const float* W1 = (const float*)d_in[5];
    const float* W2 = (const float*)d_in[6];
    const float* W3 = (const float*)d_in[7];
    const float* g1 = (const float*)d_in[8];
    const float* g2 = (const float*)d_in[9];
    float* out = (float*)d_out;

    float *xmid, *ffb;
    __half *xnh, *ctxh, *ffh, *qh, *kh, *vh;
    __half *wqh, *wkh, *wvh, *woh, *w1h, *w2h, *w3h;
    cudaGetSymbolAddress((void**)&xmid, g_xmid);
    cudaGetSymbolAddress((void**)&ffb,  g_ff);
    cudaGetSymbolAddress((void**)&xnh,  g_xn_h);
    cudaGetSymbolAddress((void**)&ctxh, g_ctx_h);
    cudaGetSymbolAddress((void**)&ffh,  g_ff_h);
    cudaGetSymbolAddress((void**)&qh,   g_qh);
    cudaGetSymbolAddress((void**)&kh,   g_kh);
    cudaGetSymbolAddress((void**)&vh,   g_vh);
    cudaGetSymbolAddress((void**)&wqh,  g_wq);
    cudaGetSymbolAddress((void**)&wkh,  g_wk);
    cudaGetSymbolAddress((void**)&wvh,  g_wv);
    cudaGetSymbolAddress((void**)&woh,  g_wo);
    cudaGetSymbolAddress((void**)&w1h,  g_w1);
    cudaGetSymbolAddress((void**)&w2h,  g_w2);
    cudaGetSymbolAddress((void**)&w3h,  g_w3);

    cudaFuncSetAttribute(gemm_mma<0>, cudaFuncAttributeMaxDynamicSharedMemorySize, GEMM_SMEM);
    cudaFuncSetAttribute(gemm_mma<1>, cudaFuncAttributeMaxDynamicSharedMemorySize, GEMM_SMEM);
    cudaFuncSetAttribute(gemm_mma<2>, cudaFuncAttributeMaxDynamicSharedMemorySize, GEMM_SMEM);
    cudaFuncSetAttribute(gemm_qkv,    cudaFuncAttributeMaxDynamicSharedMemorySize, GEMM_SMEM);
    cudaFuncSetAttribute(attn_f16,    cudaFuncAttributeMaxDynamicSharedMemorySize, ATT_SMEM);

    // ---- side stream for weight conversion (graph-capture fork/join) ----
    cudaStream_t s2;
    cudaStreamCreateWithFlags(&s2, cudaStreamNonBlocking);
    cudaEvent_t evFork, evQKV, evW;
    cudaEventCreateWithFlags(&evFork, cudaEventDisableTiming);
    cudaEventCreateWithFlags(&evQKV,  cudaEventDisableTiming);
    cudaEventCreateWithFlags(&evW,    cudaEventDisableTiming);

    cudaEventRecord(evFork, 0);
    cudaStreamWaitEvent(s2, evFork, 0);

    const int CT = 256;
    int nDM = D_MODEL * D_MODEL / 4, nFF = DFF * D_MODEL / 4;
    rope_table_kernel<<<(SEQ * 64 + 255) / 256, 256, 0, s2>>>();
    f2h_kernel<<<(nDM + CT - 1) / CT, CT, 0, s2>>>((const float4*)Wq, (__half2*)wqh, nDM);
    f2h_kernel<<<(nDM + CT - 1) / CT, CT, 0, s2>>>((const float4*)Wk, (__half2*)wkh, nDM);
    f2h_kernel<<<(nDM + CT - 1) / CT, CT, 0, s2>>>((const float4*)Wv, (__half2*)wvh, nDM);
    cudaEventRecord(evQKV, s2);
    f2h_kernel<<<(nDM + CT - 1) / CT, CT, 0, s2>>>((const float4*)Wo, (__half2*)woh, nDM);
    f2h_kernel<<<(nFF + CT - 1) / CT, CT, 0, s2>>>((const float4*)W1, (__half2*)w1h, nFF);
    f2h_kernel<<<(nFF + CT - 1) / CT, CT, 0, s2>>>((const float4*)W3, (__half2*)w3h, nFF);
    f2h_kernel<<<(nFF + CT - 1) / CT, CT, 0, s2>>>((const float4*)W2, (__half2*)w2h, nFF);
    cudaEventRecord(evW, s2);

    dim3 blk(256);
    // main stream: rmsnorm overlaps conversions
    rmsnorm_kernel<<<M_TOK, 256>>>(x, g1, xnh);
    cudaStreamWaitEvent(0, evQKV, 0);
    dim3 gq(D_MODEL / GBN, M_TOK / GBM, 3);
    gemm_qkv<<<gq, blk, GEMM_SMEM>>>(xnh);          // remaining convs hide under this
    dim3 gattn(SEQ / 128, BATCH * NHEAD);
    attn_f16<<<gattn, blk, ATT_SMEM>>>(qh, kh, vh, ctxh);
    cudaStreamWaitEvent(0, evW, 0);                  // join side stream
    dim3 gqkv(D_MODEL / GBN, M_TOK / GBM);
    gemm_mma<1><<<gqkv, blk, GEMM_SMEM>>>(ctxh, woh, x, xmid, M_TOK, D_MODEL, D_MODEL);
    rmsnorm_kernel<<<M_TOK, 256>>>(xmid, g2, xnh);
    dim3 gff(DFF / GBN, M_TOK / GBM);
    gemm_mma<0><<<gff, blk, GEMM_SMEM>>>(xnh, w1h, nullptr, ffb, M_TOK, DFF, D_MODEL);
    gemm_mma<2><<<gff, blk, GEMM_SMEM>>>(xnh, w3h, ffb, ffh, M_TOK, DFF, D_MODEL);
    gemm_mma<1><<<gqkv, blk, GEMM_SMEM>>>(ffh, w2h, xmid, out, M_TOK, D_MODEL, DFF);
}

// round 9
// speedup vs baseline: 12.4012x; 1.0277x over previous
#include <cuda_runtime.h>
#include <cuda_fp16.h>
#include <math.h>
#include <stdint.h>

#define D_MODEL 2048
#define NHEAD   16
#define DKH     128
#define DFF     5632
#define SEQ     2048
#define BATCH   2
#define M_TOK   (BATCH*SEQ)   // 4096

// ---------------- scratch ----------------
__device__ float  g_xmid[(size_t)M_TOK*D_MODEL];
__device__ float  g_ff  [(size_t)M_TOK*DFF];
__device__ __half g_xn_h [(size_t)M_TOK*D_MODEL];
__device__ __half g_ctx_h[(size_t)M_TOK*D_MODEL];
__device__ __half g_ff_h [(size_t)M_TOK*DFF];
__device__ __half g_qh[(size_t)M_TOK*D_MODEL];
__device__ __half g_kh[(size_t)M_TOK*D_MODEL];
__device__ __half g_vh[(size_t)M_TOK*D_MODEL];
__device__ __half g_wq[(size_t)D_MODEL*D_MODEL];
__device__ __half g_wk[(size_t)D_MODEL*D_MODEL];
__device__ __half g_wv[(size_t)D_MODEL*D_MODEL];
__device__ __half g_wo[(size_t)D_MODEL*D_MODEL];
__device__ __half g_w1[(size_t)DFF*D_MODEL];
__device__ __half g_w2[(size_t)D_MODEL*DFF];
__device__ __half g_w3[(size_t)DFF*D_MODEL];
__device__ float  g_rsin[SEQ*64];
__device__ float  g_rcos[SEQ*64];

// ================= helpers =================
__device__ __forceinline__ void mma_f16(float* d, const uint32_t* a, const uint32_t* b) {
    asm volatile(
        "mma.sync.aligned.m16n8k16.row.col.f32.f16.f16.f32 "
        "{%0,%1,%2,%3}, {%4,%5,%6,%7}, {%8,%9}, {%0,%1,%2,%3};"
        : "+f"(d[0]), "+f"(d[1]), "+f"(d[2]), "+f"(d[3])
        : "r"(a[0]), "r"(a[1]), "r"(a[2]), "r"(a[3]),
          "r"(b[0]), "r"(b[1]));
}
__device__ __forceinline__ uint32_t smem_u32(const void* p) {
    uint32_t a;
    asm("{ .reg .u64 t; cvta.to.shared.u64 t, %1; cvt.u32.u64 %0, t; }"
        : "=r"(a) : "l"(p));
    return a;
}
__device__ __forceinline__ void cp_async16(uint32_t dst, const void* src) {
    asm volatile("cp.async.cg.shared.global [%0], [%1], 16;" :: "r"(dst), "l"(src));
}
#define CP_COMMIT()  asm volatile("cp.async.commit_group;" ::: "memory")
#define CP_WAIT(N)   asm volatile("cp.async.wait_group %0;" :: "n"(N) : "memory")

__device__ __forceinline__ void ldsm_x4(uint32_t* r, uint32_t a) {
    asm volatile("ldmatrix.sync.aligned.m8n8.x4.shared.b16 {%0,%1,%2,%3}, [%4];"
                 : "=r"(r[0]), "=r"(r[1]), "=r"(r[2]), "=r"(r[3]) : "r"(a));
}
__device__ __forceinline__ void ldsm_x4_t(uint32_t* r, uint32_t a) {
    asm volatile("ldmatrix.sync.aligned.m8n8.x4.trans.shared.b16 {%0,%1,%2,%3}, [%4];"
                 : "=r"(r[0]), "=r"(r[1]), "=r"(r[2]), "=r"(r[3]) : "r"(a));
}

// ---------------- fp32 -> fp16 convert ----------------
__global__ void f2h_kernel(const float4* __restrict__ in, __half2* __restrict__ out, int n4) {
    int i = blockIdx.x * blockDim.x + threadIdx.x;
    if (i >= n4) return;
    float4 v = in[i];
    out[2 * i]     = __floats2half2_rn(v.x, v.y);
    out[2 * i + 1] = __floats2half2_rn(v.z, v.w);
}

// ================= fp16 GEMM, templated CTA tile (BMx128), 3-stage ==========
// C[M,N] = A[M,K] @ W[N,K]^T  (half in, fp32 accumulate)
// EPI 0: fp32 C=acc; 1: fp32 C=res+acc; 2: half C=silu(res)*acc;
// EPI 3: half C=acc with optional RoPE rotation (ropef)
// BM=256: 8 warps 4m x 2n, warp 64x64, 1 CTA/SM.
// BM=128: 8 warps 2m x 4n, warp 64x32, 2 CTAs/SM (QKV wave-quantization fix).
#define GBN 128
#define LDH  40
#define LDH2 20
#define GSTG 3
#define GEMM_SMEM_256 (GSTG*(256+GBN)*LDH*2)
#define GEMM_SMEM_128 (GSTG*(128+GBN)*LDH*2)

template<int EPI, int BM>
__device__ __forceinline__ void gemm_body(
        const __half* __restrict__ A,
        const __half* __restrict__ W,
        const float* __restrict__ res,
        void* __restrict__ CO,
        int M, int N, int K, int ropef) {
    constexpr int WN = (BM == 256) ? 8 : 4;         // n-tiles per warp
    extern __shared__ char smc[];
    __half* As = (__half*)smc;                      // [GSTG][BM][LDH]
    __half* Bs = As + GSTG * BM * LDH;              // [GSTG][GBN][LDH]

    int tid  = threadIdx.x;
    int lane = tid & 31, wid = tid >> 5;
    int wmb, wnb;                                    // warp tile bases
    if (BM == 256) { wmb = (wid >> 1) * 64; wnb = (wid & 1) * 64; }
    else           { wmb = (wid >> 2) * 64; wnb = (wid & 3) * 32; }
    int bm = blockIdx.y * BM, bn = blockIdx.x * GBN;

    uint32_t as_base = smem_u32(As);
    uint32_t bs_base = smem_u32(Bs);

    auto issue_stage = [&](int tile, int stg) {
        uint32_t aoff = (uint32_t)stg * BM * LDH * 2;
        uint32_t boff = (uint32_t)stg * GBN * LDH * 2;
        const __half* a2 = A + (size_t)bm * K + tile * 32;
        const __half* w2 = W + (size_t)bn * K + tile * 32;
#pragma unroll
        for (int i = 0; i < BM / 64; i++) {
            int idx = tid + i * 256;
            int r = idx >> 2, c = (idx & 3) * 8;
            cp_async16(as_base + aoff + (uint32_t)(r * LDH + c) * 2,
                       a2 + (size_t)r * K + c);
        }
#pragma unroll
        for (int i = 0; i < 2; i++) {
            int idx = tid + i * 256;
            int r = idx >> 2, c = (idx & 3) * 8;
            cp_async16(bs_base + boff + (uint32_t)(r * LDH + c) * 2,
                       w2 + (size_t)r * K + c);
        }
    };

    int nk = K >> 5;
    issue_stage(0, 0); CP_COMMIT();
    issue_stage(1, 1); CP_COMMIT();

    float acc[4][WN][4] = {};
    int qr = lane >> 2, qc = lane & 3;

    int stg = 0;
    for (int kt = 0; kt < nk; kt++) {
        CP_WAIT(1);
        __syncthreads();
        const uint32_t* A32 = (const uint32_t*)(As + stg * BM * LDH);
        const uint32_t* B32 = (const uint32_t*)(Bs + stg * GBN * LDH);
#pragma unroll
        for (int ks = 0; ks < 2; ks++) {
            int cb = ks * 8 + qc;
            uint32_t af[4][4], bf[WN][2];
#pragma unroll
            for (int mt = 0; mt < 4; mt++) {
                int r = wmb + mt * 16 + qr;
                af[mt][0] = A32[r * LDH2 + cb];
                af[mt][1] = A32[(r + 8) * LDH2 + cb];
                af[mt][2] = A32[r * LDH2 + cb + 4];
                af[mt][3] = A32[(r + 8) * LDH2 + cb + 4];
            }
#pragma unroll
            for (int nt = 0; nt < WN; nt++) {
                int n = wnb + nt * 8 + qr;
                bf[nt][0] = B32[n * LDH2 + cb];
                bf[nt][1] = B32[n * LDH2 + cb + 4];
            }
#pragma unroll
            for (int mt = 0; mt < 4; mt++)
#pragma unroll
                for (int nt = 0; nt < WN; nt++)
                    mma_f16(acc[mt][nt], af[mt], bf[nt]);
        }
        int nstg = stg + 2; if (nstg >= GSTG) nstg -= GSTG;
        if (kt + 2 < nk) issue_stage(kt + 2, nstg);
        CP_COMMIT();
        stg = stg + 1 == GSTG ? 0 : stg + 1;
    }

#pragma unroll
    for (int mt = 0; mt < 4; mt++) {
        int r0 = bm + wmb + mt * 16 + qr;
#pragma unroll
        for (int nt = 0; nt < WN; nt++) {
            int cc = bn + wnb + nt * 8 + 2 * qc;
            size_t i0 = (size_t)r0 * N + cc;
            size_t i1 = (size_t)(r0 + 8) * N + cc;
            if (EPI == 0) {
                float* C = (float*)CO;
                *(float2*)(C + i0) = make_float2(acc[mt][nt][0], acc[mt][nt][1]);
                *(float2*)(C + i1) = make_float2(acc[mt][nt][2], acc[mt][nt][3]);
            } else if (EPI == 1) {
                float* C = (float*)CO;
                float2 rr0 = *(const float2*)(res + i0);
                float2 rr1 = *(const float2*)(res + i1);
                *(float2*)(C + i0) = make_float2(acc[mt][nt][0] + rr0.x,
                                                 acc[mt][nt][1] + rr0.y);
                *(float2*)(C + i1) = make_float2(acc[mt][nt][2] + rr1.x,
                                                 acc[mt][nt][3] + rr1.y);
            } else if (EPI == 2) {
                __half* C = (__half*)CO;
                float2 a0 = *(const float2*)(res + i0);
                float2 a1 = *(const float2*)(res + i1);
                float v0 = acc[mt][nt][0] * (a0.x / (1.f + __expf(-a0.x)));
                float v1 = acc[mt][nt][1] * (a0.y / (1.f + __expf(-a0.y)));
                float v2 = acc[mt][nt][2] * (a1.x / (1.f + __expf(-a1.x)));
                float v3 = acc[mt][nt][3] * (a1.y / (1.f + __expf(-a1.y)));
                *(__half2*)(C + i0) = __floats2half2_rn(v0, v1);
                *(__half2*)(C + i1) = __floats2half2_rn(v2, v3);
            } else {
                __half* C = (__half*)CO;
                float a0 = acc[mt][nt][0], a1 = acc[mt][nt][1];
                float a2 = acc[mt][nt][2], a3 = acc[mt][nt][3];
                if (ropef) {
                    int s0 = r0 & (SEQ - 1), s1 = (r0 + 8) & (SEQ - 1);
                    int j  = (cc & 127) >> 1;
                    float sn0 = g_rsin[s0 * 64 + j], cs0 = g_rcos[s0 * 64 + j];
                    float sn1 = g_rsin[s1 * 64 + j], cs1 = g_rcos[s1 * 64 + j];
                    *(__half2*)(C + i0) = __floats2half2_rn(a0 * cs0 - a1 * sn0,
                                                            a0 * sn0 + a1 * cs0);
                    *(__half2*)(C + i1) = __floats2half2_rn(a2 * cs1 - a3 * sn1,
                                                            a2 * sn1 + a3 * cs1);
                } else {
                    *(__half2*)(C + i0) = __floats2half2_rn(a0, a1);
                    *(__half2*)(C + i1) = __floats2half2_rn(a2, a3);
                }
            }
        }
    }
}

template<int EPI>
__global__ __launch_bounds__(256) void gemm_mma(
        const __half* __restrict__ A, const __half* __restrict__ W,
        const float* __restrict__ res, void* __restrict__ CO,
        int M, int N, int K) {
    gemm_body<EPI, 256>(A, W, res, CO, M, N, K, 0);
}

// QKV: 128x128 tiles, 2 CTAs/SM, RoPE fused
__global__ __launch_bounds__(256, 2) void gemm_qkv(const __half* __restrict__ A) {
    int z = blockIdx.z;
    const __half* W = z == 0 ? g_wq : (z == 1 ? g_wk : g_wv);
    __half* C = z == 0 ? g_qh : (z == 1 ? g_kh : g_vh);
    gemm_body<3, 128>(A, W, nullptr, C, M_TOK, D_MODEL, D_MODEL, z < 2);
}

// ---------------- RMSNorm (writes half) ----------------
__global__ void rmsnorm_kernel(const float* __restrict__ x,
                               const float* __restrict__ g,
                               __half* __restrict__ out) {
    int row = blockIdx.x;
    const float* xr = x + (size_t)row * D_MODEL;
    __half*      orow = out + (size_t)row * D_MODEL;
    float s = 0.f;
    for (int i = threadIdx.x; i < D_MODEL; i += blockDim.x) {
        float v = xr[i]; s += v * v;
    }
    __shared__ float red[32];
    for (int o = 16; o; o >>= 1) s += __shfl_down_sync(0xffffffffu, s, o);
    if ((threadIdx.x & 31) == 0) red[threadIdx.x >> 5] = s;
    __syncthreads();
    if (threadIdx.x < 32) {
        float v = (threadIdx.x < (blockDim.x >> 5)) ? red[threadIdx.x] : 0.f;
        for (int o = 16; o; o >>= 1) v += __shfl_down_sync(0xffffffffu, v, o);
        if (threadIdx.x == 0) red[0] = v;
    }
    __syncthreads();
    float rinv = rsqrtf(red[0] * (1.0f / D_MODEL) + 1e-5f);
    for (int i = threadIdx.x; i < D_MODEL; i += blockDim.x)
        orow[i] = __float2half(xr[i] * g[i] * rinv);
}

// ---------------- RoPE tables ----------------
__global__ void rope_table_kernel() {
    int idx = blockIdx.x * blockDim.x + threadIdx.x;
    if (idx >= SEQ * 64) return;
    int j = idx & 63, s = idx >> 6;
    double inv = exp(-(double)j * (9.210340371976184 / 64.0));
    double ang = (double)s * inv;
    g_rsin[idx] = (float)sin(ang);
    g_rcos[idx] = (float)cos(ang);
}

// ---------------- fp16 tensor-core flash attention (causal) ----------------
#define QLD 136
#define KLH 136
#define PLH 72
#define ATT_SMEM ((2*64*KLH + 2*64*KLH + 128*PLH) * 2)

__global__ __launch_bounds__(256) void attn_f16(
        const __half* __restrict__ Q,
        const __half* __restrict__ K,
        const __half* __restrict__ V,
        __half* __restrict__ O) {
    extern __shared__ __half smh[];
    __half* Qst = smh;
    __half* Ksm = smh;
    __half* Vsm = Ksm + 2 * 64 * KLH;
    __half* Psm = Vsm + 2 * 64 * KLH;

    int tid = threadIdx.x;
    int lane = tid & 31, wid = tid >> 5;
    int qr = lane >> 2, qc = lane & 3;
    int bh = blockIdx.y;
    int b = bh >> 4, h = bh & 15;
    int qblk = gridDim.x - 1 - blockIdx.x;   // heavy-first
    int q0 = qblk * 128;
    int nkb = 2 * qblk + 2;
    int m4 = lane >> 3;
    int r8 = lane & 7;

    for (int i = tid; i < 128 * 16; i += 256) {
        int r = i >> 4, c8 = (i & 15) * 8;
        *(uint4*)(Qst + r * QLD + c8) =
            *(const uint4*)(Q + (size_t)(b * SEQ + q0 + r) * D_MODEL + h * DKH + c8);
    }
    __syncthreads();
    uint32_t afq[8][4];
    {
        uint32_t qb_ = smem_u32(Qst);
        int row = wid * 16 + (m4 & 1) * 8 + r8;
#pragma unroll
        for (int ks = 0; ks < 8; ks++)
            ldsm_x4(afq[ks], qb_ + (uint32_t)(row * QLD + ks * 16 + (m4 >> 1) * 8) * 2);
    }
    __syncthreads();

    uint32_t ks_base = smem_u32(Ksm);
    uint32_t vs_base = smem_u32(Vsm);
    auto issue_kv = [&](int kb, int stg) {
        uint32_t off = (uint32_t)stg * 64 * KLH * 2;
#pragma unroll
        for (int i = 0; i < 4; i++) {
            int idx = tid + i * 256;
            int r = idx >> 4, c8 = (idx & 15) * 8;
            size_t g = (size_t)(b * SEQ + kb * 64 + r) * D_MODEL + h * DKH + c8;
            uint32_t d = (uint32_t)(r * KLH + c8) * 2;
            cp_async16(ks_base + off + d, K + g);
            cp_async16(vs_base + off + d, V + g);
        }
    };

    issue_kv(0, 0); CP_COMMIT();

    float o[16][4] = {};
    float m0 = -1e30f, m1 = -1e30f, l0 = 0.f, l1 = 0.f;
    const float scale = 0.08838834764831845f;

    for (int kb = 0; kb < nkb; kb++) {
        CP_WAIT(0);
        __syncthreads();
        if (kb + 1 < nkb) issue_kv(kb + 1, (kb + 1) & 1);
        CP_COMMIT();
        uint32_t kst = ks_base + (uint32_t)(kb & 1) * 64 * KLH * 2;
        uint32_t vst = vs_base + (uint32_t)(kb & 1) * 64 * KLH * 2;

        float s[8][4] = {};
#pragma unroll
        for (int c2 = 0; c2 < 4; c2++) {
#pragma unroll
            for (int n0 = 0; n0 < 8; n0++) {
                uint32_t kf[4];
                ldsm_x4(kf, kst + (uint32_t)((n0 * 8 + r8) * KLH + c2 * 32 + m4 * 8) * 2);
                mma_f16(s[n0], afq[2 * c2],     kf);
                mma_f16(s[n0], afq[2 * c2 + 1], kf + 2);
            }
        }

        bool diag = (kb >= 2 * qblk);
        int row0 = q0 + wid * 16 + qr, row1 = row0 + 8;
        float mt0 = -1e30f, mt1 = -1e30f;
#pragma unroll
        for (int nt = 0; nt < 8; nt++) {
            int col = kb * 64 + nt * 8 + 2 * qc;
            s[nt][0] *= scale; s[nt][1] *= scale;
            s[nt][2] *= scale; s[nt][3] *= scale;
            if (diag) {
                if (col > row0)     s[nt][0] = -1e30f;
                if (col + 1 > row0) s[nt][1] = -1e30f;
                if (col > row1)     s[nt][2] = -1e30f;
                if (col + 1 > row1) s[nt][3] = -1e30f;
            }
            mt0 = fmaxf(mt0, fmaxf(s[nt][0], s[nt][1]));
            mt1 = fmaxf(mt1, fmaxf(s[nt][2], s[nt][3]));
        }
#pragma unroll
        for (int off = 1; off < 4; off <<= 1) {
            mt0 = fmaxf(mt0, __shfl_xor_sync(0xffffffffu, mt0, off));
            mt1 = fmaxf(mt1, __shfl_xor_sync(0xffffffffu, mt1, off));
        }
        float mn0 = fmaxf(m0, mt0), mn1 = fmaxf(m1, mt1);
        float ls0 = 0.f, ls1 = 0.f;
        int prow = wid * 16 + qr;
#pragma unroll
        for (int nt = 0; nt < 8; nt++) {
            __half2 h01 = __floats2half2_rn(__expf(s[nt][0] - mn0), __expf(s[nt][1] - mn0));
            __half2 h23 = __floats2half2_rn(__expf(s[nt][2] - mn1), __expf(s[nt][3] - mn1));
            float2 f01 = __half22float2(h01), f23 = __half22float2(h23);
            ls0 += f01.x + f01.y; ls1 += f23.x + f23.y;
            *(__half2*)(Psm + prow * PLH + nt * 8 + 2 * qc)       = h01;
            *(__half2*)(Psm + (prow + 8) * PLH + nt * 8 + 2 * qc) = h23;
        }
#pragma unroll
        for (int off = 1; off < 4; off <<= 1) {
            ls0 += __shfl_xor_sync(0xffffffffu, ls0, off);
            ls1 += __shfl_xor_sync(0xffffffffu, ls1, off);
        }
        float al0 = __expf(m0 - mn0), al1 = __expf(m1 - mn1);
        l0 = l0 * al0 + ls0; l1 = l1 * al1 + ls1;
        m0 = mn0; m1 = mn1;
#pragma unroll
        for (int nt = 0; nt < 16; nt++) {
            o[nt][0] *= al0; o[nt][1] *= al0;
            o[nt][2] *= al1; o[nt][3] *= al1;
        }
        __syncwarp();

        uint32_t afp[4][4];
        {
            uint32_t pb = smem_u32(Psm);
            int row = wid * 16 + (m4 & 1) * 8 + r8;
#pragma unroll
            for (int ks = 0; ks < 4; ks++)
                ldsm_x4(afp[ks], pb + (uint32_t)(row * PLH + ks * 16 + (m4 >> 1) * 8) * 2);
        }
#pragma unroll
        for (int ks = 0; ks < 4; ks++) {
#pragma unroll
            for (int g = 0; g < 8; g++) {
                uint32_t vf[4];
                ldsm_x4_t(vf, vst + (uint32_t)((ks * 16 + (m4 & 1) * 8 + r8) * KLH
                                               + g * 16 + (m4 >> 1) * 8) * 2);
                mma_f16(o[2 * g],     afp[ks], vf);
                mma_f16(o[2 * g + 1], afp[ks], vf + 2);
            }
        }
    }

    float i0 = 1.f / l0, i1 = 1.f / l1;
    int r0 = b * SEQ + q0 + wid * 16 + qr;
#pragma unroll
    for (int nt = 0; nt < 16; nt++) {
        int cc = h * DKH + nt * 8 + 2 * qc;
        *(__half2*)(O + (size_t)r0 * D_MODEL + cc) =
            __floats2half2_rn(o[nt][0] * i0, o[nt][1] * i0);
        *(__half2*)(O + (size_t)(r0 + 8) * D_MODEL + cc) =
            __floats2half2_rn(o[nt][2] * i1, o[nt][3] * i1);
    }
}

// ---------------- launch ----------------
extern "C" void kernel_launch(void* const* d_in, const int* in_sizes, int n_in,
                              void* d_out, int out_size) {
    const float* x  = (const float*)d_in[0];
    const float* Wq = (const float*)d_in[1];
    const float* Wk = (const float*)d_in[2];
    const float* Wv = (const float*)d_in[3];
    const float* Wo = (const float*)d_in[4];
    const float* W1 = (const float*)d_in[5];
    const float* W2 = (const float*)d_in[6];
    const float* W3 = (const float*)d_in[7];
    const float* g1 = (const float*)d_in[8];
    const float* g2 = (const float*)d_in[9];
    float* out = (float*)d_out;

    float *xmid, *ffb;
    __half *xnh, *ctxh, *ffh, *qh, *kh, *vh;
    __half *wqh, *wkh, *wvh, *woh, *w1h, *w2h, *w3h;
    cudaGetSymbolAddress((void**)&xmid, g_xmid);
    cudaGetSymbolAddress((void**)&ffb,  g_ff);
    cudaGetSymbolAddress((void**)&xnh,  g_xn_h);
    cudaGetSymbolAddress((void**)&ctxh, g_ctx_h);
    cudaGetSymbolAddress((void**)&ffh,  g_ff_h);
    cudaGetSymbolAddress((void**)&qh,   g_qh);
    cudaGetSymbolAddress((void**)&kh,   g_kh);
    cudaGetSymbolAddress((void**)&vh,   g_vh);
    cudaGetSymbolAddress((void**)&wqh,  g_wq);
    cudaGetSymbolAddress((void**)&wkh,  g_wk);
    cudaGetSymbolAddress((void**)&wvh,  g_wv);
    cudaGetSymbolAddress((void**)&woh,  g_wo);
    cudaGetSymbolAddress((void**)&w1h,  g_w1);
    cudaGetSymbolAddress((void**)&w2h,  g_w2);
    cudaGetSymbolAddress((void**)&w3h,  g_w3);

    cudaFuncSetAttribute(gemm_mma<0>, cudaFuncAttributeMaxDynamicSharedMemorySize, GEMM_SMEM_256);
    cudaFuncSetAttribute(gemm_mma<1>, cudaFuncAttributeMaxDynamicSharedMemorySize, GEMM_SMEM_256);
    cudaFuncSetAttribute(gemm_mma<2>, cudaFuncAttributeMaxDynamicSharedMemorySize, GEMM_SMEM_256);
    cudaFuncSetAttribute(gemm_qkv,    cudaFuncAttributeMaxDynamicSharedMemorySize, GEMM_SMEM_128);
    cudaFuncSetAttribute(attn_f16,    cudaFuncAttributeMaxDynamicSharedMemorySize, ATT_SMEM);

    // ---- side stream for weight conversion (graph-capture fork/join) ----
    cudaStream_t s2;
    cudaStreamCreateWithFlags(&s2, cudaStreamNonBlocking);
    cudaEvent_t evFork, evQKV, evW;
    cudaEventCreateWithFlags(&evFork, cudaEventDisableTiming);
    cudaEventCreateWithFlags(&evQKV,  cudaEventDisableTiming);
    cudaEventCreateWithFlags(&evW,    cudaEventDisableTiming);

    cudaEventRecord(evFork, 0);
    cudaStreamWaitEvent(s2, evFork, 0);

    const int CT = 256;
    int nDM = D_MODEL * D_MODEL / 4, nFF = DFF * D_MODEL / 4;
    rope_table_kernel<<<(SEQ * 64 + 255) / 256, 256, 0, s2>>>();
    f2h_kernel<<<(nDM + CT - 1) / CT, CT, 0, s2>>>((const float4*)Wq, (__half2*)wqh, nDM);
    f2h_kernel<<<(nDM + CT - 1) / CT, CT, 0, s2>>>((const float4*)Wk, (__half2*)wkh, nDM);
    f2h_kernel<<<(nDM + CT - 1) / CT, CT, 0, s2>>>((const float4*)Wv, (__half2*)wvh, nDM);
    cudaEventRecord(evQKV, s2);
    f2h_kernel<<<(nDM + CT - 1) / CT, CT, 0, s2>>>((const float4*)Wo, (__half2*)woh, nDM);
    f2h_kernel<<<(nFF + CT - 1) / CT, CT, 0, s2>>>((const float4*)W1, (__half2*)w1h, nFF);
    f2h_kernel<<<(nFF + CT - 1) / CT, CT, 0, s2>>>((const float4*)W3, (__half2*)w3h, nFF);
    f2h_kernel<<<(nFF + CT - 1) / CT, CT, 0, s2>>>((const float4*)W2, (__half2*)w2h, nFF);
    cudaEventRecord(evW, s2);

    dim3 blk(256);
    rmsnorm_kernel<<<M_TOK, 256>>>(x, g1, xnh);
    cudaStreamWaitEvent(0, evQKV, 0);
    dim3 gq(D_MODEL / 128, M_TOK / 128, 3);          // 128x128 tiles, 2 CTA/SM
    gemm_qkv<<<gq, blk, GEMM_SMEM_128>>>(xnh);
    dim3 gattn(SEQ / 128, BATCH * NHEAD);
    attn_f16<<<gattn, blk, ATT_SMEM>>>(qh, kh, vh, ctxh);
    cudaStreamWaitEvent(0, evW, 0);
    dim3 gqkv(D_MODEL / GBN, M_TOK / 256);
    gemm_mma<1><<<gqkv, blk, GEMM_SMEM_256>>>(ctxh, woh, x, xmid, M_TOK, D_MODEL, D_MODEL);
    rmsnorm_kernel<<<M_TOK, 256>>>(xmid, g2, xnh);
    dim3 gff(DFF / GBN, M_TOK / 256);
    gemm_mma<0><<<gff, blk, GEMM_SMEM_256>>>(xnh, w1h, nullptr, ffb, M_TOK, DFF, D_MODEL);
    gemm_mma<2><<<gff, blk, GEMM_SMEM_256>>>(xnh, w3h, ffb, ffh, M_TOK, DFF, D_MODEL);
    gemm_mma<1><<<gqkv, blk, GEMM_SMEM_256>>>(ffh, w2h, xmid, out, M_TOK, D_MODEL, DFF);
}

// round 10
// speedup vs baseline: 13.2618x; 1.0694x over previous
#include <cuda_runtime.h>
#include <cuda_fp16.h>
#include <math.h>
#include <stdint.h>

#define D_MODEL 2048
#define NHEAD   16
#define DKH     128
#define DFF     5632
#define SEQ     2048
#define BATCH   2
#define M_TOK   (BATCH*SEQ)   // 4096

// ---------------- scratch ----------------
__device__ float  g_xmid[(size_t)M_TOK*D_MODEL];
__device__ __half g_xn_h [(size_t)M_TOK*D_MODEL];
__device__ __half g_ctx_h[(size_t)M_TOK*D_MODEL];
__device__ __half g_ffa_h[(size_t)M_TOK*DFF];   // W1 output (pre-silu), half
__device__ __half g_ff_h [(size_t)M_TOK*DFF];   // silu(a)*gate, half
__device__ __half g_qh[(size_t)M_TOK*D_MODEL];
__device__ __half g_kh[(size_t)M_TOK*D_MODEL];
__device__ __half g_vh[(size_t)M_TOK*D_MODEL];
__device__ __half g_wq[(size_t)D_MODEL*D_MODEL];
__device__ __half g_wk[(size_t)D_MODEL*D_MODEL];
__device__ __half g_wv[(size_t)D_MODEL*D_MODEL];
__device__ __half g_wo[(size_t)D_MODEL*D_MODEL];
__device__ __half g_w1[(size_t)DFF*D_MODEL];
__device__ __half g_w2[(size_t)D_MODEL*DFF];
__device__ __half g_w3[(size_t)DFF*D_MODEL];
__device__ float  g_rsin[SEQ*64];
__device__ float  g_rcos[SEQ*64];

// ================= helpers =================
__device__ __forceinline__ void mma_f16(float* d, const uint32_t* a, const uint32_t* b) {
    asm volatile(
        "mma.sync.aligned.m16n8k16.row.col.f32.f16.f16.f32 "
        "{%0,%1,%2,%3}, {%4,%5,%6,%7}, {%8,%9}, {%0,%1,%2,%3};"
        : "+f"(d[0]), "+f"(d[1]), "+f"(d[2]), "+f"(d[3])
        : "r"(a[0]), "r"(a[1]), "r"(a[2]), "r"(a[3]),
          "r"(b[0]), "r"(b[1]));
}
__device__ __forceinline__ uint32_t smem_u32(const void* p) {
    uint32_t a;
    asm("{ .reg .u64 t; cvta.to.shared.u64 t, %1; cvt.u32.u64 %0, t; }"
        : "=r"(a) : "l"(p));
    return a;
}
__device__ __forceinline__ void cp_async16(uint32_t dst, const void* src) {
    asm volatile("cp.async.cg.shared.global [%0], [%1], 16;" :: "r"(dst), "l"(src));
}
#define CP_COMMIT()  asm volatile("cp.async.commit_group;" ::: "memory")
#define CP_WAIT(N)   asm volatile("cp.async.wait_group %0;" :: "n"(N) : "memory")

__device__ __forceinline__ void ldsm_x4(uint32_t* r, uint32_t a) {
    asm volatile("ldmatrix.sync.aligned.m8n8.x4.shared.b16 {%0,%1,%2,%3}, [%4];"
                 : "=r"(r[0]), "=r"(r[1]), "=r"(r[2]), "=r"(r[3]) : "r"(a));
}
__device__ __forceinline__ void ldsm_x4_t(uint32_t* r, uint32_t a) {
    asm volatile("ldmatrix.sync.aligned.m8n8.x4.trans.shared.b16 {%0,%1,%2,%3}, [%4];"
                 : "=r"(r[0]), "=r"(r[1]), "=r"(r[2]), "=r"(r[3]) : "r"(a));
}

// ---------------- fp32 -> fp16 convert ----------------
__global__ void f2h_kernel(const float4* __restrict__ in, __half2* __restrict__ out, int n4) {
    int i = blockIdx.x * blockDim.x + threadIdx.x;
    if (i >= n4) return;
    float4 v = in[i];
    out[2 * i]     = __floats2half2_rn(v.x, v.y);
    out[2 * i + 1] = __floats2half2_rn(v.z, v.w);
}

// ================= fp16 GEMM, 128x128 tiles, 2 CTAs/SM, 3-stage =============
// C[M,N] = A[M,K] @ W[N,K]^T  (half in, fp32 accumulate)
// EPI 1: fp32 C = res(f32) + acc
// EPI 2: half C = silu(res(f16)) * acc
// EPI 3: half C = acc, optional RoPE (ropef)
#define GBM 128
#define GBN 128
#define LDH  40
#define LDH2 20
#define GSTG 3
#define GEMM_SMEM (GSTG*(GBM+GBN)*LDH*2)

template<int EPI>
__device__ __forceinline__ void gemm_body(
        const __half* __restrict__ A,
        const __half* __restrict__ W,
        const void* __restrict__ res,
        void* __restrict__ CO,
        int M, int N, int K, int ropef) {
    extern __shared__ char smc[];
    __half* As = (__half*)smc;                      // [GSTG][GBM][LDH]
    __half* Bs = As + GSTG * GBM * LDH;             // [GSTG][GBN][LDH]

    int tid  = threadIdx.x;
    int lane = tid & 31, wid = tid >> 5;
    int wmb = (wid >> 2) * 64, wnb = (wid & 3) * 32;   // 2m x 4n warps
    int bm = blockIdx.y * GBM, bn = blockIdx.x * GBN;

    uint32_t as_base = smem_u32(As);
    uint32_t bs_base = smem_u32(Bs);

    auto issue_stage = [&](int tile, int stg) {
        uint32_t aoff = (uint32_t)stg * GBM * LDH * 2;
        uint32_t boff = (uint32_t)stg * GBN * LDH * 2;
        const __half* a2 = A + (size_t)bm * K + tile * 32;
        const __half* w2 = W + (size_t)bn * K + tile * 32;
#pragma unroll
        for (int i = 0; i < 2; i++) {
            int idx = tid + i * 256;
            int r = idx >> 2, c = (idx & 3) * 8;
            cp_async16(as_base + aoff + (uint32_t)(r * LDH + c) * 2,
                       a2 + (size_t)r * K + c);
            cp_async16(bs_base + boff + (uint32_t)(r * LDH + c) * 2,
                       w2 + (size_t)r * K + c);
        }
    };

    int nk = K >> 5;
    issue_stage(0, 0); CP_COMMIT();
    issue_stage(1, 1); CP_COMMIT();

    float acc[4][4][4] = {};
    int qr = lane >> 2, qc = lane & 3;

    int stg = 0;
    for (int kt = 0; kt < nk; kt++) {
        CP_WAIT(1);
        __syncthreads();
        const uint32_t* A32 = (const uint32_t*)(As + stg * GBM * LDH);
        const uint32_t* B32 = (const uint32_t*)(Bs + stg * GBN * LDH);
#pragma unroll
        for (int ks = 0; ks < 2; ks++) {
            int cb = ks * 8 + qc;
            uint32_t af[4][4], bf[4][2];
#pragma unroll
            for (int mt = 0; mt < 4; mt++) {
                int r = wmb + mt * 16 + qr;
                af[mt][0] = A32[r * LDH2 + cb];
                af[mt][1] = A32[(r + 8) * LDH2 + cb];
                af[mt][2] = A32[r * LDH2 + cb + 4];
                af[mt][3] = A32[(r + 8) * LDH2 + cb + 4];
            }
#pragma unroll
            for (int nt = 0; nt < 4; nt++) {
                int n = wnb + nt * 8 + qr;
                bf[nt][0] = B32[n * LDH2 + cb];
                bf[nt][1] = B32[n * LDH2 + cb + 4];
            }
#pragma unroll
            for (int mt = 0; mt < 4; mt++)
#pragma unroll
                for (int nt = 0; nt < 4; nt++)
                    mma_f16(acc[mt][nt], af[mt], bf[nt]);
        }
        int nstg = stg + 2; if (nstg >= GSTG) nstg -= GSTG;
        if (kt + 2 < nk) issue_stage(kt + 2, nstg);
        CP_COMMIT();
        stg = stg + 1 == GSTG ? 0 : stg + 1;
    }

#pragma unroll
    for (int mt = 0; mt < 4; mt++) {
        int r0 = bm + wmb + mt * 16 + qr;
#pragma unroll
        for (int nt = 0; nt < 4; nt++) {
            int cc = bn + wnb + nt * 8 + 2 * qc;
            size_t i0 = (size_t)r0 * N + cc;
            size_t i1 = (size_t)(r0 + 8) * N + cc;
            if (EPI == 1) {
                const float* rf = (const float*)res;
                float* C = (float*)CO;
                float2 rr0 = *(const float2*)(rf + i0);
                float2 rr1 = *(const float2*)(rf + i1);
                *(float2*)(C + i0) = make_float2(acc[mt][nt][0] + rr0.x,
                                                 acc[mt][nt][1] + rr0.y);
                *(float2*)(C + i1) = make_float2(acc[mt][nt][2] + rr1.x,
                                                 acc[mt][nt][3] + rr1.y);
            } else if (EPI == 2) {
                const __half* rh = (const __half*)res;
                __half* C = (__half*)CO;
                float2 a0 = __half22float2(*(const __half2*)(rh + i0));
                float2 a1 = __half22float2(*(const __half2*)(rh + i1));
                float v0 = acc[mt][nt][0] * (a0.x / (1.f + __expf(-a0.x)));
                float v1 = acc[mt][nt][1] * (a0.y / (1.f + __expf(-a0.y)));
                float v2 = acc[mt][nt][2] * (a1.x / (1.f + __expf(-a1.x)));
                float v3 = acc[mt][nt][3] * (a1.y / (1.f + __expf(-a1.y)));
                *(__half2*)(C + i0) = __floats2half2_rn(v0, v1);
                *(__half2*)(C + i1) = __floats2half2_rn(v2, v3);
            } else {
                __half* C = (__half*)CO;
                float a0 = acc[mt][nt][0], a1 = acc[mt][nt][1];
                float a2 = acc[mt][nt][2], a3 = acc[mt][nt][3];
                if (ropef) {
                    int s0 = r0 & (SEQ - 1), s1 = (r0 + 8) & (SEQ - 1);
                    int j  = (cc & 127) >> 1;
                    float sn0 = g_rsin[s0 * 64 + j], cs0 = g_rcos[s0 * 64 + j];
                    float sn1 = g_rsin[s1 * 64 + j], cs1 = g_rcos[s1 * 64 + j];
                    *(__half2*)(C + i0) = __floats2half2_rn(a0 * cs0 - a1 * sn0,
                                                            a0 * sn0 + a1 * cs0);
                    *(__half2*)(C + i1) = __floats2half2_rn(a2 * cs1 - a3 * sn1,
                                                            a2 * sn1 + a3 * cs1);
                } else {
                    *(__half2*)(C + i0) = __floats2half2_rn(a0, a1);
                    *(__half2*)(C + i1) = __floats2half2_rn(a2, a3);
                }
            }
        }
    }
}

template<int EPI>
__global__ __launch_bounds__(256, 2) void gemm_mma(
        const __half* __restrict__ A, const __half* __restrict__ W,
        const void* __restrict__ res, void* __restrict__ CO,
        int M, int N, int K) {
    gemm_body<EPI>(A, W, res, CO, M, N, K, 0);
}

// QKV: RoPE fused into Q/K epilogues
__global__ __launch_bounds__(256, 2) void gemm_qkv(const __half* __restrict__ A) {
    int z = blockIdx.z;
    const __half* W = z == 0 ? g_wq : (z == 1 ? g_wk : g_wv);
    __half* C = z == 0 ? g_qh : (z == 1 ? g_kh : g_vh);
    gemm_body<3>(A, W, nullptr, C, M_TOK, D_MODEL, D_MODEL, z < 2);
}

// ---------------- RMSNorm (writes half) ----------------
__global__ void rmsnorm_kernel(const float* __restrict__ x,
                               const float* __restrict__ g,
                               __half* __restrict__ out) {
    int row = blockIdx.x;
    const float* xr = x + (size_t)row * D_MODEL;
    __half*      orow = out + (size_t)row * D_MODEL;
    float s = 0.f;
    for (int i = threadIdx.x; i < D_MODEL; i += blockDim.x) {
        float v = xr[i]; s += v * v;
    }
    __shared__ float red[32];
    for (int o = 16; o; o >>= 1) s += __shfl_down_sync(0xffffffffu, s, o);
    if ((threadIdx.x & 31) == 0) red[threadIdx.x >> 5] = s;
    __syncthreads();
    if (threadIdx.x < 32) {
        float v = (threadIdx.x < (blockDim.x >> 5)) ? red[threadIdx.x] : 0.f;
        for (int o = 16; o; o >>= 1) v += __shfl_down_sync(0xffffffffu, v, o);
        if (threadIdx.x == 0) red[0] = v;
    }
    __syncthreads();
    float rinv = rsqrtf(red[0] * (1.0f / D_MODEL) + 1e-5f);
    for (int i = threadIdx.x; i < D_MODEL; i += blockDim.x)
        orow[i] = __float2half(xr[i] * g[i] * rinv);
}

// ---------------- RoPE tables ----------------
__global__ void rope_table_kernel() {
    int idx = blockIdx.x * blockDim.x + threadIdx.x;
    if (idx >= SEQ * 64) return;
    int j = idx & 63, s = idx >> 6;
    double inv = exp(-(double)j * (9.210340371976184 / 64.0));
    double ang = (double)s * inv;
    g_rsin[idx] = (float)sin(ang);
    g_rcos[idx] = (float)cos(ang);
}

// ---------------- fp16 tensor-core flash attention (causal) ----------------
#define QLD 136
#define KLH 136
#define PLH 72
#define ATT_SMEM ((2*64*KLH + 2*64*KLH + 128*PLH) * 2)

__global__ __launch_bounds__(256) void attn_f16(
        const __half* __restrict__ Q,
        const __half* __restrict__ K,
        const __half* __restrict__ V,
        __half* __restrict__ O) {
    extern __shared__ __half smh[];
    __half* Qst = smh;
    __half* Ksm = smh;
    __half* Vsm = Ksm + 2 * 64 * KLH;
    __half* Psm = Vsm + 2 * 64 * KLH;

    int tid = threadIdx.x;
    int lane = tid & 31, wid = tid >> 5;
    int qr = lane >> 2, qc = lane & 3;
    int bh = blockIdx.y;
    int b = bh >> 4, h = bh & 15;
    int qblk = gridDim.x - 1 - blockIdx.x;   // heavy-first
    int q0 = qblk * 128;
    int nkb = 2 * qblk + 2;
    int m4 = lane >> 3;
    int r8 = lane & 7;

    for (int i = tid; i < 128 * 16; i += 256) {
        int r = i >> 4, c8 = (i & 15) * 8;
        *(uint4*)(Qst + r * QLD + c8) =
            *(const uint4*)(Q + (size_t)(b * SEQ + q0 + r) * D_MODEL + h * DKH + c8);
    }
    __syncthreads();
    uint32_t afq[8][4];
    {
        uint32_t qb_ = smem_u32(Qst);
        int row = wid * 16 + (m4 & 1) * 8 + r8;
#pragma unroll
        for (int ks = 0; ks < 8; ks++)
            ldsm_x4(afq[ks], qb_ + (uint32_t)(row * QLD + ks * 16 + (m4 >> 1) * 8) * 2);
    }
    __syncthreads();

    uint32_t ks_base = smem_u32(Ksm);
    uint32_t vs_base = smem_u32(Vsm);
    auto issue_kv = [&](int kb, int stg) {
        uint32_t off = (uint32_t)stg * 64 * KLH * 2;
#pragma unroll
        for (int i = 0; i < 4; i++) {
            int idx = tid + i * 256;
            int r = idx >> 4, c8 = (idx & 15) * 8;
            size_t g = (size_t)(b * SEQ + kb * 64 + r) * D_MODEL + h * DKH + c8;
            uint32_t d = (uint32_t)(r * KLH + c8) * 2;
            cp_async16(ks_base + off + d, K + g);
            cp_async16(vs_base + off + d, V + g);
        }
    };

    issue_kv(0, 0); CP_COMMIT();

    float o[16][4] = {};
    float m0 = -1e30f, m1 = -1e30f, l0 = 0.f, l1 = 0.f;
    const float scale = 0.08838834764831845f;

    for (int kb = 0; kb < nkb; kb++) {
        CP_WAIT(0);
        __syncthreads();
        if (kb + 1 < nkb) issue_kv(kb + 1, (kb + 1) & 1);
        CP_COMMIT();
        uint32_t kst = ks_base + (uint32_t)(kb & 1) * 64 * KLH * 2;
        uint32_t vst = vs_base + (uint32_t)(kb & 1) * 64 * KLH * 2;

        float s[8][4] = {};
#pragma unroll
        for (int c2 = 0; c2 < 4; c2++) {
#pragma unroll
            for (int n0 = 0; n0 < 8; n0++) {
                uint32_t kf[4];
                ldsm_x4(kf, kst + (uint32_t)((n0 * 8 + r8) * KLH + c2 * 32 + m4 * 8) * 2);
                mma_f16(s[n0], afq[2 * c2],     kf);
                mma_f16(s[n0], afq[2 * c2 + 1], kf + 2);
            }
        }

        bool diag = (kb >= 2 * qblk);
        int row0 = q0 + wid * 16 + qr, row1 = row0 + 8;
        float mt0 = -1e30f, mt1 = -1e30f;
#pragma unroll
        for (int nt = 0; nt < 8; nt++) {
            int col = kb * 64 + nt * 8 + 2 * qc;
            s[nt][0] *= scale; s[nt][1] *= scale;
            s[nt][2] *= scale; s[nt][3] *= scale;
            if (diag) {
                if (col > row0)     s[nt][0] = -1e30f;
                if (col + 1 > row0) s[nt][1] = -1e30f;
                if (col > row1)     s[nt][2] = -1e30f;
                if (col + 1 > row1) s[nt][3] = -1e30f;
            }
            mt0 = fmaxf(mt0, fmaxf(s[nt][0], s[nt][1]));
            mt1 = fmaxf(mt1, fmaxf(s[nt][2], s[nt][3]));
        }
#pragma unroll
        for (int off = 1; off < 4; off <<= 1) {
            mt0 = fmaxf(mt0, __shfl_xor_sync(0xffffffffu, mt0, off));
            mt1 = fmaxf(mt1, __shfl_xor_sync(0xffffffffu, mt1, off));
        }
        float mn0 = fmaxf(m0, mt0), mn1 = fmaxf(m1, mt1);
        float ls0 = 0.f, ls1 = 0.f;
        int prow = wid * 16 + qr;
#pragma unroll
        for (int nt = 0; nt < 8; nt++) {
            __half2 h01 = __floats2half2_rn(__expf(s[nt][0] - mn0), __expf(s[nt][1] - mn0));
            __half2 h23 = __floats2half2_rn(__expf(s[nt][2] - mn1), __expf(s[nt][3] - mn1));
            float2 f01 = __half22float2(h01), f23 = __half22float2(h23);
            ls0 += f01.x + f01.y; ls1 += f23.x + f23.y;
            *(__half2*)(Psm + prow * PLH + nt * 8 + 2 * qc)       = h01;
            *(__half2*)(Psm + (prow + 8) * PLH + nt * 8 + 2 * qc) = h23;
        }
#pragma unroll
        for (int off = 1; off < 4; off <<= 1) {
            ls0 += __shfl_xor_sync(0xffffffffu, ls0, off);
            ls1 += __shfl_xor_sync(0xffffffffu, ls1, off);
        }
        float al0 = __expf(m0 - mn0), al1 = __expf(m1 - mn1);
        l0 = l0 * al0 + ls0; l1 = l1 * al1 + ls1;
        m0 = mn0; m1 = mn1;
#pragma unroll
        for (int nt = 0; nt < 16; nt++) {
            o[nt][0] *= al0; o[nt][1] *= al0;
            o[nt][2] *= al1; o[nt][3] *= al1;
        }
        __syncwarp();

        uint32_t afp[4][4];
        {
            uint32_t pb = smem_u32(Psm);
            int row = wid * 16 + (m4 & 1) * 8 + r8;
#pragma unroll
            for (int ks = 0; ks < 4; ks++)
                ldsm_x4(afp[ks], pb + (uint32_t)(row * PLH + ks * 16 + (m4 >> 1) * 8) * 2);
        }
#pragma unroll
        for (int ks = 0; ks < 4; ks++) {
#pragma unroll
            for (int g = 0; g < 8; g++) {
                uint32_t vf[4];
                ldsm_x4_t(vf, vst + (uint32_t)((ks * 16 + (m4 & 1) * 8 + r8) * KLH
                                               + g * 16 + (m4 >> 1) * 8) * 2);
                mma_f16(o[2 * g],     afp[ks], vf);
                mma_f16(o[2 * g + 1], afp[ks], vf + 2);
            }
        }
    }

    float i0 = 1.f / l0, i1 = 1.f / l1;
    int r0 = b * SEQ + q0 + wid * 16 + qr;
#pragma unroll
    for (int nt = 0; nt < 16; nt++) {
        int cc = h * DKH + nt * 8 + 2 * qc;
        *(__half2*)(O + (size_t)r0 * D_MODEL + cc) =
            __floats2half2_rn(o[nt][0] * i0, o[nt][1] * i0);
        *(__half2*)(O + (size_t)(r0 + 8) * D_MODEL + cc) =
            __floats2half2_rn(o[nt][2] * i1, o[nt][3] * i1);
    }
}

// ---------------- launch ----------------
extern "C" void kernel_launch(void* const* d_in, const int* in_sizes, int n_in,
                              void* d_out, int out_size) {
    const float* x  = (const float*)d_in[0];
    const float* Wq = (const float*)d_in[1];
    const float* Wk = (const float*)d_in[2];
    const float* Wv = (const float*)d_in[3];
    const float* Wo = (const float*)d_in[4];
    const float* W1 = (const float*)d_in[5];
    const float* W2 = (const float*)d_in[6];
    const float* W3 = (const float*)d_in[7];
    const float* g1 = (const float*)d_in[8];
    const float* g2 = (const float*)d_in[9];
    float* out = (float*)d_out;

    float *xmid;
    __half *xnh, *ctxh, *ffah, *ffh, *qh, *kh, *vh;
    __half *wqh, *wkh, *wvh, *woh, *w1h, *w2h, *w3h;
    cudaGetSymbolAddress((void**)&xmid, g_xmid);
    cudaGetSymbolAddress((void**)&xnh,  g_xn_h);
    cudaGetSymbolAddress((void**)&ctxh, g_ctx_h);
    cudaGetSymbolAddress((void**)&ffah, g_ffa_h);
    cudaGetSymbolAddress((void**)&ffh,  g_ff_h);
    cudaGetSymbolAddress((void**)&qh,   g_qh);
    cudaGetSymbolAddress((void**)&kh,   g_kh);
    cudaGetSymbolAddress((void**)&vh,   g_vh);
    cudaGetSymbolAddress((void**)&wqh,  g_wq);
    cudaGetSymbolAddress((void**)&wkh,  g_wk);
    cudaGetSymbolAddress((void**)&wvh,  g_wv);
    cudaGetSymbolAddress((void**)&woh,  g_wo);
    cudaGetSymbolAddress((void**)&w1h,  g_w1);
    cudaGetSymbolAddress((void**)&w2h,  g_w2);
    cudaGetSymbolAddress((void**)&w3h,  g_w3);

    cudaFuncSetAttribute(gemm_mma<1>, cudaFuncAttributeMaxDynamicSharedMemorySize, GEMM_SMEM);
    cudaFuncSetAttribute(gemm_mma<2>, cudaFuncAttributeMaxDynamicSharedMemorySize, GEMM_SMEM);
    cudaFuncSetAttribute(gemm_mma<3>, cudaFuncAttributeMaxDynamicSharedMemorySize, GEMM_SMEM);
    cudaFuncSetAttribute(gemm_qkv,    cudaFuncAttributeMaxDynamicSharedMemorySize, GEMM_SMEM);
    cudaFuncSetAttribute(attn_f16,    cudaFuncAttributeMaxDynamicSharedMemorySize, ATT_SMEM);

    // ---- side stream for weight conversion (graph-capture fork/join) ----
    cudaStream_t s2;
    cudaStreamCreateWithFlags(&s2, cudaStreamNonBlocking);
    cudaEvent_t evFork, evQKV, evW;
    cudaEventCreateWithFlags(&evFork, cudaEventDisableTiming);
    cudaEventCreateWithFlags(&evQKV,  cudaEventDisableTiming);
    cudaEventCreateWithFlags(&evW,    cudaEventDisableTiming);

    cudaEventRecord(evFork, 0);
    cudaStreamWaitEvent(s2, evFork, 0);

    const int CT = 256;
    int nDM = D_MODEL * D_MODEL / 4, nFF = DFF * D_MODEL / 4;
    rope_table_kernel<<<(SEQ * 64 + 255) / 256, 256, 0, s2>>>();
    f2h_kernel<<<(nDM + CT - 1) / CT, CT, 0, s2>>>((const float4*)Wq, (__half2*)wqh, nDM);
    f2h_kernel<<<(nDM + CT - 1) / CT, CT, 0, s2>>>((const float4*)Wk, (__half2*)wkh, nDM);
    f2h_kernel<<<(nDM + CT - 1) / CT, CT, 0, s2>>>((const float4*)Wv, (__half2*)wvh, nDM);
    cudaEventRecord(evQKV, s2);
    f2h_kernel<<<(nDM + CT - 1) / CT, CT, 0, s2>>>((const float4*)Wo, (__half2*)woh, nDM);
    f2h_kernel<<<(nFF + CT - 1) / CT, CT, 0, s2>>>((const float4*)W1, (__half2*)w1h, nFF);
    f2h_kernel<<<(nFF + CT - 1) / CT, CT, 0, s2>>>((const float4*)W3, (__half2*)w3h, nFF);
    f2h_kernel<<<(nFF + CT - 1) / CT, CT, 0, s2>>>((const float4*)W2, (__half2*)w2h, nFF);
    cudaEventRecord(evW, s2);

    dim3 blk(256);
    rmsnorm_kernel<<<M_TOK, 256>>>(x, g1, xnh);
    cudaStreamWaitEvent(0, evQKV, 0);
    dim3 gq(D_MODEL / GBN, M_TOK / GBM, 3);
    gemm_qkv<<<gq, blk, GEMM_SMEM>>>(xnh);
    dim3 gattn(SEQ / 128, BATCH * NHEAD);
    attn_f16<<<gattn, blk, ATT_SMEM>>>(qh, kh, vh, ctxh);
    cudaStreamWaitEvent(0, evW, 0);
    dim3 gdm(D_MODEL / GBN, M_TOK / GBM);
    gemm_mma<1><<<gdm, blk, GEMM_SMEM>>>(ctxh, woh, x, xmid, M_TOK, D_MODEL, D_MODEL);
    rmsnorm_kernel<<<M_TOK, 256>>>(xmid, g2, xnh);
    dim3 gff(DFF / GBN, M_TOK / GBM);
    gemm_mma<3><<<gff, blk, GEMM_SMEM>>>(xnh, w1h, nullptr, ffah, M_TOK, DFF, D_MODEL);
    gemm_mma<2><<<gff, blk, GEMM_SMEM>>>(xnh, w3h, ffah, ffh, M_TOK, DFF, D_MODEL);
    gemm_mma<1><<<gdm, blk, GEMM_SMEM>>>(ffh, w2h, xmid, out, M_TOK, D_MODEL, DFF);
}

// round 11
// speedup vs baseline: 13.3866x; 1.0094x over previous
#include <cuda_runtime.h>
#include <cuda_fp16.h>
#include <math.h>
#include <stdint.h>

#define D_MODEL 2048
#define NHEAD   16
#define DKH     128
#define DFF     5632
#define SEQ     2048
#define BATCH   2
#define M_TOK   (BATCH*SEQ)   // 4096

// ---------------- scratch ----------------
__device__ float  g_xmid[(size_t)M_TOK*D_MODEL];
__device__ __half g_xn_h [(size_t)M_TOK*D_MODEL];
__device__ __half g_ctx_h[(size_t)M_TOK*D_MODEL];
__device__ __half g_ffa_h[(size_t)M_TOK*DFF];
__device__ __half g_ff_h [(size_t)M_TOK*DFF];
__device__ __half g_qh[(size_t)M_TOK*D_MODEL];
__device__ __half g_kh[(size_t)M_TOK*D_MODEL];
__device__ __half g_vh[(size_t)M_TOK*D_MODEL];
__device__ __half g_wq[(size_t)D_MODEL*D_MODEL];
__device__ __half g_wk[(size_t)D_MODEL*D_MODEL];
__device__ __half g_wv[(size_t)D_MODEL*D_MODEL];
__device__ __half g_wo[(size_t)D_MODEL*D_MODEL];
__device__ __half g_w1[(size_t)DFF*D_MODEL];
__device__ __half g_w2[(size_t)D_MODEL*DFF];
__device__ __half g_w3[(size_t)DFF*D_MODEL];
__device__ float  g_rsin[SEQ*64];
__device__ float  g_rcos[SEQ*64];

// ================= helpers =================
__device__ __forceinline__ void mma_f16(float* d, const uint32_t* a, const uint32_t* b) {
    asm volatile(
        "mma.sync.aligned.m16n8k16.row.col.f32.f16.f16.f32 "
        "{%0,%1,%2,%3}, {%4,%5,%6,%7}, {%8,%9}, {%0,%1,%2,%3};"
        : "+f"(d[0]), "+f"(d[1]), "+f"(d[2]), "+f"(d[3])
        : "r"(a[0]), "r"(a[1]), "r"(a[2]), "r"(a[3]),
          "r"(b[0]), "r"(b[1]));
}
__device__ __forceinline__ uint32_t smem_u32(const void* p) {
    uint32_t a;
    asm("{ .reg .u64 t; cvta.to.shared.u64 t, %1; cvt.u32.u64 %0, t; }"
        : "=r"(a) : "l"(p));
    return a;
}
__device__ __forceinline__ void cp_async16(uint32_t dst, const void* src) {
    asm volatile("cp.async.cg.shared.global [%0], [%1], 16;" :: "r"(dst), "l"(src));
}
#define CP_COMMIT()  asm volatile("cp.async.commit_group;" ::: "memory")
#define CP_WAIT(N)   asm volatile("cp.async.wait_group %0;" :: "n"(N) : "memory")

__device__ __forceinline__ void ldsm_x4(uint32_t* r, uint32_t a) {
    asm volatile("ldmatrix.sync.aligned.m8n8.x4.shared.b16 {%0,%1,%2,%3}, [%4];"
                 : "=r"(r[0]), "=r"(r[1]), "=r"(r[2]), "=r"(r[3]) : "r"(a));
}
__device__ __forceinline__ void ldsm_x4_t(uint32_t* r, uint32_t a) {
    asm volatile("ldmatrix.sync.aligned.m8n8.x4.trans.shared.b16 {%0,%1,%2,%3}, [%4];"
                 : "=r"(r[0]), "=r"(r[1]), "=r"(r[2]), "=r"(r[3]) : "r"(a));
}
__device__ __forceinline__ uint32_t f22u(float a, float b) {
    __half2 h = __floats2half2_rn(a, b);
    return *(uint32_t*)&h;
}

// ---------------- fp32 -> fp16 convert ----------------
__global__ void f2h_kernel(const float4* __restrict__ in, __half2* __restrict__ out, int n4) {
    int i = blockIdx.x * blockDim.x + threadIdx.x;
    if (i >= n4) return;
    float4 v = in[i];
    out[2 * i]     = __floats2half2_rn(v.x, v.y);
    out[2 * i + 1] = __floats2half2_rn(v.z, v.w);
}

// ================= fp16 GEMM, 128x128 tiles, 2 CTAs/SM, 3-stage =============
// EPI 1: fp32 C = res(f32) + acc
// EPI 2: half C = silu(res(f16)) * acc
// EPI 3: half C = acc, optional RoPE (ropef)
#define GBM 128
#define GBN 128
#define LDH  40
#define LDH2 20
#define GSTG 3
#define GEMM_SMEM (GSTG*(GBM+GBN)*LDH*2)

template<int EPI>
__device__ __forceinline__ void gemm_body(
        const __half* __restrict__ A,
        const __half* __restrict__ W,
        const void* __restrict__ res,
        void* __restrict__ CO,
        int M, int N, int K, int ropef) {
    extern __shared__ char smc[];
    __half* As = (__half*)smc;
    __half* Bs = As + GSTG * GBM * LDH;

    int tid  = threadIdx.x;
    int lane = tid & 31, wid = tid >> 5;
    int wmb = (wid >> 2) * 64, wnb = (wid & 3) * 32;
    int bm = blockIdx.y * GBM, bn = blockIdx.x * GBN;

    uint32_t as_base = smem_u32(As);
    uint32_t bs_base = smem_u32(Bs);

    auto issue_stage = [&](int tile, int stg) {
        uint32_t aoff = (uint32_t)stg * GBM * LDH * 2;
        uint32_t boff = (uint32_t)stg * GBN * LDH * 2;
        const __half* a2 = A + (size_t)bm * K + tile * 32;
        const __half* w2 = W + (size_t)bn * K + tile * 32;
#pragma unroll
        for (int i = 0; i < 2; i++) {
            int idx = tid + i * 256;
            int r = idx >> 2, c = (idx & 3) * 8;
            cp_async16(as_base + aoff + (uint32_t)(r * LDH + c) * 2,
                       a2 + (size_t)r * K + c);
            cp_async16(bs_base + boff + (uint32_t)(r * LDH + c) * 2,
                       w2 + (size_t)r * K + c);
        }
    };

    int nk = K >> 5;
    issue_stage(0, 0); CP_COMMIT();
    issue_stage(1, 1); CP_COMMIT();

    float acc[4][4][4] = {};
    int qr = lane >> 2, qc = lane & 3;

    int stg = 0;
    for (int kt = 0; kt < nk; kt++) {
        CP_WAIT(1);
        __syncthreads();
        const uint32_t* A32 = (const uint32_t*)(As + stg * GBM * LDH);
        const uint32_t* B32 = (const uint32_t*)(Bs + stg * GBN * LDH);
#pragma unroll
        for (int ks = 0; ks < 2; ks++) {
            int cb = ks * 8 + qc;
            uint32_t af[4][4], bf[4][2];
#pragma unroll
            for (int mt = 0; mt < 4; mt++) {
                int r = wmb + mt * 16 + qr;
                af[mt][0] = A32[r * LDH2 + cb];
                af[mt][1] = A32[(r + 8) * LDH2 + cb];
                af[mt][2] = A32[r * LDH2 + cb + 4];
                af[mt][3] = A32[(r + 8) * LDH2 + cb + 4];
            }
#pragma unroll
            for (int nt = 0; nt < 4; nt++) {
                int n = wnb + nt * 8 + qr;
                bf[nt][0] = B32[n * LDH2 + cb];
                bf[nt][1] = B32[n * LDH2 + cb + 4];
            }
#pragma unroll
            for (int mt = 0; mt < 4; mt++)
#pragma unroll
                for (int nt = 0; nt < 4; nt++)
                    mma_f16(acc[mt][nt], af[mt], bf[nt]);
        }
        int nstg = stg + 2; if (nstg >= GSTG) nstg -= GSTG;
        if (kt + 2 < nk) issue_stage(kt + 2, nstg);
        CP_COMMIT();
        stg = stg + 1 == GSTG ? 0 : stg + 1;
    }

#pragma unroll
    for (int mt = 0; mt < 4; mt++) {
        int r0 = bm + wmb + mt * 16 + qr;
#pragma unroll
        for (int nt = 0; nt < 4; nt++) {
            int cc = bn + wnb + nt * 8 + 2 * qc;
            size_t i0 = (size_t)r0 * N + cc;
            size_t i1 = (size_t)(r0 + 8) * N + cc;
            if (EPI == 1) {
                const float* rf = (const float*)res;
                float* C = (float*)CO;
                float2 rr0 = *(const float2*)(rf + i0);
                float2 rr1 = *(const float2*)(rf + i1);
                *(float2*)(C + i0) = make_float2(acc[mt][nt][0] + rr0.x,
                                                 acc[mt][nt][1] + rr0.y);
                *(float2*)(C + i1) = make_float2(acc[mt][nt][2] + rr1.x,
                                                 acc[mt][nt][3] + rr1.y);
            } else if (EPI == 2) {
                const __half* rh = (const __half*)res;
                __half* C = (__half*)CO;
                float2 a0 = __half22float2(*(const __half2*)(rh + i0));
                float2 a1 = __half22float2(*(const __half2*)(rh + i1));
                float v0 = acc[mt][nt][0] * (a0.x / (1.f + __expf(-a0.x)));
                float v1 = acc[mt][nt][1] * (a0.y / (1.f + __expf(-a0.y)));
                float v2 = acc[mt][nt][2] * (a1.x / (1.f + __expf(-a1.x)));
                float v3 = acc[mt][nt][3] * (a1.y / (1.f + __expf(-a1.y)));
                *(__half2*)(C + i0) = __floats2half2_rn(v0, v1);
                *(__half2*)(C + i1) = __floats2half2_rn(v2, v3);
            } else {
                __half* C = (__half*)CO;
                float a0 = acc[mt][nt][0], a1 = acc[mt][nt][1];
                float a2 = acc[mt][nt][2], a3 = acc[mt][nt][3];
                if (ropef) {
                    int s0 = r0 & (SEQ - 1), s1 = (r0 + 8) & (SEQ - 1);
                    int j  = (cc & 127) >> 1;
                    float sn0 = g_rsin[s0 * 64 + j], cs0 = g_rcos[s0 * 64 + j];
                    float sn1 = g_rsin[s1 * 64 + j], cs1 = g_rcos[s1 * 64 + j];
                    *(__half2*)(C + i0) = __floats2half2_rn(a0 * cs0 - a1 * sn0,
                                                            a0 * sn0 + a1 * cs0);
                    *(__half2*)(C + i1) = __floats2half2_rn(a2 * cs1 - a3 * sn1,
                                                            a2 * sn1 + a3 * cs1);
                } else {
                    *(__half2*)(C + i0) = __floats2half2_rn(a0, a1);
                    *(__half2*)(C + i1) = __floats2half2_rn(a2, a3);
                }
            }
        }
    }
}

template<int EPI>
__global__ __launch_bounds__(256, 2) void gemm_mma(
        const __half* __restrict__ A, const __half* __restrict__ W,
        const void* __restrict__ res, void* __restrict__ CO,
        int M, int N, int K) {
    gemm_body<EPI>(A, W, res, CO, M, N, K, 0);
}

__global__ __launch_bounds__(256, 2) void gemm_qkv(const __half* __restrict__ A) {
    int z = blockIdx.z;
    const __half* W = z == 0 ? g_wq : (z == 1 ? g_wk : g_wv);
    __half* C = z == 0 ? g_qh : (z == 1 ? g_kh : g_vh);
    gemm_body<3>(A, W, nullptr, C, M_TOK, D_MODEL, D_MODEL, z < 2);
}

// ---------------- RMSNorm (writes half) ----------------
__global__ void rmsnorm_kernel(const float* __restrict__ x,
                               const float* __restrict__ g,
                               __half* __restrict__ out) {
    int row = blockIdx.x;
    const float* xr = x + (size_t)row * D_MODEL;
    __half*      orow = out + (size_t)row * D_MODEL;
    float s = 0.f;
    for (int i = threadIdx.x; i < D_MODEL; i += blockDim.x) {
        float v = xr[i]; s += v * v;
    }
    __shared__ float red[32];
    for (int o = 16; o; o >>= 1) s += __shfl_down_sync(0xffffffffu, s, o);
    if ((threadIdx.x & 31) == 0) red[threadIdx.x >> 5] = s;
    __syncthreads();
    if (threadIdx.x < 32) {
        float v = (threadIdx.x < (blockDim.x >> 5)) ? red[threadIdx.x] : 0.f;
        for (int o = 16; o; o >>= 1) v += __shfl_down_sync(0xffffffffu, v, o);
        if (threadIdx.x == 0) red[0] = v;
    }
    __syncthreads();
    float rinv = rsqrtf(red[0] * (1.0f / D_MODEL) + 1e-5f);
    for (int i = threadIdx.x; i < D_MODEL; i += blockDim.x)
        orow[i] = __float2half(xr[i] * g[i] * rinv);
}

// ---------------- RoPE tables (double range-reduce, float sincos) ----------
__global__ void rope_table_kernel() {
    int idx = blockIdx.x * blockDim.x + threadIdx.x;
    if (idx >= SEQ * 64) return;
    int j = idx & 63, s = idx >> 6;
    double inv = exp(-(double)j * (9.210340371976184 / 64.0));
    double ang = fmod((double)s * inv, 6.283185307179586476925286766559);
    float fa = (float)ang;
    g_rsin[idx] = sinf(fa);
    g_rcos[idx] = cosf(fa);
}

// ---------------- fp16 tensor-core flash attention (causal) ----------------
// BQ=128, BK=64, 256 threads (8 warps). P packed directly into A-fragments.
#define QLD 136
#define KLH 136
#define ATT_SMEM ((2*64*KLH + 2*64*KLH) * 2)

__global__ __launch_bounds__(256) void attn_f16(
        const __half* __restrict__ Q,
        const __half* __restrict__ K,
        const __half* __restrict__ V,
        __half* __restrict__ O) {
    extern __shared__ __half smh[];
    __half* Qst = smh;                    // staging, overlaps K stages
    __half* Ksm = smh;                    // 2 x 64 x KLH
    __half* Vsm = Ksm + 2 * 64 * KLH;     // 2 x 64 x KLH

    int tid = threadIdx.x;
    int lane = tid & 31, wid = tid >> 5;
    int qr = lane >> 2, qc = lane & 3;
    int bh = blockIdx.y;
    int b = bh >> 4, h = bh & 15;
    int qblk = gridDim.x - 1 - blockIdx.x;   // heavy-first
    int q0 = qblk * 128;
    int nkb = 2 * qblk + 2;
    int m4 = lane >> 3;
    int r8 = lane & 7;

    // ---- stage Q, extract register A-fragments ----
    for (int i = tid; i < 128 * 16; i += 256) {
        int r = i >> 4, c8 = (i & 15) * 8;
        *(uint4*)(Qst + r * QLD + c8) =
            *(const uint4*)(Q + (size_t)(b * SEQ + q0 + r) * D_MODEL + h * DKH + c8);
    }
    __syncthreads();
    uint32_t afq[8][4];
    {
        uint32_t qb_ = smem_u32(Qst);
        int row = wid * 16 + (m4 & 1) * 8 + r8;
#pragma unroll
        for (int ks = 0; ks < 8; ks++)
            ldsm_x4(afq[ks], qb_ + (uint32_t)(row * QLD + ks * 16 + (m4 >> 1) * 8) * 2);
    }
    __syncthreads();

    uint32_t ks_base = smem_u32(Ksm);
    uint32_t vs_base = smem_u32(Vsm);
    auto issue_kv = [&](int kb, int stg) {
        uint32_t off = (uint32_t)stg * 64 * KLH * 2;
#pragma unroll
        for (int i = 0; i < 4; i++) {
            int idx = tid + i * 256;
            int r = idx >> 4, c8 = (idx & 15) * 8;
            size_t g = (size_t)(b * SEQ + kb * 64 + r) * D_MODEL + h * DKH + c8;
            uint32_t d = (uint32_t)(r * KLH + c8) * 2;
            cp_async16(ks_base + off + d, K + g);
            cp_async16(vs_base + off + d, V + g);
        }
    };

    issue_kv(0, 0); CP_COMMIT();

    float o[16][4] = {};
    float m0 = -1e30f, m1 = -1e30f, l0 = 0.f, l1 = 0.f;
    const float scale = 0.08838834764831845f;

    for (int kb = 0; kb < nkb; kb++) {
        CP_WAIT(0);
        __syncthreads();
        if (kb + 1 < nkb) issue_kv(kb + 1, (kb + 1) & 1);
        CP_COMMIT();
        uint32_t kst = ks_base + (uint32_t)(kb & 1) * 64 * KLH * 2;
        uint32_t vst = vs_base + (uint32_t)(kb & 1) * 64 * KLH * 2;

        // ---- S = Q K^T ----
        float s[8][4] = {};
#pragma unroll
        for (int c2 = 0; c2 < 4; c2++) {
#pragma unroll
            for (int n0 = 0; n0 < 8; n0++) {
                uint32_t kf[4];
                ldsm_x4(kf, kst + (uint32_t)((n0 * 8 + r8) * KLH + c2 * 32 + m4 * 8) * 2);
                mma_f16(s[n0], afq[2 * c2],     kf);
                mma_f16(s[n0], afq[2 * c2 + 1], kf + 2);
            }
        }

        // ---- mask + online softmax ----
        bool diag = (kb >= 2 * qblk);
        int row0 = q0 + wid * 16 + qr, row1 = row0 + 8;
        float mt0 = -1e30f, mt1 = -1e30f;
#pragma unroll
        for (int nt = 0; nt < 8; nt++) {
            int col = kb * 64 + nt * 8 + 2 * qc;
            s[nt][0] *= scale; s[nt][1] *= scale;
            s[nt][2] *= scale; s[nt][3] *= scale;
            if (diag) {
                if (col > row0)     s[nt][0] = -1e30f;
                if (col + 1 > row0) s[nt][1] = -1e30f;
                if (col > row1)     s[nt][2] = -1e30f;
                if (col + 1 > row1) s[nt][3] = -1e30f;
            }
            mt0 = fmaxf(mt0, fmaxf(s[nt][0], s[nt][1]));
            mt1 = fmaxf(mt1, fmaxf(s[nt][2], s[nt][3]));
        }
#pragma unroll
        for (int off = 1; off < 4; off <<= 1) {
            mt0 = fmaxf(mt0, __shfl_xor_sync(0xffffffffu, mt0, off));
            mt1 = fmaxf(mt1, __shfl_xor_sync(0xffffffffu, mt1, off));
        }
        float mn0 = fmaxf(m0, mt0), mn1 = fmaxf(m1, mt1);
        float ls0 = 0.f, ls1 = 0.f;

        // exp -> pack DIRECTLY into A-fragments (S-acc layout == A-frag layout)
        uint32_t afp[4][4];
#pragma unroll
        for (int nt = 0; nt < 8; nt++) {
            uint32_t h01 = f22u(__expf(s[nt][0] - mn0), __expf(s[nt][1] - mn0));
            uint32_t h23 = f22u(__expf(s[nt][2] - mn1), __expf(s[nt][3] - mn1));
            float2 f01 = __half22float2(*(__half2*)&h01);
            float2 f23 = __half22float2(*(__half2*)&h23);
            ls0 += f01.x + f01.y; ls1 += f23.x + f23.y;
            int ks = nt >> 1;
            if ((nt & 1) == 0) { afp[ks][0] = h01; afp[ks][1] = h23; }
            else               { afp[ks][2] = h01; afp[ks][3] = h23; }
        }
#pragma unroll
        for (int off = 1; off < 4; off <<= 1) {
            ls0 += __shfl_xor_sync(0xffffffffu, ls0, off);
            ls1 += __shfl_xor_sync(0xffffffffu, ls1, off);
        }
        float al0 = __expf(m0 - mn0), al1 = __expf(m1 - mn1);
        l0 = l0 * al0 + ls0; l1 = l1 * al1 + ls1;
        m0 = mn0; m1 = mn1;
#pragma unroll
        for (int nt = 0; nt < 16; nt++) {
            o[nt][0] *= al0; o[nt][1] *= al0;
            o[nt][2] *= al1; o[nt][3] *= al1;
        }

        // ---- O += P V ----
#pragma unroll
        for (int ks = 0; ks < 4; ks++) {
#pragma unroll
            for (int g = 0; g < 8; g++) {
                uint32_t vf[4];
                ldsm_x4_t(vf, vst + (uint32_t)((ks * 16 + (m4 & 1) * 8 + r8) * KLH
                                               + g * 16 + (m4 >> 1) * 8) * 2);
                mma_f16(o[2 * g],     afp[ks], vf);
                mma_f16(o[2 * g + 1], afp[ks], vf + 2);
            }
        }
    }

    float i0 = 1.f / l0, i1 = 1.f / l1;
    int r0 = b * SEQ + q0 + wid * 16 + qr;
#pragma unroll
    for (int nt = 0; nt < 16; nt++) {
        int cc = h * DKH + nt * 8 + 2 * qc;
        *(__half2*)(O + (size_t)r0 * D_MODEL + cc) =
            __floats2half2_rn(o[nt][0] * i0, o[nt][1] * i0);
        *(__half2*)(O + (size_t)(r0 + 8) * D_MODEL + cc) =
            __floats2half2_rn(o[nt][2] * i1, o[nt][3] * i1);
    }
}

// ---------------- launch ----------------
extern "C" void kernel_launch(void* const* d_in, const int* in_sizes, int n_in,
                              void* d_out, int out_size) {
    const float* x  = (const float*)d_in[0];
    const float* Wq = (const float*)d_in[1];
    const float* Wk = (const float*)d_in[2];
    const float* Wv = (const float*)d_in[3];
    const float* Wo = (const float*)d_in[4];
    const float* W1 = (const float*)d_in[5];
    const float* W2 = (const float*)d_in[6];
    const float* W3 = (const float*)d_in[7];
    const float* g1 = (const float*)d_in[8];
    const float* g2 = (const float*)d_in[9];
    float* out = (float*)d_out;

    float *xmid;
    __half *xnh, *ctxh, *ffah, *ffh, *qh, *kh, *vh;
    __half *wqh, *wkh, *wvh, *woh, *w1h, *w2h, *w3h;
    cudaGetSymbolAddress((void**)&xmid, g_xmid);
    cudaGetSymbolAddress((void**)&xnh,  g_xn_h);
    cudaGetSymbolAddress((void**)&ctxh, g_ctx_h);
    cudaGetSymbolAddress((void**)&ffah, g_ffa_h);
    cudaGetSymbolAddress((void**)&ffh,  g_ff_h);
    cudaGetSymbolAddress((void**)&qh,   g_qh);
    cudaGetSymbolAddress((void**)&kh,   g_kh);
    cudaGetSymbolAddress((void**)&vh,   g_vh);
    cudaGetSymbolAddress((void**)&wqh,  g_wq);
    cudaGetSymbolAddress((void**)&wkh,  g_wk);
    cudaGetSymbolAddress((void**)&wvh,  g_wv);
    cudaGetSymbolAddress((void**)&woh,  g_wo);
    cudaGetSymbolAddress((void**)&w1h,  g_w1);
    cudaGetSymbolAddress((void**)&w2h,  g_w2);
    cudaGetSymbolAddress((void**)&w3h,  g_w3);

    cudaFuncSetAttribute(gemm_mma<1>, cudaFuncAttributeMaxDynamicSharedMemorySize, GEMM_SMEM);
    cudaFuncSetAttribute(gemm_mma<2>, cudaFuncAttributeMaxDynamicSharedMemorySize, GEMM_SMEM);
    cudaFuncSetAttribute(gemm_mma<3>, cudaFuncAttributeMaxDynamicSharedMemorySize, GEMM_SMEM);
    cudaFuncSetAttribute(gemm_qkv,    cudaFuncAttributeMaxDynamicSharedMemorySize, GEMM_SMEM);
    cudaFuncSetAttribute(attn_f16,    cudaFuncAttributeMaxDynamicSharedMemorySize, ATT_SMEM);

    // ---- side stream for weight conversion (graph-capture fork/join) ----
    cudaStream_t s2;
    cudaStreamCreateWithFlags(&s2, cudaStreamNonBlocking);
    cudaEvent_t evFork, evQKV, evW;
    cudaEventCreateWithFlags(&evFork, cudaEventDisableTiming);
    cudaEventCreateWithFlags(&evQKV,  cudaEventDisableTiming);
    cudaEventCreateWithFlags(&evW,    cudaEventDisableTiming);

    cudaEventRecord(evFork, 0);
    cudaStreamWaitEvent(s2, evFork, 0);

    const int CT = 256;
    int nDM = D_MODEL * D_MODEL / 4, nFF = DFF * D_MODEL / 4;
    f2h_kernel<<<(nDM + CT - 1) / CT, CT, 0, s2>>>((const float4*)Wq, (__half2*)wqh, nDM);
    f2h_kernel<<<(nDM + CT - 1) / CT, CT, 0, s2>>>((const float4*)Wk, (__half2*)wkh, nDM);
    f2h_kernel<<<(nDM + CT - 1) / CT, CT, 0, s2>>>((const float4*)Wv, (__half2*)wvh, nDM);
    rope_table_kernel<<<(SEQ * 64 + 255) / 256, 256, 0, s2>>>();
    cudaEventRecord(evQKV, s2);
    f2h_kernel<<<(nDM + CT - 1) / CT, CT, 0, s2>>>((const float4*)Wo, (__half2*)woh, nDM);
    f2h_kernel<<<(nFF + CT - 1) / CT, CT, 0, s2>>>((const float4*)W1, (__half2*)w1h, nFF);
    f2h_kernel<<<(nFF + CT - 1) / CT, CT, 0, s2>>>((const float4*)W3, (__half2*)w3h, nFF);
    f2h_kernel<<<(nFF + CT - 1) / CT, CT, 0, s2>>>((const float4*)W2, (__half2*)w2h, nFF);
    cudaEventRecord(evW, s2);

    dim3 blk(256);
    rmsnorm_kernel<<<M_TOK, 256>>>(x, g1, xnh);
    cudaStreamWaitEvent(0, evQKV, 0);
    dim3 gq(D_MODEL / GBN, M_TOK / GBM, 3);
    gemm_qkv<<<gq, blk, GEMM_SMEM>>>(xnh);
    dim3 gattn(SEQ / 128, BATCH * NHEAD);
    attn_f16<<<gattn, blk, ATT_SMEM>>>(qh, kh, vh, ctxh);
    cudaStreamWaitEvent(0, evW, 0);
    dim3 gdm(D_MODEL / GBN, M_TOK / GBM);
    gemm_mma<1><<<gdm, blk, GEMM_SMEM>>>(ctxh, woh, x, xmid, M_TOK, D_MODEL, D_MODEL);
    rmsnorm_kernel<<<M_TOK, 256>>>(xmid, g2, xnh);
    dim3 gff(DFF / GBN, M_TOK / GBM);
    gemm_mma<3><<<gff, blk, GEMM_SMEM>>>(xnh, w1h, nullptr, ffah, M_TOK, DFF, D_MODEL);
    gemm_mma<2><<<gff, blk, GEMM_SMEM>>>(xnh, w3h, ffah, ffh, M_TOK, DFF, D_MODEL);
    gemm_mma<1><<<gdm, blk, GEMM_SMEM>>>(ffh, w2h, xmid, out, M_TOK, D_MODEL, DFF);
}

// round 12
// speedup vs baseline: 13.9282x; 1.0405x over previous
#include <cuda_runtime.h>
#include <cuda_fp16.h>
#include <math.h>
#include <stdint.h>

#define D_MODEL 2048
#define NHEAD   16
#define DKH     128
#define DFF     5632
#define SEQ     2048
#define BATCH   2
#define M_TOK   (BATCH*SEQ)   // 4096

// ---------------- scratch ----------------
__device__ float  g_xmid[(size_t)M_TOK*D_MODEL];
__device__ __half g_xn_h [(size_t)M_TOK*D_MODEL];
__device__ __half g_ctx_h[(size_t)M_TOK*D_MODEL];
__device__ __half g_ff_h [(size_t)M_TOK*DFF];
__device__ __half g_qh[(size_t)M_TOK*D_MODEL];
__device__ __half g_kh[(size_t)M_TOK*D_MODEL];
__device__ __half g_vh[(size_t)M_TOK*D_MODEL];
__device__ __half g_wq[(size_t)D_MODEL*D_MODEL];
__device__ __half g_wk[(size_t)D_MODEL*D_MODEL];
__device__ __half g_wv[(size_t)D_MODEL*D_MODEL];
__device__ __half g_wo[(size_t)D_MODEL*D_MODEL];
__device__ __half g_w1[(size_t)DFF*D_MODEL];
__device__ __half g_w2[(size_t)D_MODEL*DFF];
__device__ __half g_w3[(size_t)DFF*D_MODEL];
__device__ float  g_rsin[SEQ*64];
__device__ float  g_rcos[SEQ*64];

// ================= helpers =================
__device__ __forceinline__ void mma_f16(float* d, const uint32_t* a, const uint32_t* b) {
    asm volatile(
        "mma.sync.aligned.m16n8k16.row.col.f32.f16.f16.f32 "
        "{%0,%1,%2,%3}, {%4,%5,%6,%7}, {%8,%9}, {%0,%1,%2,%3};"
        : "+f"(d[0]), "+f"(d[1]), "+f"(d[2]), "+f"(d[3])
        : "r"(a[0]), "r"(a[1]), "r"(a[2]), "r"(a[3]),
          "r"(b[0]), "r"(b[1]));
}
__device__ __forceinline__ uint32_t smem_u32(const void* p) {
    uint32_t a;
    asm("{ .reg .u64 t; cvta.to.shared.u64 t, %1; cvt.u32.u64 %0, t; }"
        : "=r"(a) : "l"(p));
    return a;
}
__device__ __forceinline__ void cp_async16(uint32_t dst, const void* src) {
    asm volatile("cp.async.cg.shared.global [%0], [%1], 16;" :: "r"(dst), "l"(src));
}
#define CP_COMMIT()  asm volatile("cp.async.commit_group;" ::: "memory")
#define CP_WAIT(N)   asm volatile("cp.async.wait_group %0;" :: "n"(N) : "memory")

__device__ __forceinline__ void ldsm_x4(uint32_t* r, uint32_t a) {
    asm volatile("ldmatrix.sync.aligned.m8n8.x4.shared.b16 {%0,%1,%2,%3}, [%4];"
                 : "=r"(r[0]), "=r"(r[1]), "=r"(r[2]), "=r"(r[3]) : "r"(a));
}
__device__ __forceinline__ void ldsm_x4_t(uint32_t* r, uint32_t a) {
    asm volatile("ldmatrix.sync.aligned.m8n8.x4.trans.shared.b16 {%0,%1,%2,%3}, [%4];"
                 : "=r"(r[0]), "=r"(r[1]), "=r"(r[2]), "=r"(r[3]) : "r"(a));
}
__device__ __forceinline__ uint32_t f22u(float a, float b) {
    __half2 h = __floats2half2_rn(a, b);
    return *(uint32_t*)&h;
}

// ---------------- fp32 -> fp16 convert ----------------
__global__ void f2h_kernel(const float4* __restrict__ in, __half2* __restrict__ out, int n4) {
    int i = blockIdx.x * blockDim.x + threadIdx.x;
    if (i >= n4) return;
    float4 v = in[i];
    out[2 * i]     = __floats2half2_rn(v.x, v.y);
    out[2 * i + 1] = __floats2half2_rn(v.z, v.w);
}

// ================= fp16 GEMM, 128x128 tiles, 2 CTAs/SM, 3-stage =============
// EPI 1: fp32 C = res(f32) + acc
// EPI 3: half C = acc, optional RoPE (ropef)
#define GBM 128
#define GBN 128
#define LDH  40
#define LDH2 20
#define GSTG 3
#define GEMM_SMEM (GSTG*(GBM+GBN)*LDH*2)

template<int EPI>
__device__ __forceinline__ void gemm_body(
        const __half* __restrict__ A,
        const __half* __restrict__ W,
        const void* __restrict__ res,
        void* __restrict__ CO,
        int M, int N, int K, int ropef) {
    extern __shared__ char smc[];
    __half* As = (__half*)smc;
    __half* Bs = As + GSTG * GBM * LDH;

    int tid  = threadIdx.x;
    int lane = tid & 31, wid = tid >> 5;
    int wmb = (wid >> 2) * 64, wnb = (wid & 3) * 32;
    int bm = blockIdx.y * GBM, bn = blockIdx.x * GBN;

    uint32_t as_base = smem_u32(As);
    uint32_t bs_base = smem_u32(Bs);

    auto issue_stage = [&](int tile, int stg) {
        uint32_t aoff = (uint32_t)stg * GBM * LDH * 2;
        uint32_t boff = (uint32_t)stg * GBN * LDH * 2;
        const __half* a2 = A + (size_t)bm * K + tile * 32;
        const __half* w2 = W + (size_t)bn * K + tile * 32;
#pragma unroll
        for (int i = 0; i < 2; i++) {
            int idx = tid + i * 256;
            int r = idx >> 2, c = (idx & 3) * 8;
            cp_async16(as_base + aoff + (uint32_t)(r * LDH + c) * 2,
                       a2 + (size_t)r * K + c);
            cp_async16(bs_base + boff + (uint32_t)(r * LDH + c) * 2,
                       w2 + (size_t)r * K + c);
        }
    };

    int nk = K >> 5;
    issue_stage(0, 0); CP_COMMIT();
    issue_stage(1, 1); CP_COMMIT();

    float acc[4][4][4] = {};
    int qr = lane >> 2, qc = lane & 3;

    int stg = 0;
    for (int kt = 0; kt < nk; kt++) {
        CP_WAIT(1);
        __syncthreads();
        const uint32_t* A32 = (const uint32_t*)(As + stg * GBM * LDH);
        const uint32_t* B32 = (const uint32_t*)(Bs + stg * GBN * LDH);
#pragma unroll
        for (int ks = 0; ks < 2; ks++) {
            int cb = ks * 8 + qc;
            uint32_t af[4][4], bf[4][2];
#pragma unroll
            for (int mt = 0; mt < 4; mt++) {
                int r = wmb + mt * 16 + qr;
                af[mt][0] = A32[r * LDH2 + cb];
                af[mt][1] = A32[(r + 8) * LDH2 + cb];
                af[mt][2] = A32[r * LDH2 + cb + 4];
                af[mt][3] = A32[(r + 8) * LDH2 + cb + 4];
            }
#pragma unroll
            for (int nt = 0; nt < 4; nt++) {
                int n = wnb + nt * 8 + qr;
                bf[nt][0] = B32[n * LDH2 + cb];
                bf[nt][1] = B32[n * LDH2 + cb + 4];
            }
#pragma unroll
            for (int mt = 0; mt < 4; mt++)
#pragma unroll
                for (int nt = 0; nt < 4; nt++)
                    mma_f16(acc[mt][nt], af[mt], bf[nt]);
        }
        int nstg = stg + 2; if (nstg >= GSTG) nstg -= GSTG;
        if (kt + 2 < nk) issue_stage(kt + 2, nstg);
        CP_COMMIT();
        stg = stg + 1 == GSTG ? 0 : stg + 1;
    }

#pragma unroll
    for (int mt = 0; mt < 4; mt++) {
        int r0 = bm + wmb + mt * 16 + qr;
#pragma unroll
        for (int nt = 0; nt < 4; nt++) {
            int cc = bn + wnb + nt * 8 + 2 * qc;
            size_t i0 = (size_t)r0 * N + cc;
            size_t i1 = (size_t)(r0 + 8) * N + cc;
            if (EPI == 1) {
                const float* rf = (const float*)res;
                float* C = (float*)CO;
                float2 rr0 = *(const float2*)(rf + i0);
                float2 rr1 = *(const float2*)(rf + i1);
                *(float2*)(C + i0) = make_float2(acc[mt][nt][0] + rr0.x,
                                                 acc[mt][nt][1] + rr0.y);
                *(float2*)(C + i1) = make_float2(acc[mt][nt][2] + rr1.x,
                                                 acc[mt][nt][3] + rr1.y);
            } else {
                __half* C = (__half*)CO;
                float a0 = acc[mt][nt][0], a1 = acc[mt][nt][1];
                float a2 = acc[mt][nt][2], a3 = acc[mt][nt][3];
                if (ropef) {
                    int s0 = r0 & (SEQ - 1), s1 = (r0 + 8) & (SEQ - 1);
                    int j  = (cc & 127) >> 1;
                    float sn0 = g_rsin[s0 * 64 + j], cs0 = g_rcos[s0 * 64 + j];
                    float sn1 = g_rsin[s1 * 64 + j], cs1 = g_rcos[s1 * 64 + j];
                    *(__half2*)(C + i0) = __floats2half2_rn(a0 * cs0 - a1 * sn0,
                                                            a0 * sn0 + a1 * cs0);
                    *(__half2*)(C + i1) = __floats2half2_rn(a2 * cs1 - a3 * sn1,
                                                            a2 * sn1 + a3 * cs1);
                } else {
                    *(__half2*)(C + i0) = __floats2half2_rn(a0, a1);
                    *(__half2*)(C + i1) = __floats2half2_rn(a2, a3);
                }
            }
        }
    }
}

template<int EPI>
__global__ __launch_bounds__(256, 2) void gemm_mma(
        const __half* __restrict__ A, const __half* __restrict__ W,
        const void* __restrict__ res, void* __restrict__ CO,
        int M, int N, int K) {
    gemm_body<EPI>(A, W, res, CO, M, N, K, 0);
}

__global__ __launch_bounds__(256, 2) void gemm_qkv(const __half* __restrict__ A) {
    int z = blockIdx.z;
    const __half* W = z == 0 ? g_wq : (z == 1 ? g_wk : g_wv);
    __half* C = z == 0 ? g_qh : (z == 1 ? g_kh : g_vh);
    gemm_body<3>(A, W, nullptr, C, M_TOK, D_MODEL, D_MODEL, z < 2);
}

// ========== fused W1+W3 GEMM: ff = silu(W1 xn) * (W3 xn), no intermediate ===
// Tile 128(M) x 64(N per weight). 8 warps = 2m x 4n, warp tile 64 x 16/weight.
// smem: A[128] + B1[64] + B3[64] rows -> same footprint as gemm_body.
__global__ __launch_bounds__(256, 2) void gemm_w13(const __half* __restrict__ A,
                                                   __half* __restrict__ FF) {
    extern __shared__ char smc[];
    __half* As  = (__half*)smc;                  // [GSTG][128][LDH]
    __half* B1s = As  + GSTG * 128 * LDH;        // [GSTG][64][LDH]
    __half* B3s = B1s + GSTG * 64 * LDH;         // [GSTG][64][LDH]

    const int K = D_MODEL, N = DFF;
    int tid  = threadIdx.x;
    int lane = tid & 31, wid = tid >> 5;
    int wmb = (wid >> 2) * 64, wnb = (wid & 3) * 16;
    int bm = blockIdx.y * 128, bn = blockIdx.x * 64;

    uint32_t as_base  = smem_u32(As);
    uint32_t b1_base  = smem_u32(B1s);
    uint32_t b3_base  = smem_u32(B3s);

    auto issue_stage = [&](int tile, int stg) {
        uint32_t aoff = (uint32_t)stg * 128 * LDH * 2;
        uint32_t boff = (uint32_t)stg * 64 * LDH * 2;
        const __half* a2 = A    + (size_t)bm * K + tile * 32;
        const __half* w1 = g_w1 + (size_t)bn * K + tile * 32;
        const __half* w3 = g_w3 + (size_t)bn * K + tile * 32;
#pragma unroll
        for (int i = 0; i < 2; i++) {
            int idx = tid + i * 256;
            int r = idx >> 2, c = (idx & 3) * 8;
            cp_async16(as_base + aoff + (uint32_t)(r * LDH + c) * 2,
                       a2 + (size_t)r * K + c);
        }
        {
            int r = tid >> 2, c = (tid & 3) * 8;   // 0..63 rows
            uint32_t d = (uint32_t)(r * LDH + c) * 2;
            cp_async16(b1_base + boff + d, w1 + (size_t)r * K + c);
            cp_async16(b3_base + boff + d, w3 + (size_t)r * K + c);
        }
    };

    int nk = K >> 5;
    issue_stage(0, 0); CP_COMMIT();
    issue_stage(1, 1); CP_COMMIT();

    float acc1[4][2][4] = {}, acc3[4][2][4] = {};
    int qr = lane >> 2, qc = lane & 3;

    int stg = 0;
    for (int kt = 0; kt < nk; kt++) {
        CP_WAIT(1);
        __syncthreads();
        const uint32_t* A32  = (const uint32_t*)(As  + stg * 128 * LDH);
        const uint32_t* B1_32 = (const uint32_t*)(B1s + stg * 64 * LDH);
        const uint32_t* B3_32 = (const uint32_t*)(B3s + stg * 64 * LDH);
#pragma unroll
        for (int ks = 0; ks < 2; ks++) {
            int cb = ks * 8 + qc;
            uint32_t af[4][4], b1f[2][2], b3f[2][2];
#pragma unroll
            for (int mt = 0; mt < 4; mt++) {
                int r = wmb + mt * 16 + qr;
                af[mt][0] = A32[r * LDH2 + cb];
                af[mt][1] = A32[(r + 8) * LDH2 + cb];
                af[mt][2] = A32[r * LDH2 + cb + 4];
                af[mt][3] = A32[(r + 8) * LDH2 + cb + 4];
            }
#pragma unroll
            for (int nt = 0; nt < 2; nt++) {
                int n = wnb + nt * 8 + qr;
                b1f[nt][0] = B1_32[n * LDH2 + cb];
                b1f[nt][1] = B1_32[n * LDH2 + cb + 4];
                b3f[nt][0] = B3_32[n * LDH2 + cb];
                b3f[nt][1] = B3_32[n * LDH2 + cb + 4];
            }
#pragma unroll
            for (int mt = 0; mt < 4; mt++)
#pragma unroll
                for (int nt = 0; nt < 2; nt++) {
                    mma_f16(acc1[mt][nt], af[mt], b1f[nt]);
                    mma_f16(acc3[mt][nt], af[mt], b3f[nt]);
                }
        }
        int nstg = stg + 2; if (nstg >= GSTG) nstg -= GSTG;
        if (kt + 2 < nk) issue_stage(kt + 2, nstg);
        CP_COMMIT();
        stg = stg + 1 == GSTG ? 0 : stg + 1;
    }

#pragma unroll
    for (int mt = 0; mt < 4; mt++) {
        int r0 = bm + wmb + mt * 16 + qr;
#pragma unroll
        for (int nt = 0; nt < 2; nt++) {
            int cc = bn + wnb + nt * 8 + 2 * qc;
            size_t i0 = (size_t)r0 * N + cc;
            size_t i1 = (size_t)(r0 + 8) * N + cc;
            float a0 = acc1[mt][nt][0], a1 = acc1[mt][nt][1];
            float a2 = acc1[mt][nt][2], a3 = acc1[mt][nt][3];
            float v0 = acc3[mt][nt][0] * (a0 / (1.f + __expf(-a0)));
            float v1 = acc3[mt][nt][1] * (a1 / (1.f + __expf(-a1)));
            float v2 = acc3[mt][nt][2] * (a2 / (1.f + __expf(-a2)));
            float v3 = acc3[mt][nt][3] * (a3 / (1.f + __expf(-a3)));
            *(__half2*)(FF + i0) = __floats2half2_rn(v0, v1);
            *(__half2*)(FF + i1) = __floats2half2_rn(v2, v3);
        }
    }
}

// ---------------- RMSNorm (writes half) ----------------
__global__ void rmsnorm_kernel(const float* __restrict__ x,
                               const float* __restrict__ g,
                               __half* __restrict__ out) {
    int row = blockIdx.x;
    const float* xr = x + (size_t)row * D_MODEL;
    __half*      orow = out + (size_t)row * D_MODEL;
    float s = 0.f;
    for (int i = threadIdx.x; i < D_MODEL; i += blockDim.x) {
        float v = xr[i]; s += v * v;
    }
    __shared__ float red[32];
    for (int o = 16; o; o >>= 1) s += __shfl_down_sync(0xffffffffu, s, o);
    if ((threadIdx.x & 31) == 0) red[threadIdx.x >> 5] = s;
    __syncthreads();
    if (threadIdx.x < 32) {
        float v = (threadIdx.x < (blockDim.x >> 5)) ? red[threadIdx.x] : 0.f;
        for (int o = 16; o; o >>= 1) v += __shfl_down_sync(0xffffffffu, v, o);
        if (threadIdx.x == 0) red[0] = v;
    }
    __syncthreads();
    float rinv = rsqrtf(red[0] * (1.0f / D_MODEL) + 1e-5f);
    for (int i = threadIdx.x; i < D_MODEL; i += blockDim.x)
        orow[i] = __float2half(xr[i] * g[i] * rinv);
}

// ---------------- RoPE tables ----------------
__global__ void rope_table_kernel() {
    int idx = blockIdx.x * blockDim.x + threadIdx.x;
    if (idx >= SEQ * 64) return;
    int j = idx & 63, s = idx >> 6;
    double inv = exp(-(double)j * (9.210340371976184 / 64.0));
    double ang = fmod((double)s * inv, 6.283185307179586476925286766559);
    float fa = (float)ang;
    g_rsin[idx] = sinf(fa);
    g_rcos[idx] = cosf(fa);
}

// ---------------- fp16 tensor-core flash attention (causal) ----------------
#define QLD 136
#define KLH 136
#define ATT_SMEM ((2*64*KLH + 2*64*KLH) * 2)

__global__ __launch_bounds__(256) void attn_f16(
        const __half* __restrict__ Q,
        const __half* __restrict__ K,
        const __half* __restrict__ V,
        __half* __restrict__ O) {
    extern __shared__ __half smh[];
    __half* Qst = smh;
    __half* Ksm = smh;
    __half* Vsm = Ksm + 2 * 64 * KLH;

    int tid = threadIdx.x;
    int lane = tid & 31, wid = tid >> 5;
    int qr = lane >> 2, qc = lane & 3;
    int bh = blockIdx.y;
    int b = bh >> 4, h = bh & 15;
    int qblk = gridDim.x - 1 - blockIdx.x;
    int q0 = qblk * 128;
    int nkb = 2 * qblk + 2;
    int m4 = lane >> 3;
    int r8 = lane & 7;

    for (int i = tid; i < 128 * 16; i += 256) {
        int r = i >> 4, c8 = (i & 15) * 8;
        *(uint4*)(Qst + r * QLD + c8) =
            *(const uint4*)(Q + (size_t)(b * SEQ + q0 + r) * D_MODEL + h * DKH + c8);
    }
    __syncthreads();
    uint32_t afq[8][4];
    {
        uint32_t qb_ = smem_u32(Qst);
        int row = wid * 16 + (m4 & 1) * 8 + r8;
#pragma unroll
        for (int ks = 0; ks < 8; ks++)
            ldsm_x4(afq[ks], qb_ + (uint32_t)(row * QLD + ks * 16 + (m4 >> 1) * 8) * 2);
    }
    __syncthreads();

    uint32_t ks_base = smem_u32(Ksm);
    uint32_t vs_base = smem_u32(Vsm);
    auto issue_kv = [&](int kb, int stg) {
        uint32_t off = (uint32_t)stg * 64 * KLH * 2;
#pragma unroll
        for (int i = 0; i < 4; i++) {
            int idx = tid + i * 256;
            int r = idx >> 4, c8 = (idx & 15) * 8;
            size_t g = (size_t)(b * SEQ + kb * 64 + r) * D_MODEL + h * DKH + c8;
            uint32_t d = (uint32_t)(r * KLH + c8) * 2;
            cp_async16(ks_base + off + d, K + g);
            cp_async16(vs_base + off + d, V + g);
        }
    };

    issue_kv(0, 0); CP_COMMIT();

    float o[16][4] = {};
    float m0 = -1e30f, m1 = -1e30f, l0 = 0.f, l1 = 0.f;
    const float scale = 0.08838834764831845f;

    for (int kb = 0; kb < nkb; kb++) {
        CP_WAIT(0);
        __syncthreads();
        if (kb + 1 < nkb) issue_kv(kb + 1, (kb + 1) & 1);
        CP_COMMIT();
        uint32_t kst = ks_base + (uint32_t)(kb & 1) * 64 * KLH * 2;
        uint32_t vst = vs_base + (uint32_t)(kb & 1) * 64 * KLH * 2;

        float s[8][4] = {};
#pragma unroll
        for (int c2 = 0; c2 < 4; c2++) {
#pragma unroll
            for (int n0 = 0; n0 < 8; n0++) {
                uint32_t kf[4];
                ldsm_x4(kf, kst + (uint32_t)((n0 * 8 + r8) * KLH + c2 * 32 + m4 * 8) * 2);
                mma_f16(s[n0], afq[2 * c2],     kf);
                mma_f16(s[n0], afq[2 * c2 + 1], kf + 2);
            }
        }

        bool diag = (kb >= 2 * qblk);
        int row0 = q0 + wid * 16 + qr, row1 = row0 + 8;
        float mt0 = -1e30f, mt1 = -1e30f;
#pragma unroll
        for (int nt = 0; nt < 8; nt++) {
            int col = kb * 64 + nt * 8 + 2 * qc;
            s[nt][0] *= scale; s[nt][1] *= scale;
            s[nt][2] *= scale; s[nt][3] *= scale;
            if (diag) {
                if (col > row0)     s[nt][0] = -1e30f;
                if (col + 1 > row0) s[nt][1] = -1e30f;
                if (col > row1)     s[nt][2] = -1e30f;
                if (col + 1 > row1) s[nt][3] = -1e30f;
            }
            mt0 = fmaxf(mt0, fmaxf(s[nt][0], s[nt][1]));
            mt1 = fmaxf(mt1, fmaxf(s[nt][2], s[nt][3]));
        }
#pragma unroll
        for (int off = 1; off < 4; off <<= 1) {
            mt0 = fmaxf(mt0, __shfl_xor_sync(0xffffffffu, mt0, off));
            mt1 = fmaxf(mt1, __shfl_xor_sync(0xffffffffu, mt1, off));
        }
        float mn0 = fmaxf(m0, mt0), mn1 = fmaxf(m1, mt1);
        float ls0 = 0.f, ls1 = 0.f;

        uint32_t afp[4][4];
#pragma unroll
        for (int nt = 0; nt < 8; nt++) {
            uint32_t h01 = f22u(__expf(s[nt][0] - mn0), __expf(s[nt][1] - mn0));
            uint32_t h23 = f22u(__expf(s[nt][2] - mn1), __expf(s[nt][3] - mn1));
            float2 f01 = __half22float2(*(__half2*)&h01);
            float2 f23 = __half22float2(*(__half2*)&h23);
            ls0 += f01.x + f01.y; ls1 += f23.x + f23.y;
            int ks = nt >> 1;
            if ((nt & 1) == 0) { afp[ks][0] = h01; afp[ks][1] = h23; }
            else               { afp[ks][2] = h01; afp[ks][3] = h23; }
        }
#pragma unroll
        for (int off = 1; off < 4; off <<= 1) {
            ls0 += __shfl_xor_sync(0xffffffffu, ls0, off);
            ls1 += __shfl_xor_sync(0xffffffffu, ls1, off);
        }
        float al0 = __expf(m0 - mn0), al1 = __expf(m1 - mn1);
        l0 = l0 * al0 + ls0; l1 = l1 * al1 + ls1;
        m0 = mn0; m1 = mn1;
#pragma unroll
        for (int nt = 0; nt < 16; nt++) {
            o[nt][0] *= al0; o[nt][1] *= al0;
            o[nt][2] *= al1; o[nt][3] *= al1;
        }

#pragma unroll
        for (int ks = 0; ks < 4; ks++) {
#pragma unroll
            for (int g = 0; g < 8; g++) {
                uint32_t vf[4];
                ldsm_x4_t(vf, vst + (uint32_t)((ks * 16 + (m4 & 1) * 8 + r8) * KLH
                                               + g * 16 + (m4 >> 1) * 8) * 2);
                mma_f16(o[2 * g],     afp[ks], vf);
                mma_f16(o[2 * g + 1], afp[ks], vf + 2);
            }
        }
    }

    float i0 = 1.f / l0, i1 = 1.f / l1;
    int r0 = b * SEQ + q0 + wid * 16 + qr;
#pragma unroll
    for (int nt = 0; nt < 16; nt++) {
        int cc = h * DKH + nt * 8 + 2 * qc;
        *(__half2*)(O + (size_t)r0 * D_MODEL + cc) =
            __floats2half2_rn(o[nt][0] * i0, o[nt][1] * i0);
        *(__half2*)(O + (size_t)(r0 + 8) * D_MODEL + cc) =
            __floats2half2_rn(o[nt][2] * i1, o[nt][3] * i1);
    }
}

// ---------------- launch ----------------
extern "C" void kernel_launch(void* const* d_in, const int* in_sizes, int n_in,
                              void* d_out, int out_size) {
    const float* x  = (const float*)d_in[0];
    const float* Wq = (const float*)d_in[1];
    const float* Wk = (const float*)d_in[2];
    const float* Wv = (const float*)d_in[3];
    const float* Wo = (const float*)d_in[4];
    const float* W1 = (const float*)d_in[5];
    const float* W2 = (const float*)d_in[6];
    const float* W3 = (const float*)d_in[7];
    const float* g1 = (const float*)d_in[8];
    const float* g2 = (const float*)d_in[9];
    float* out = (float*)d_out;

    float *xmid;
    __half *xnh, *ctxh, *ffh, *qh, *kh, *vh;
    __half *wqh, *wkh, *wvh, *woh, *w1h, *w2h, *w3h;
    cudaGetSymbolAddress((void**)&xmid, g_xmid);
    cudaGetSymbolAddress((void**)&xnh,  g_xn_h);
    cudaGetSymbolAddress((void**)&ctxh, g_ctx_h);
    cudaGetSymbolAddress((void**)&ffh,  g_ff_h);
    cudaGetSymbolAddress((void**)&qh,   g_qh);
    cudaGetSymbolAddress((void**)&kh,   g_kh);
    cudaGetSymbolAddress((void**)&vh,   g_vh);
    cudaGetSymbolAddress((void**)&wqh,  g_wq);
    cudaGetSymbolAddress((void**)&wkh,  g_wk);
    cudaGetSymbolAddress((void**)&wvh,  g_wv);
    cudaGetSymbolAddress((void**)&woh,  g_wo);
    cudaGetSymbolAddress((void**)&w1h,  g_w1);
    cudaGetSymbolAddress((void**)&w2h,  g_w2);
    cudaGetSymbolAddress((void**)&w3h,  g_w3);

    cudaFuncSetAttribute(gemm_mma<1>, cudaFuncAttributeMaxDynamicSharedMemorySize, GEMM_SMEM);
    cudaFuncSetAttribute(gemm_mma<3>, cudaFuncAttributeMaxDynamicSharedMemorySize, GEMM_SMEM);
    cudaFuncSetAttribute(gemm_qkv,    cudaFuncAttributeMaxDynamicSharedMemorySize, GEMM_SMEM);
    cudaFuncSetAttribute(gemm_w13,    cudaFuncAttributeMaxDynamicSharedMemorySize, GEMM_SMEM);
    cudaFuncSetAttribute(attn_f16,    cudaFuncAttributeMaxDynamicSharedMemorySize, ATT_SMEM);

    // ---- side stream for weight conversion (graph-capture fork/join) ----
    cudaStream_t s2;
    cudaStreamCreateWithFlags(&s2, cudaStreamNonBlocking);
    cudaEvent_t evFork, evQKV, evW;
    cudaEventCreateWithFlags(&evFork, cudaEventDisableTiming);
    cudaEventCreateWithFlags(&evQKV,  cudaEventDisableTiming);
    cudaEventCreateWithFlags(&evW,    cudaEventDisableTiming);

    cudaEventRecord(evFork, 0);
    cudaStreamWaitEvent(s2, evFork, 0);

    const int CT = 256;
    int nDM = D_MODEL * D_MODEL / 4, nFF = DFF * D_MODEL / 4;
    f2h_kernel<<<(nDM + CT - 1) / CT, CT, 0, s2>>>((const float4*)Wq, (__half2*)wqh, nDM);
    f2h_kernel<<<(nDM + CT - 1) / CT, CT, 0, s2>>>((const float4*)Wk, (__half2*)wkh, nDM);
    f2h_kernel<<<(nDM + CT - 1) / CT, CT, 0, s2>>>((const float4*)Wv, (__half2*)wvh, nDM);
    rope_table_kernel<<<(SEQ * 64 + 255) / 256, 256, 0, s2>>>();
    cudaEventRecord(evQKV, s2);
    f2h_kernel<<<(nDM + CT - 1) / CT, CT, 0, s2>>>((const float4*)Wo, (__half2*)woh, nDM);
    f2h_kernel<<<(nFF + CT - 1) / CT, CT, 0, s2>>>((const float4*)W1, (__half2*)w1h, nFF);
    f2h_kernel<<<(nFF + CT - 1) / CT, CT, 0, s2>>>((const float4*)W3, (__half2*)w3h, nFF);
    f2h_kernel<<<(nFF + CT - 1) / CT, CT, 0, s2>>>((const float4*)W2, (__half2*)w2h, nFF);
    cudaEventRecord(evW, s2);

    dim3 blk(256);
    rmsnorm_kernel<<<M_TOK, 256>>>(x, g1, xnh);
    cudaStreamWaitEvent(0, evQKV, 0);
    dim3 gq(D_MODEL / GBN, M_TOK / GBM, 3);
    gemm_qkv<<<gq, blk, GEMM_SMEM>>>(xnh);
    dim3 gattn(SEQ / 128, BATCH * NHEAD);
    attn_f16<<<gattn, blk, ATT_SMEM>>>(qh, kh, vh, ctxh);
    cudaStreamWaitEvent(0, evW, 0);
    dim3 gdm(D_MODEL / GBN, M_TOK / GBM);
    gemm_mma<1><<<gdm, blk, GEMM_SMEM>>>(ctxh, woh, x, xmid, M_TOK, D_MODEL, D_MODEL);
    rmsnorm_kernel<<<M_TOK, 256>>>(xmid, g2, xnh);
    dim3 gw13(DFF / 64, M_TOK / 128);
    gemm_w13<<<gw13, blk, GEMM_SMEM>>>(xnh, ffh);
    gemm_mma<1><<<gdm, blk, GEMM_SMEM>>>(ffh, w2h, xmid, out, M_TOK, D_MODEL, DFF);
}

// round 13
// speedup vs baseline: 15.6220x; 1.1216x over previous
#include <cuda_runtime.h>
#include <cuda_fp16.h>
#include <math.h>
#include <stdint.h>

#define D_MODEL 2048
#define NHEAD   16
#define DKH     128
#define DFF     5632
#define SEQ     2048
#define BATCH   2
#define M_TOK   (BATCH*SEQ)   // 4096

// ---------------- scratch ----------------
__device__ float  g_xmid[(size_t)M_TOK*D_MODEL];
__device__ __half g_xn_h [(size_t)M_TOK*D_MODEL];
__device__ __half g_ctx_h[(size_t)M_TOK*D_MODEL];
__device__ __half g_ff_h [(size_t)M_TOK*DFF];
__device__ __half g_qh[(size_t)M_TOK*D_MODEL];
__device__ __half g_kh[(size_t)M_TOK*D_MODEL];
__device__ __half g_vh[(size_t)M_TOK*D_MODEL];
__device__ __half g_wq[(size_t)D_MODEL*D_MODEL];
__device__ __half g_wk[(size_t)D_MODEL*D_MODEL];
__device__ __half g_wv[(size_t)D_MODEL*D_MODEL];
__device__ __half g_wo[(size_t)D_MODEL*D_MODEL];
__device__ __half g_w1[(size_t)DFF*D_MODEL];
__device__ __half g_w2[(size_t)D_MODEL*DFF];
__device__ __half g_w3[(size_t)DFF*D_MODEL];
__device__ float  g_rsin[SEQ*64];
__device__ float  g_rcos[SEQ*64];

// ================= helpers =================
__device__ __forceinline__ void mma_f16(float* d, const uint32_t* a, const uint32_t* b) {
    asm volatile(
        "mma.sync.aligned.m16n8k16.row.col.f32.f16.f16.f32 "
        "{%0,%1,%2,%3}, {%4,%5,%6,%7}, {%8,%9}, {%0,%1,%2,%3};"
        : "+f"(d[0]), "+f"(d[1]), "+f"(d[2]), "+f"(d[3])
        : "r"(a[0]), "r"(a[1]), "r"(a[2]), "r"(a[3]),
          "r"(b[0]), "r"(b[1]));
}
__device__ __forceinline__ uint32_t smem_u32(const void* p) {
    uint32_t a;
    asm("{ .reg .u64 t; cvta.to.shared.u64 t, %1; cvt.u32.u64 %0, t; }"
        : "=r"(a) : "l"(p));
    return a;
}
__device__ __forceinline__ void cp_async16(uint32_t dst, const void* src) {
    asm volatile("cp.async.cg.shared.global [%0], [%1], 16;" :: "r"(dst), "l"(src));
}
#define CP_COMMIT()  asm volatile("cp.async.commit_group;" ::: "memory")
#define CP_WAIT(N)   asm volatile("cp.async.wait_group %0;" :: "n"(N) : "memory")

__device__ __forceinline__ void ldsm_x4(uint32_t* r, uint32_t a) {
    asm volatile("ldmatrix.sync.aligned.m8n8.x4.shared.b16 {%0,%1,%2,%3}, [%4];"
                 : "=r"(r[0]), "=r"(r[1]), "=r"(r[2]), "=r"(r[3]) : "r"(a));
}
__device__ __forceinline__ void ldsm_x4_t(uint32_t* r, uint32_t a) {
    asm volatile("ldmatrix.sync.aligned.m8n8.x4.trans.shared.b16 {%0,%1,%2,%3}, [%4];"
                 : "=r"(r[0]), "=r"(r[1]), "=r"(r[2]), "=r"(r[3]) : "r"(a));
}
__device__ __forceinline__ uint32_t f22u(float a, float b) {
    __half2 h = __floats2half2_rn(a, b);
    return *(uint32_t*)&h;
}

// ---------------- fp32 -> fp16 convert ----------------
__global__ void f2h_kernel(const float4* __restrict__ in, __half2* __restrict__ out, int n4) {
    int i = blockIdx.x * blockDim.x + threadIdx.x;
    if (i >= n4) return;
    float4 v = in[i];
    out[2 * i]     = __floats2half2_rn(v.x, v.y);
    out[2 * i + 1] = __floats2half2_rn(v.z, v.w);
}

// ================= fp16 GEMM, 128x128 tiles, 2 CTAs/SM, 3-stage =============
// Fragments via ldmatrix (12 LDSM vs 96 LDS.32 per warp per k-tile).
// EPI 1: fp32 C = res(f32) + acc
// EPI 3: half C = acc, optional RoPE (ropef)
#define GBM 128
#define GBN 128
#define LDH  40
#define GSTG 3
#define GEMM_SMEM (GSTG*(GBM+GBN)*LDH*2)

template<int EPI>
__device__ __forceinline__ void gemm_body(
        const __half* __restrict__ A,
        const __half* __restrict__ W,
        const void* __restrict__ res,
        void* __restrict__ CO,
        int M, int N, int K, int ropef) {
    extern __shared__ char smc[];
    __half* As = (__half*)smc;
    __half* Bs = As + GSTG * GBM * LDH;

    int tid  = threadIdx.x;
    int lane = tid & 31, wid = tid >> 5;
    int wmb = (wid >> 2) * 64, wnb = (wid & 3) * 32;
    int bm = blockIdx.y * GBM, bn = blockIdx.x * GBN;
    int m4 = lane >> 3, r8 = lane & 7;

    uint32_t as_base = smem_u32(As);
    uint32_t bs_base = smem_u32(Bs);

    auto issue_stage = [&](int tile, int stg) {
        uint32_t aoff = (uint32_t)stg * GBM * LDH * 2;
        uint32_t boff = (uint32_t)stg * GBN * LDH * 2;
        const __half* a2 = A + (size_t)bm * K + tile * 32;
        const __half* w2 = W + (size_t)bn * K + tile * 32;
#pragma unroll
        for (int i = 0; i < 2; i++) {
            int idx = tid + i * 256;
            int r = idx >> 2, c = (idx & 3) * 8;
            cp_async16(as_base + aoff + (uint32_t)(r * LDH + c) * 2,
                       a2 + (size_t)r * K + c);
            cp_async16(bs_base + boff + (uint32_t)(r * LDH + c) * 2,
                       w2 + (size_t)r * K + c);
        }
    };

    int nk = K >> 5;
    issue_stage(0, 0); CP_COMMIT();
    issue_stage(1, 1); CP_COMMIT();

    float acc[4][4][4] = {};
    int qr = lane >> 2, qc = lane & 3;

    int stg = 0;
    for (int kt = 0; kt < nk; kt++) {
        CP_WAIT(1);
        __syncthreads();
        uint32_t aS = as_base + (uint32_t)stg * GBM * LDH * 2;
        uint32_t bS = bs_base + (uint32_t)stg * GBN * LDH * 2;

        // B fragments: one ldsm_x4 per 8-n group covers k 0..31
        uint32_t bf4[4][4];
#pragma unroll
        for (int nt = 0; nt < 4; nt++) {
            int n0 = wnb + nt * 8 + r8;
            ldsm_x4(bf4[nt], bS + (uint32_t)(n0 * LDH + m4 * 8) * 2);
        }
#pragma unroll
        for (int ks = 0; ks < 2; ks++) {
            uint32_t af[4][4];
#pragma unroll
            for (int mt = 0; mt < 4; mt++) {
                int r0 = wmb + mt * 16 + (m4 & 1) * 8 + r8;
                ldsm_x4(af[mt], aS + (uint32_t)(r0 * LDH + ks * 16 + (m4 >> 1) * 8) * 2);
            }
#pragma unroll
            for (int mt = 0; mt < 4; mt++)
#pragma unroll
                for (int nt = 0; nt < 4; nt++)
                    mma_f16(acc[mt][nt], af[mt], &bf4[nt][2 * ks]);
        }
        int nstg = stg + 2; if (nstg >= GSTG) nstg -= GSTG;
        if (kt + 2 < nk) issue_stage(kt + 2, nstg);
        CP_COMMIT();
        stg = stg + 1 == GSTG ? 0 : stg + 1;
    }

#pragma unroll
    for (int mt = 0; mt < 4; mt++) {
        int r0 = bm + wmb + mt * 16 + qr;
#pragma unroll
        for (int nt = 0; nt < 4; nt++) {
            int cc = bn + wnb + nt * 8 + 2 * qc;
            size_t i0 = (size_t)r0 * N + cc;
            size_t i1 = (size_t)(r0 + 8) * N + cc;
            if (EPI == 1) {
                const float* rf = (const float*)res;
                float* C = (float*)CO;
                float2 rr0 = *(const float2*)(rf + i0);
                float2 rr1 = *(const float2*)(rf + i1);
                *(float2*)(C + i0) = make_float2(acc[mt][nt][0] + rr0.x,
                                                 acc[mt][nt][1] + rr0.y);
                *(float2*)(C + i1) = make_float2(acc[mt][nt][2] + rr1.x,
                                                 acc[mt][nt][3] + rr1.y);
            } else {
                __half* C = (__half*)CO;
                float a0 = acc[mt][nt][0], a1 = acc[mt][nt][1];
                float a2 = acc[mt][nt][2], a3 = acc[mt][nt][3];
                if (ropef) {
                    int s0 = r0 & (SEQ - 1), s1 = (r0 + 8) & (SEQ - 1);
                    int j  = (cc & 127) >> 1;
                    float sn0 = g_rsin[s0 * 64 + j], cs0 = g_rcos[s0 * 64 + j];
                    float sn1 = g_rsin[s1 * 64 + j], cs1 = g_rcos[s1 * 64 + j];
                    *(__half2*)(C + i0) = __floats2half2_rn(a0 * cs0 - a1 * sn0,
                                                            a0 * sn0 + a1 * cs0);
                    *(__half2*)(C + i1) = __floats2half2_rn(a2 * cs1 - a3 * sn1,
                                                            a2 * sn1 + a3 * cs1);
                } else {
                    *(__half2*)(C + i0) = __floats2half2_rn(a0, a1);
                    *(__half2*)(C + i1) = __floats2half2_rn(a2, a3);
                }
            }
        }
    }
}

template<int EPI>
__global__ __launch_bounds__(256, 2) void gemm_mma(
        const __half* __restrict__ A, const __half* __restrict__ W,
        const void* __restrict__ res, void* __restrict__ CO,
        int M, int N, int K) {
    gemm_body<EPI>(A, W, res, CO, M, N, K, 0);
}

__global__ __launch_bounds__(256, 2) void gemm_qkv(const __half* __restrict__ A) {
    int z = blockIdx.z;
    const __half* W = z == 0 ? g_wq : (z == 1 ? g_wk : g_wv);
    __half* C = z == 0 ? g_qh : (z == 1 ? g_kh : g_vh);
    gemm_body<3>(A, W, nullptr, C, M_TOK, D_MODEL, D_MODEL, z < 2);
}

// ========== fused W1+W3 GEMM: ff = silu(W1 xn) * (W3 xn) ====================
__global__ __launch_bounds__(256, 2) void gemm_w13(const __half* __restrict__ A,
                                                   __half* __restrict__ FF) {
    extern __shared__ char smc[];
    __half* As  = (__half*)smc;                  // [GSTG][128][LDH]
    __half* B1s = As  + GSTG * 128 * LDH;        // [GSTG][64][LDH]
    __half* B3s = B1s + GSTG * 64 * LDH;         // [GSTG][64][LDH]

    const int K = D_MODEL, N = DFF;
    int tid  = threadIdx.x;
    int lane = tid & 31, wid = tid >> 5;
    int wmb = (wid >> 2) * 64, wnb = (wid & 3) * 16;
    int bm = blockIdx.y * 128, bn = blockIdx.x * 64;
    int m4 = lane >> 3, r8 = lane & 7;

    uint32_t as_base  = smem_u32(As);
    uint32_t b1_base  = smem_u32(B1s);
    uint32_t b3_base  = smem_u32(B3s);

    auto issue_stage = [&](int tile, int stg) {
        uint32_t aoff = (uint32_t)stg * 128 * LDH * 2;
        uint32_t boff = (uint32_t)stg * 64 * LDH * 2;
        const __half* a2 = A    + (size_t)bm * K + tile * 32;
        const __half* w1 = g_w1 + (size_t)bn * K + tile * 32;
        const __half* w3 = g_w3 + (size_t)bn * K + tile * 32;
#pragma unroll
        for (int i = 0; i < 2; i++) {
            int idx = tid + i * 256;
            int r = idx >> 2, c = (idx & 3) * 8;
            cp_async16(as_base + aoff + (uint32_t)(r * LDH + c) * 2,
                       a2 + (size_t)r * K + c);
        }
        {
            int r = tid >> 2, c = (tid & 3) * 8;
            uint32_t d = (uint32_t)(r * LDH + c) * 2;
            cp_async16(b1_base + boff + d, w1 + (size_t)r * K + c);
            cp_async16(b3_base + boff + d, w3 + (size_t)r * K + c);
        }
    };

    int nk = K >> 5;
    issue_stage(0, 0); CP_COMMIT();
    issue_stage(1, 1); CP_COMMIT();

    float acc1[4][2][4] = {}, acc3[4][2][4] = {};
    int qr = lane >> 2, qc = lane & 3;

    int stg = 0;
    for (int kt = 0; kt < nk; kt++) {
        CP_WAIT(1);
        __syncthreads();
        uint32_t aS  = as_base + (uint32_t)stg * 128 * LDH * 2;
        uint32_t b1S = b1_base + (uint32_t)stg * 64 * LDH * 2;
        uint32_t b3S = b3_base + (uint32_t)stg * 64 * LDH * 2;

        uint32_t b1f4[2][4], b3f4[2][4];
#pragma unroll
        for (int nt = 0; nt < 2; nt++) {
            int n0 = wnb + nt * 8 + r8;
            ldsm_x4(b1f4[nt], b1S + (uint32_t)(n0 * LDH + m4 * 8) * 2);
            ldsm_x4(b3f4[nt], b3S + (uint32_t)(n0 * LDH + m4 * 8) * 2);
        }
#pragma unroll
        for (int ks = 0; ks < 2; ks++) {
            uint32_t af[4][4];
#pragma unroll
            for (int mt = 0; mt < 4; mt++) {
                int r0 = wmb + mt * 16 + (m4 & 1) * 8 + r8;
                ldsm_x4(af[mt], aS + (uint32_t)(r0 * LDH + ks * 16 + (m4 >> 1) * 8) * 2);
            }
#pragma unroll
            for (int mt = 0; mt < 4; mt++)
#pragma unroll
                for (int nt = 0; nt < 2; nt++) {
                    mma_f16(acc1[mt][nt], af[mt], &b1f4[nt][2 * ks]);
                    mma_f16(acc3[mt][nt], af[mt], &b3f4[nt][2 * ks]);
                }
        }
        int nstg = stg + 2; if (nstg >= GSTG) nstg -= GSTG;
        if (kt + 2 < nk) issue_stage(kt + 2, nstg);
        CP_COMMIT();
        stg = stg + 1 == GSTG ? 0 : stg + 1;
    }

#pragma unroll
    for (int mt = 0; mt < 4; mt++) {
        int r0 = bm + wmb + mt * 16 + qr;
#pragma unroll
        for (int nt = 0; nt < 2; nt++) {
            int cc = bn + wnb + nt * 8 + 2 * qc;
            size_t i0 = (size_t)r0 * N + cc;
            size_t i1 = (size_t)(r0 + 8) * N + cc;
            float a0 = acc1[mt][nt][0], a1 = acc1[mt][nt][1];
            float a2 = acc1[mt][nt][2], a3 = acc1[mt][nt][3];
            float v0 = acc3[mt][nt][0] * (a0 / (1.f + __expf(-a0)));
            float v1 = acc3[mt][nt][1] * (a1 / (1.f + __expf(-a1)));
            float v2 = acc3[mt][nt][2] * (a2 / (1.f + __expf(-a2)));
            float v3 = acc3[mt][nt][3] * (a3 / (1.f + __expf(-a3)));
            *(__half2*)(FF + i0) = __floats2half2_rn(v0, v1);
            *(__half2*)(FF + i1) = __floats2half2_rn(v2, v3);
        }
    }
}

// ---------------- RMSNorm (float4 loads, writes half) ----------------
__global__ void rmsnorm_kernel(const float* __restrict__ x,
                               const float* __restrict__ g,
                               __half* __restrict__ out) {
    int row = blockIdx.x;
    const float4* xr = (const float4*)(x + (size_t)row * D_MODEL);
    float4 v[2];
    v[0] = xr[threadIdx.x];
    v[1] = xr[threadIdx.x + 256];
    float s = v[0].x*v[0].x + v[0].y*v[0].y + v[0].z*v[0].z + v[0].w*v[0].w
            + v[1].x*v[1].x + v[1].y*v[1].y + v[1].z*v[1].z + v[1].w*v[1].w;
    __shared__ float red[32];
    for (int o = 16; o; o >>= 1) s += __shfl_down_sync(0xffffffffu, s, o);
    if ((threadIdx.x & 31) == 0) red[threadIdx.x >> 5] = s;
    __syncthreads();
    if (threadIdx.x < 32) {
        float t = (threadIdx.x < 8) ? red[threadIdx.x] : 0.f;
        for (int o = 4; o; o >>= 1) t += __shfl_down_sync(0xffffffffu, t, o);
        if (threadIdx.x == 0) red[0] = t;
    }
    __syncthreads();
    float rinv = rsqrtf(red[0] * (1.0f / D_MODEL) + 1e-5f);
    __half2* orow = (__half2*)(out + (size_t)row * D_MODEL);
    const float4* g4 = (const float4*)g;
#pragma unroll
    for (int i = 0; i < 2; i++) {
        float4 gv = g4[threadIdx.x + i * 256];
        orow[(threadIdx.x + i * 256) * 2]     =
            __floats2half2_rn(v[i].x * gv.x * rinv, v[i].y * gv.y * rinv);
        orow[(threadIdx.x + i * 256) * 2 + 1] =
            __floats2half2_rn(v[i].z * gv.z * rinv, v[i].w * gv.w * rinv);
    }
}

// ---------------- RoPE tables ----------------
__global__ void rope_table_kernel() {
    int idx = blockIdx.x * blockDim.x + threadIdx.x;
    if (idx >= SEQ * 64) return;
    int j = idx & 63, s = idx >> 6;
    double inv = exp(-(double)j * (9.210340371976184 / 64.0));
    double ang = fmod((double)s * inv, 6.283185307179586476925286766559);
    float fa = (float)ang;
    g_rsin[idx] = sinf(fa);
    g_rcos[idx] = cosf(fa);
}

// ---------------- fp16 tensor-core flash attention (causal) ----------------
#define QLD 136
#define KLH 136
#define ATT_SMEM ((2*64*KLH + 2*64*KLH) * 2)

__global__ __launch_bounds__(256) void attn_f16(
        const __half* __restrict__ Q,
        const __half* __restrict__ K,
        const __half* __restrict__ V,
        __half* __restrict__ O) {
    extern __shared__ __half smh[];
    __half* Qst = smh;
    __half* Ksm = smh;
    __half* Vsm = Ksm + 2 * 64 * KLH;

    int tid = threadIdx.x;
    int lane = tid & 31, wid = tid >> 5;
    int qr = lane >> 2, qc = lane & 3;
    int bh = blockIdx.y;
    int b = bh >> 4, h = bh & 15;
    int qblk = gridDim.x - 1 - blockIdx.x;
    int q0 = qblk * 128;
    int nkb = 2 * qblk + 2;
    int m4 = lane >> 3;
    int r8 = lane & 7;

    for (int i = tid; i < 128 * 16; i += 256) {
        int r = i >> 4, c8 = (i & 15) * 8;
        *(uint4*)(Qst + r * QLD + c8) =
            *(const uint4*)(Q + (size_t)(b * SEQ + q0 + r) * D_MODEL + h * DKH + c8);
    }
    __syncthreads();
    uint32_t afq[8][4];
    {
        uint32_t qb_ = smem_u32(Qst);
        int row = wid * 16 + (m4 & 1) * 8 + r8;
#pragma unroll
        for (int ks = 0; ks < 8; ks++)
            ldsm_x4(afq[ks], qb_ + (uint32_t)(row * QLD + ks * 16 + (m4 >> 1) * 8) * 2);
    }
    __syncthreads();

    uint32_t ks_base = smem_u32(Ksm);
    uint32_t vs_base = smem_u32(Vsm);
    auto issue_kv = [&](int kb, int stg) {
        uint32_t off = (uint32_t)stg * 64 * KLH * 2;
#pragma unroll
        for (int i = 0; i < 4; i++) {
            int idx = tid + i * 256;
            int r = idx >> 4, c8 = (idx & 15) * 8;
            size_t g = (size_t)(b * SEQ + kb * 64 + r) * D_MODEL + h * DKH + c8;
            uint32_t d = (uint32_t)(r * KLH + c8) * 2;
            cp_async16(ks_base + off + d, K + g);
            cp_async16(vs_base + off + d, V + g);
        }
    };

    issue_kv(0, 0); CP_COMMIT();

    float o[16][4] = {};
    float m0 = -1e30f, m1 = -1e30f, l0 = 0.f, l1 = 0.f;
    const float scale = 0.08838834764831845f;

    for (int kb = 0; kb < nkb; kb++) {
        CP_WAIT(0);
        __syncthreads();
        if (kb + 1 < nkb) issue_kv(kb + 1, (kb + 1) & 1);
        CP_COMMIT();
        uint32_t kst = ks_base + (uint32_t)(kb & 1) * 64 * KLH * 2;
        uint32_t vst = vs_base + (uint32_t)(kb & 1) * 64 * KLH * 2;

        float s[8][4] = {};
#pragma unroll
        for (int c2 = 0; c2 < 4; c2++) {
#pragma unroll
            for (int n0 = 0; n0 < 8; n0++) {
                uint32_t kf[4];
                ldsm_x4(kf, kst + (uint32_t)((n0 * 8 + r8) * KLH + c2 * 32 + m4 * 8) * 2);
                mma_f16(s[n0], afq[2 * c2],     kf);
                mma_f16(s[n0], afq[2 * c2 + 1], kf + 2);
            }
        }

        bool diag = (kb >= 2 * qblk);
        int row0 = q0 + wid * 16 + qr, row1 = row0 + 8;
        float mt0 = -1e30f, mt1 = -1e30f;
#pragma unroll
        for (int nt = 0; nt < 8; nt++) {
            int col = kb * 64 + nt * 8 + 2 * qc;
            s[nt][0] *= scale; s[nt][1] *= scale;
            s[nt][2] *= scale; s[nt][3] *= scale;
            if (diag) {
                if (col > row0)     s[nt][0] = -1e30f;
                if (col + 1 > row0) s[nt][1] = -1e30f;
                if (col > row1)     s[nt][2] = -1e30f;
                if (col + 1 > row1) s[nt][3] = -1e30f;
            }
            mt0 = fmaxf(mt0, fmaxf(s[nt][0], s[nt][1]));
            mt1 = fmaxf(mt1, fmaxf(s[nt][2], s[nt][3]));
        }
#pragma unroll
        for (int off = 1; off < 4; off <<= 1) {
            mt0 = fmaxf(mt0, __shfl_xor_sync(0xffffffffu, mt0, off));
            mt1 = fmaxf(mt1, __shfl_xor_sync(0xffffffffu, mt1, off));
        }
        float mn0 = fmaxf(m0, mt0), mn1 = fmaxf(m1, mt1);
        float ls0 = 0.f, ls1 = 0.f;

        uint32_t afp[4][4];
#pragma unroll
        for (int nt = 0; nt < 8; nt++) {
            uint32_t h01 = f22u(__expf(s[nt][0] - mn0), __expf(s[nt][1] - mn0));
            uint32_t h23 = f22u(__expf(s[nt][2] - mn1), __expf(s[nt][3] - mn1));
            float2 f01 = __half22float2(*(__half2*)&h01);
            float2 f23 = __half22float2(*(__half2*)&h23);
            ls0 += f01.x + f01.y; ls1 += f23.x + f23.y;
            int ks = nt >> 1;
            if ((nt & 1) == 0) { afp[ks][0] = h01; afp[ks][1] = h23; }
            else               { afp[ks][2] = h01; afp[ks][3] = h23; }
        }
#pragma unroll
        for (int off = 1; off < 4; off <<= 1) {
            ls0 += __shfl_xor_sync(0xffffffffu, ls0, off);
            ls1 += __shfl_xor_sync(0xffffffffu, ls1, off);
        }
        float al0 = __expf(m0 - mn0), al1 = __expf(m1 - mn1);
        l0 = l0 * al0 + ls0; l1 = l1 * al1 + ls1;
        m0 = mn0; m1 = mn1;
#pragma unroll
        for (int nt = 0; nt < 16; nt++) {
            o[nt][0] *= al0; o[nt][1] *= al0;
            o[nt][2] *= al1; o[nt][3] *= al1;
        }

#pragma unroll
        for (int ks = 0; ks < 4; ks++) {
#pragma unroll
            for (int g = 0; g < 8; g++) {
                uint32_t vf[4];
                ldsm_x4_t(vf, vst + (uint32_t)((ks * 16 + (m4 & 1) * 8 + r8) * KLH
                                               + g * 16 + (m4 >> 1) * 8) * 2);
                mma_f16(o[2 * g],     afp[ks], vf);
                mma_f16(o[2 * g + 1], afp[ks], vf + 2);
            }
        }
    }

    float i0 = 1.f / l0, i1 = 1.f / l1;
    int r0 = b * SEQ + q0 + wid * 16 + qr;
#pragma unroll
    for (int nt = 0; nt < 16; nt++) {
        int cc = h * DKH + nt * 8 + 2 * qc;
        *(__half2*)(O + (size_t)r0 * D_MODEL + cc) =
            __floats2half2_rn(o[nt][0] * i0, o[nt][1] * i0);
        *(__half2*)(O + (size_t)(r0 + 8) * D_MODEL + cc) =
            __floats2half2_rn(o[nt][2] * i1, o[nt][3] * i1);
    }
}

// ---------------- launch ----------------
extern "C" void kernel_launch(void* const* d_in, const int* in_sizes, int n_in,
                              void* d_out, int out_size) {
    const float* x  = (const float*)d_in[0];
    const float* Wq = (const float*)d_in[1];
    const float* Wk = (const float*)d_in[2];
    const float* Wv = (const float*)d_in[3];
    const float* Wo = (const float*)d_in[4];
    const float* W1 = (const float*)d_in[5];
    const float* W2 = (const float*)d_in[6];
    const float* W3 = (const float*)d_in[7];
    const float* g1 = (const float*)d_in[8];
    const float* g2 = (const float*)d_in[9];
    float* out = (float*)d_out;

    float *xmid;
    __half *xnh, *ctxh, *ffh, *qh, *kh, *vh;
    __half *wqh, *wkh, *wvh, *woh, *w1h, *w2h, *w3h;
    cudaGetSymbolAddress((void**)&xmid, g_xmid);
    cudaGetSymbolAddress((void**)&xnh,  g_xn_h);
    cudaGetSymbolAddress((void**)&ctxh, g_ctx_h);
    cudaGetSymbolAddress((void**)&ffh,  g_ff_h);
    cudaGetSymbolAddress((void**)&qh,   g_qh);
    cudaGetSymbolAddress((void**)&kh,   g_kh);
    cudaGetSymbolAddress((void**)&vh,   g_vh);
    cudaGetSymbolAddress((void**)&wqh,  g_wq);
    cudaGetSymbolAddress((void**)&wkh,  g_wk);
    cudaGetSymbolAddress((void**)&wvh,  g_wv);
    cudaGetSymbolAddress((void**)&woh,  g_wo);
    cudaGetSymbolAddress((void**)&w1h,  g_w1);
    cudaGetSymbolAddress((void**)&w2h,  g_w2);
    cudaGetSymbolAddress((void**)&w3h,  g_w3);

    cudaFuncSetAttribute(gemm_mma<1>, cudaFuncAttributeMaxDynamicSharedMemorySize, GEMM_SMEM);
    cudaFuncSetAttribute(gemm_mma<3>, cudaFuncAttributeMaxDynamicSharedMemorySize, GEMM_SMEM);
    cudaFuncSetAttribute(gemm_qkv,    cudaFuncAttributeMaxDynamicSharedMemorySize, GEMM_SMEM);
    cudaFuncSetAttribute(gemm_w13,    cudaFuncAttributeMaxDynamicSharedMemorySize, GEMM_SMEM);
    cudaFuncSetAttribute(attn_f16,    cudaFuncAttributeMaxDynamicSharedMemorySize, ATT_SMEM);

    // ---- side stream for weight conversion (graph-capture fork/join) ----
    cudaStream_t s2;
    cudaStreamCreateWithFlags(&s2, cudaStreamNonBlocking);
    cudaEvent_t evFork, evQKV, evW;
    cudaEventCreateWithFlags(&evFork, cudaEventDisableTiming);
    cudaEventCreateWithFlags(&evQKV,  cudaEventDisableTiming);
    cudaEventCreateWithFlags(&evW,    cudaEventDisableTiming);

    cudaEventRecord(evFork, 0);
    cudaStreamWaitEvent(s2, evFork, 0);

    const int CT = 256;
    int nDM = D_MODEL * D_MODEL / 4, nFF = DFF * D_MODEL / 4;
    f2h_kernel<<<(nDM + CT - 1) / CT, CT, 0, s2>>>((const float4*)Wq, (__half2*)wqh, nDM);
    f2h_kernel<<<(nDM + CT - 1) / CT, CT, 0, s2>>>((const float4*)Wk, (__half2*)wkh, nDM);
    f2h_kernel<<<(nDM + CT - 1) / CT, CT, 0, s2>>>((const float4*)Wv, (__half2*)wvh, nDM);
    rope_table_kernel<<<(SEQ * 64 + 255) / 256, 256, 0, s2>>>();
    cudaEventRecord(evQKV, s2);
    f2h_kernel<<<(nDM + CT - 1) / CT, CT, 0, s2>>>((const float4*)Wo, (__half2*)woh, nDM);
    f2h_kernel<<<(nFF + CT - 1) / CT, CT, 0, s2>>>((const float4*)W1, (__half2*)w1h, nFF);
    f2h_kernel<<<(nFF + CT - 1) / CT, CT, 0, s2>>>((const float4*)W3, (__half2*)w3h, nFF);
    f2h_kernel<<<(nFF + CT - 1) / CT, CT, 0, s2>>>((const float4*)W2, (__half2*)w2h, nFF);
    cudaEventRecord(evW, s2);

    dim3 blk(256);
    rmsnorm_kernel<<<M_TOK, 256>>>(x, g1, xnh);
    cudaStreamWaitEvent(0, evQKV, 0);
    dim3 gq(D_MODEL / GBN, M_TOK / GBM, 3);
    gemm_qkv<<<gq, blk, GEMM_SMEM>>>(xnh);
    dim3 gattn(SEQ / 128, BATCH * NHEAD);
    attn_f16<<<gattn, blk, ATT_SMEM>>>(qh, kh, vh, ctxh);
    cudaStreamWaitEvent(0, evW, 0);
    dim3 gdm(D_MODEL / GBN, M_TOK / GBM);
    gemm_mma<1><<<gdm, blk, GEMM_SMEM>>>(ctxh, woh, x, xmid, M_TOK, D_MODEL, D_MODEL);
    rmsnorm_kernel<<<M_TOK, 256>>>(xmid, g2, xnh);
    dim3 gw13(DFF / 64, M_TOK / 128);
    gemm_w13<<<gw13, blk, GEMM_SMEM>>>(xnh, ffh);
    gemm_mma<1><<<gdm, blk, GEMM_SMEM>>>(ffh, w2h, xmid, out, M_TOK, D_MODEL, DFF);
}

// round 14
// speedup vs baseline: 16.6720x; 1.0672x over previous
#include <cuda_runtime.h>
#include <cuda_fp16.h>
#include <math.h>
#include <stdint.h>

#define D_MODEL 2048
#define NHEAD   16
#define DKH     128
#define DFF     5632
#define SEQ     2048
#define BATCH   2
#define M_TOK   (BATCH*SEQ)   // 4096

// ---------------- scratch ----------------
__device__ float  g_xmid[(size_t)M_TOK*D_MODEL];
__device__ __half g_xn_h [(size_t)M_TOK*D_MODEL];
__device__ __half g_ctx_h[(size_t)M_TOK*D_MODEL];
__device__ __half g_ff_h [(size_t)M_TOK*DFF];
__device__ __half g_qh[(size_t)M_TOK*D_MODEL];
__device__ __half g_kh[(size_t)M_TOK*D_MODEL];
__device__ __half g_vh[(size_t)M_TOK*D_MODEL];
__device__ __half g_wq[(size_t)D_MODEL*D_MODEL];
__device__ __half g_wk[(size_t)D_MODEL*D_MODEL];
__device__ __half g_wv[(size_t)D_MODEL*D_MODEL];
__device__ __half g_wo[(size_t)D_MODEL*D_MODEL];
__device__ __half g_w1[(size_t)DFF*D_MODEL];
__device__ __half g_w2[(size_t)D_MODEL*DFF];
__device__ __half g_w3[(size_t)DFF*D_MODEL];
__device__ float  g_rsin[SEQ*64];
__device__ float  g_rcos[SEQ*64];

// ================= helpers =================
__device__ __forceinline__ void mma_f16(float* d, const uint32_t* a, const uint32_t* b) {
    asm volatile(
        "mma.sync.aligned.m16n8k16.row.col.f32.f16.f16.f32 "
        "{%0,%1,%2,%3}, {%4,%5,%6,%7}, {%8,%9}, {%0,%1,%2,%3};"
        : "+f"(d[0]), "+f"(d[1]), "+f"(d[2]), "+f"(d[3])
        : "r"(a[0]), "r"(a[1]), "r"(a[2]), "r"(a[3]),
          "r"(b[0]), "r"(b[1]));
}
__device__ __forceinline__ uint32_t smem_u32(const void* p) {
    uint32_t a;
    asm("{ .reg .u64 t; cvta.to.shared.u64 t, %1; cvt.u32.u64 %0, t; }"
        : "=r"(a) : "l"(p));
    return a;
}
__device__ __forceinline__ void cp_async16(uint32_t dst, const void* src) {
    asm volatile("cp.async.cg.shared.global [%0], [%1], 16;" :: "r"(dst), "l"(src));
}
#define CP_COMMIT()  asm volatile("cp.async.commit_group;" ::: "memory")
#define CP_WAIT(N)   asm volatile("cp.async.wait_group %0;" :: "n"(N) : "memory")

__device__ __forceinline__ void ldsm_x4(uint32_t* r, uint32_t a) {
    asm volatile("ldmatrix.sync.aligned.m8n8.x4.shared.b16 {%0,%1,%2,%3}, [%4];"
                 : "=r"(r[0]), "=r"(r[1]), "=r"(r[2]), "=r"(r[3]) : "r"(a));
}
__device__ __forceinline__ void ldsm_x4_t(uint32_t* r, uint32_t a) {
    asm volatile("ldmatrix.sync.aligned.m8n8.x4.trans.shared.b16 {%0,%1,%2,%3}, [%4];"
                 : "=r"(r[0]), "=r"(r[1]), "=r"(r[2]), "=r"(r[3]) : "r"(a));
}
__device__ __forceinline__ uint32_t f22u(float a, float b) {
    __half2 h = __floats2half2_rn(a, b);
    return *(uint32_t*)&h;
}

// ---------------- fp32 -> fp16 convert ----------------
__global__ void f2h_kernel(const float4* __restrict__ in, __half2* __restrict__ out, int n4) {
    int i = blockIdx.x * blockDim.x + threadIdx.x;
    if (i >= n4) return;
    float4 v = in[i];
    out[2 * i]     = __floats2half2_rn(v.x, v.y);
    out[2 * i + 1] = __floats2half2_rn(v.z, v.w);
}

// ================= fp16 GEMM, 128x128 tiles, BK=64, 3-stage, 2 CTAs/SM ======
// Fragments via ldmatrix; B loaded in two k-halves to limit live registers.
// EPI 1: fp32 C = res(f32) + acc
// EPI 3: half C = acc, optional RoPE (ropef)
#define GBM 128
#define GBN 128
#define LDH  72            // halfs per smem row (64 + 8 pad)
#define GSTG 3
#define GEMM_SMEM (GSTG*(GBM+GBN)*LDH*2)

template<int EPI>
__device__ __forceinline__ void gemm_body(
        const __half* __restrict__ A,
        const __half* __restrict__ W,
        const void* __restrict__ res,
        void* __restrict__ CO,
        int M, int N, int K, int ropef) {
    extern __shared__ char smc[];
    __half* As = (__half*)smc;
    __half* Bs = As + GSTG * GBM * LDH;

    int tid  = threadIdx.x;
    int lane = tid & 31, wid = tid >> 5;
    int wmb = (wid >> 2) * 64, wnb = (wid & 3) * 32;
    int bm = blockIdx.y * GBM, bn = blockIdx.x * GBN;
    int m4 = lane >> 3, r8 = lane & 7;

    uint32_t as_base = smem_u32(As);
    uint32_t bs_base = smem_u32(Bs);

    auto issue_stage = [&](int tile, int stg) {
        uint32_t aoff = (uint32_t)stg * GBM * LDH * 2;
        uint32_t boff = (uint32_t)stg * GBN * LDH * 2;
        const __half* a2 = A + (size_t)bm * K + tile * 64;
        const __half* w2 = W + (size_t)bn * K + tile * 64;
#pragma unroll
        for (int i = 0; i < 4; i++) {
            int idx = tid + i * 256;            // 0..1023
            int r = idx >> 3, c = (idx & 7) * 8;
            cp_async16(as_base + aoff + (uint32_t)(r * LDH + c) * 2,
                       a2 + (size_t)r * K + c);
            cp_async16(bs_base + boff + (uint32_t)(r * LDH + c) * 2,
                       w2 + (size_t)r * K + c);
        }
    };

    int nk = K >> 6;
    issue_stage(0, 0); CP_COMMIT();
    issue_stage(1, 1); CP_COMMIT();

    float acc[4][4][4] = {};
    int qr = lane >> 2, qc = lane & 3;

    int stg = 0;
    for (int kt = 0; kt < nk; kt++) {
        CP_WAIT(1);
        __syncthreads();
        uint32_t aS = as_base + (uint32_t)stg * GBM * LDH * 2;
        uint32_t bS = bs_base + (uint32_t)stg * GBN * LDH * 2;

#pragma unroll
        for (int kh = 0; kh < 2; kh++) {
            uint32_t bf[4][4];
#pragma unroll
            for (int nt = 0; nt < 4; nt++) {
                int n0 = wnb + nt * 8 + r8;
                ldsm_x4(bf[nt], bS + (uint32_t)(n0 * LDH + kh * 32 + m4 * 8) * 2);
            }
#pragma unroll
            for (int k2 = 0; k2 < 2; k2++) {
                int ks = kh * 2 + k2;
                uint32_t af[4][4];
#pragma unroll
                for (int mt = 0; mt < 4; mt++) {
                    int r0 = wmb + mt * 16 + (m4 & 1) * 8 + r8;
                    ldsm_x4(af[mt], aS + (uint32_t)(r0 * LDH + ks * 16 + (m4 >> 1) * 8) * 2);
                }
#pragma unroll
                for (int mt = 0; mt < 4; mt++)
#pragma unroll
                    for (int nt = 0; nt < 4; nt++)
                        mma_f16(acc[mt][nt], af[mt], &bf[nt][2 * k2]);
            }
        }
        int nstg = stg + 2; if (nstg >= GSTG) nstg -= GSTG;
        if (kt + 2 < nk) issue_stage(kt + 2, nstg);
        CP_COMMIT();
        stg = stg + 1 == GSTG ? 0 : stg + 1;
    }

#pragma unroll
    for (int mt = 0; mt < 4; mt++) {
        int r0 = bm + wmb + mt * 16 + qr;
#pragma unroll
        for (int nt = 0; nt < 4; nt++) {
            int cc = bn + wnb + nt * 8 + 2 * qc;
            size_t i0 = (size_t)r0 * N + cc;
            size_t i1 = (size_t)(r0 + 8) * N + cc;
            if (EPI == 1) {
                const float* rf = (const float*)res;
                float* C = (float*)CO;
                float2 rr0 = *(const float2*)(rf + i0);
                float2 rr1 = *(const float2*)(rf + i1);
                *(float2*)(C + i0) = make_float2(acc[mt][nt][0] + rr0.x,
                                                 acc[mt][nt][1] + rr0.y);
                *(float2*)(C + i1) = make_float2(acc[mt][nt][2] + rr1.x,
                                                 acc[mt][nt][3] + rr1.y);
            } else {
                __half* C = (__half*)CO;
                float a0 = acc[mt][nt][0], a1 = acc[mt][nt][1];
                float a2 = acc[mt][nt][2], a3 = acc[mt][nt][3];
                if (ropef) {
                    int s0 = r0 & (SEQ - 1), s1 = (r0 + 8) & (SEQ - 1);
                    int j  = (cc & 127) >> 1;
                    float sn0 = g_rsin[s0 * 64 + j], cs0 = g_rcos[s0 * 64 + j];
                    float sn1 = g_rsin[s1 * 64 + j], cs1 = g_rcos[s1 * 64 + j];
                    *(__half2*)(C + i0) = __floats2half2_rn(a0 * cs0 - a1 * sn0,
                                                            a0 * sn0 + a1 * cs0);
                    *(__half2*)(C + i1) = __floats2half2_rn(a2 * cs1 - a3 * sn1,
                                                            a2 * sn1 + a3 * cs1);
                } else {
                    *(__half2*)(C + i0) = __floats2half2_rn(a0, a1);
                    *(__half2*)(C + i1) = __floats2half2_rn(a2, a3);
                }
            }
        }
    }
}

template<int EPI>
__global__ __launch_bounds__(256, 2) void gemm_mma(
        const __half* __restrict__ A, const __half* __restrict__ W,
        const void* __restrict__ res, void* __restrict__ CO,
        int M, int N, int K) {
    gemm_body<EPI>(A, W, res, CO, M, N, K, 0);
}

__global__ __launch_bounds__(256, 2) void gemm_qkv(const __half* __restrict__ A) {
    int z = blockIdx.z;
    const __half* W = z == 0 ? g_wq : (z == 1 ? g_wk : g_wv);
    __half* C = z == 0 ? g_qh : (z == 1 ? g_kh : g_vh);
    gemm_body<3>(A, W, nullptr, C, M_TOK, D_MODEL, D_MODEL, z < 2);
}

// ========== fused W1+W3 GEMM: ff = silu(W1 xn) * (W3 xn), BK=64 =============
__global__ __launch_bounds__(256, 2) void gemm_w13(const __half* __restrict__ A,
                                                   __half* __restrict__ FF) {
    extern __shared__ char smc[];
    __half* As  = (__half*)smc;                  // [GSTG][128][LDH]
    __half* B1s = As  + GSTG * 128 * LDH;        // [GSTG][64][LDH]
    __half* B3s = B1s + GSTG * 64 * LDH;         // [GSTG][64][LDH]

    const int K = D_MODEL, N = DFF;
    int tid  = threadIdx.x;
    int lane = tid & 31, wid = tid >> 5;
    int wmb = (wid >> 2) * 64, wnb = (wid & 3) * 16;
    int bm = blockIdx.y * 128, bn = blockIdx.x * 64;
    int m4 = lane >> 3, r8 = lane & 7;

    uint32_t as_base  = smem_u32(As);
    uint32_t b1_base  = smem_u32(B1s);
    uint32_t b3_base  = smem_u32(B3s);

    auto issue_stage = [&](int tile, int stg) {
        uint32_t aoff = (uint32_t)stg * 128 * LDH * 2;
        uint32_t boff = (uint32_t)stg * 64 * LDH * 2;
        const __half* a2 = A    + (size_t)bm * K + tile * 64;
        const __half* w1 = g_w1 + (size_t)bn * K + tile * 64;
        const __half* w3 = g_w3 + (size_t)bn * K + tile * 64;
#pragma unroll
        for (int i = 0; i < 4; i++) {
            int idx = tid + i * 256;
            int r = idx >> 3, c = (idx & 7) * 8;
            cp_async16(as_base + aoff + (uint32_t)(r * LDH + c) * 2,
                       a2 + (size_t)r * K + c);
        }
#pragma unroll
        for (int i = 0; i < 2; i++) {
            int idx = tid + i * 256;             // 0..511
            int r = idx >> 3, c = (idx & 7) * 8;
            uint32_t d = (uint32_t)(r * LDH + c) * 2;
            cp_async16(b1_base + boff + d, w1 + (size_t)r * K + c);
            cp_async16(b3_base + boff + d, w3 + (size_t)r * K + c);
        }
    };

    int nk = K >> 6;
    issue_stage(0, 0); CP_COMMIT();
    issue_stage(1, 1); CP_COMMIT();

    float acc1[4][2][4] = {}, acc3[4][2][4] = {};
    int qr = lane >> 2, qc = lane & 3;

    int stg = 0;
    for (int kt = 0; kt < nk; kt++) {
        CP_WAIT(1);
        __syncthreads();
        uint32_t aS  = as_base + (uint32_t)stg * 128 * LDH * 2;
        uint32_t b1S = b1_base + (uint32_t)stg * 64 * LDH * 2;
        uint32_t b3S = b3_base + (uint32_t)stg * 64 * LDH * 2;

#pragma unroll
        for (int kh = 0; kh < 2; kh++) {
            uint32_t b1f[2][4], b3f[2][4];
#pragma unroll
            for (int nt = 0; nt < 2; nt++) {
                int n0 = wnb + nt * 8 + r8;
                ldsm_x4(b1f[nt], b1S + (uint32_t)(n0 * LDH + kh * 32 + m4 * 8) * 2);
                ldsm_x4(b3f[nt], b3S + (uint32_t)(n0 * LDH + kh * 32 + m4 * 8) * 2);
            }
#pragma unroll
            for (int k2 = 0; k2 < 2; k2++) {
                int ks = kh * 2 + k2;
                uint32_t af[4][4];
#pragma unroll
                for (int mt = 0; mt < 4; mt++) {
                    int r0 = wmb + mt * 16 + (m4 & 1) * 8 + r8;
                    ldsm_x4(af[mt], aS + (uint32_t)(r0 * LDH + ks * 16 + (m4 >> 1) * 8) * 2);
                }
#pragma unroll
                for (int mt = 0; mt < 4; mt++)
#pragma unroll
                    for (int nt = 0; nt < 2; nt++) {
                        mma_f16(acc1[mt][nt], af[mt], &b1f[nt][2 * k2]);
                        mma_f16(acc3[mt][nt], af[mt], &b3f[nt][2 * k2]);
                    }
            }
        }
        int nstg = stg + 2; if (nstg >= GSTG) nstg -= GSTG;
        if (kt + 2 < nk) issue_stage(kt + 2, nstg);
        CP_COMMIT();
        stg = stg + 1 == GSTG ? 0 : stg + 1;
    }

#pragma unroll
    for (int mt = 0; mt < 4; mt++) {
        int r0 = bm + wmb + mt * 16 + qr;
#pragma unroll
        for (int nt = 0; nt < 2; nt++) {
            int cc = bn + wnb + nt * 8 + 2 * qc;
            size_t i0 = (size_t)r0 * N + cc;
            size_t i1 = (size_t)(r0 + 8) * N + cc;
            float a0 = acc1[mt][nt][0], a1 = acc1[mt][nt][1];
            float a2 = acc1[mt][nt][2], a3 = acc1[mt][nt][3];
            float v0 = acc3[mt][nt][0] * (a0 / (1.f + __expf(-a0)));
            float v1 = acc3[mt][nt][1] * (a1 / (1.f + __expf(-a1)));
            float v2 = acc3[mt][nt][2] * (a2 / (1.f + __expf(-a2)));
            float v3 = acc3[mt][nt][3] * (a3 / (1.f + __expf(-a3)));
            *(__half2*)(FF + i0) = __floats2half2_rn(v0, v1);
            *(__half2*)(FF + i1) = __floats2half2_rn(v2, v3);
        }
    }
}

// ---------------- RMSNorm (float4 loads, writes half) ----------------
__global__ void rmsnorm_kernel(const float* __restrict__ x,
                               const float* __restrict__ g,
                               __half* __restrict__ out) {
    int row = blockIdx.x;
    const float4* xr = (const float4*)(x + (size_t)row * D_MODEL);
    float4 v[2];
    v[0] = xr[threadIdx.x];
    v[1] = xr[threadIdx.x + 256];
    float s = v[0].x*v[0].x + v[0].y*v[0].y + v[0].z*v[0].z + v[0].w*v[0].w
            + v[1].x*v[1].x + v[1].y*v[1].y + v[1].z*v[1].z + v[1].w*v[1].w;
    __shared__ float red[32];
    for (int o = 16; o; o >>= 1) s += __shfl_down_sync(0xffffffffu, s, o);
    if ((threadIdx.x & 31) == 0) red[threadIdx.x >> 5] = s;
    __syncthreads();
    if (threadIdx.x < 32) {
        float t = (threadIdx.x < 8) ? red[threadIdx.x] : 0.f;
        for (int o = 4; o; o >>= 1) t += __shfl_down_sync(0xffffffffu, t, o);
        if (threadIdx.x == 0) red[0] = t;
    }
    __syncthreads();
    float rinv = rsqrtf(red[0] * (1.0f / D_MODEL) + 1e-5f);
    __half2* orow = (__half2*)(out + (size_t)row * D_MODEL);
    const float4* g4 = (const float4*)g;
#pragma unroll
    for (int i = 0; i < 2; i++) {
        float4 gv = g4[threadIdx.x + i * 256];
        orow[(threadIdx.x + i * 256) * 2]     =
            __floats2half2_rn(v[i].x * gv.x * rinv, v[i].y * gv.y * rinv);
        orow[(threadIdx.x + i * 256) * 2 + 1] =
            __floats2half2_rn(v[i].z * gv.z * rinv, v[i].w * gv.w * rinv);
    }
}

// ---------------- RoPE tables ----------------
__global__ void rope_table_kernel() {
    int idx = blockIdx.x * blockDim.x + threadIdx.x;
    if (idx >= SEQ * 64) return;
    int j = idx & 63, s = idx >> 6;
    double inv = exp(-(double)j * (9.210340371976184 / 64.0));
    double ang = fmod((double)s * inv, 6.283185307179586476925286766559);
    float fa = (float)ang;
    g_rsin[idx] = sinf(fa);
    g_rcos[idx] = cosf(fa);
}

// ---------------- fp16 tensor-core flash attention (causal) ----------------
#define QLD 136
#define KLH 136
#define ATT_SMEM ((2*64*KLH + 2*64*KLH) * 2)

__global__ __launch_bounds__(256) void attn_f16(
        const __half* __restrict__ Q,
        const __half* __restrict__ K,
        const __half* __restrict__ V,
        __half* __restrict__ O) {
    extern __shared__ __half smh[];
    __half* Qst = smh;
    __half* Ksm = smh;
    __half* Vsm = Ksm + 2 * 64 * KLH;

    int tid = threadIdx.x;
    int lane = tid & 31, wid = tid >> 5;
    int qr = lane >> 2, qc = lane & 3;
    int bh = blockIdx.y;
    int b = bh >> 4, h = bh & 15;
    int qblk = gridDim.x - 1 - blockIdx.x;
    int q0 = qblk * 128;
    int nkb = 2 * qblk + 2;
    int m4 = lane >> 3;
    int r8 = lane & 7;

    for (int i = tid; i < 128 * 16; i += 256) {
        int r = i >> 4, c8 = (i & 15) * 8;
        *(uint4*)(Qst + r * QLD + c8) =
            *(const uint4*)(Q + (size_t)(b * SEQ + q0 + r) * D_MODEL + h * DKH + c8);
    }
    __syncthreads();
    uint32_t afq[8][4];
    {
        uint32_t qb_ = smem_u32(Qst);
        int row = wid * 16 + (m4 & 1) * 8 + r8;
#pragma unroll
        for (int ks = 0; ks < 8; ks++)
            ldsm_x4(afq[ks], qb_ + (uint32_t)(row * QLD + ks * 16 + (m4 >> 1) * 8) * 2);
    }
    __syncthreads();

    uint32_t ks_base = smem_u32(Ksm);
    uint32_t vs_base = smem_u32(Vsm);
    auto issue_kv = [&](int kb, int stg) {
        uint32_t off = (uint32_t)stg * 64 * KLH * 2;
#pragma unroll
        for (int i = 0; i < 4; i++) {
            int idx = tid + i * 256;
            int r = idx >> 4, c8 = (idx & 15) * 8;
            size_t g = (size_t)(b * SEQ + kb * 64 + r) * D_MODEL + h * DKH + c8;
            uint32_t d = (uint32_t)(r * KLH + c8) * 2;
            cp_async16(ks_base + off + d, K + g);
            cp_async16(vs_base + off + d, V + g);
        }
    };

    issue_kv(0, 0); CP_COMMIT();

    float o[16][4] = {};
    float m0 = -1e30f, m1 = -1e30f, l0 = 0.f, l1 = 0.f;
    const float scale = 0.08838834764831845f;

    for (int kb = 0; kb < nkb; kb++) {
        CP_WAIT(0);
        __syncthreads();
        if (kb + 1 < nkb) issue_kv(kb + 1, (kb + 1) & 1);
        CP_COMMIT();
        uint32_t kst = ks_base + (uint32_t)(kb & 1) * 64 * KLH * 2;
        uint32_t vst = vs_base + (uint32_t)(kb & 1) * 64 * KLH * 2;

        float s[8][4] = {};
#pragma unroll
        for (int c2 = 0; c2 < 4; c2++) {
#pragma unroll
            for (int n0 = 0; n0 < 8; n0++) {
                uint32_t kf[4];
                ldsm_x4(kf, kst + (uint32_t)((n0 * 8 + r8) * KLH + c2 * 32 + m4 * 8) * 2);
                mma_f16(s[n0], afq[2 * c2],     kf);
                mma_f16(s[n0], afq[2 * c2 + 1], kf + 2);
            }
        }

        bool diag = (kb >= 2 * qblk);
        int row0 = q0 + wid * 16 + qr, row1 = row0 + 8;
        float mt0 = -1e30f, mt1 = -1e30f;
#pragma unroll
        for (int nt = 0; nt < 8; nt++) {
            int col = kb * 64 + nt * 8 + 2 * qc;
            s[nt][0] *= scale; s[nt][1] *= scale;
            s[nt][2] *= scale; s[nt][3] *= scale;
            if (diag) {
                if (col > row0)     s[nt][0] = -1e30f;
                if (col + 1 > row0) s[nt][1] = -1e30f;
                if (col > row1)     s[nt][2] = -1e30f;
                if (col + 1 > row1) s[nt][3] = -1e30f;
            }
            mt0 = fmaxf(mt0, fmaxf(s[nt][0], s[nt][1]));
            mt1 = fmaxf(mt1, fmaxf(s[nt][2], s[nt][3]));
        }
#pragma unroll
        for (int off = 1; off < 4; off <<= 1) {
            mt0 = fmaxf(mt0, __shfl_xor_sync(0xffffffffu, mt0, off));
            mt1 = fmaxf(mt1, __shfl_xor_sync(0xffffffffu, mt1, off));
        }
        float mn0 = fmaxf(m0, mt0), mn1 = fmaxf(m1, mt1);
        float ls0 = 0.f, ls1 = 0.f;

        uint32_t afp[4][4];
#pragma unroll
        for (int nt = 0; nt < 8; nt++) {
            uint32_t h01 = f22u(__expf(s[nt][0] - mn0), __expf(s[nt][1] - mn0));
            uint32_t h23 = f22u(__expf(s[nt][2] - mn1), __expf(s[nt][3] - mn1));
            float2 f01 = __half22float2(*(__half2*)&h01);
            float2 f23 = __half22float2(*(__half2*)&h23);
            ls0 += f01.x + f01.y; ls1 += f23.x + f23.y;
            int ks = nt >> 1;
            if ((nt & 1) == 0) { afp[ks][0] = h01; afp[ks][1] = h23; }
            else               { afp[ks][2] = h01; afp[ks][3] = h23; }
        }
#pragma unroll
        for (int off = 1; off < 4; off <<= 1) {
            ls0 += __shfl_xor_sync(0xffffffffu, ls0, off);
            ls1 += __shfl_xor_sync(0xffffffffu, ls1, off);
        }
        float al0 = __expf(m0 - mn0), al1 = __expf(m1 - mn1);
        l0 = l0 * al0 + ls0; l1 = l1 * al1 + ls1;
        m0 = mn0; m1 = mn1;
#pragma unroll
        for (int nt = 0; nt < 16; nt++) {
            o[nt][0] *= al0; o[nt][1] *= al0;
            o[nt][2] *= al1; o[nt][3] *= al1;
        }

#pragma unroll
        for (int ks = 0; ks < 4; ks++) {
#pragma unroll
            for (int g = 0; g < 8; g++) {
                uint32_t vf[4];
                ldsm_x4_t(vf, vst + (uint32_t)((ks * 16 + (m4 & 1) * 8 + r8) * KLH
                                               + g * 16 + (m4 >> 1) * 8) * 2);
                mma_f16(o[2 * g],     afp[ks], vf);
                mma_f16(o[2 * g + 1], afp[ks], vf + 2);
            }
        }
    }

    float i0 = 1.f / l0, i1 = 1.f / l1;
    int r0 = b * SEQ + q0 + wid * 16 + qr;
#pragma unroll
    for (int nt = 0; nt < 16; nt++) {
        int cc = h * DKH + nt * 8 + 2 * qc;
        *(__half2*)(O + (size_t)r0 * D_MODEL + cc) =
            __floats2half2_rn(o[nt][0] * i0, o[nt][1] * i0);
        *(__half2*)(O + (size_t)(r0 + 8) * D_MODEL + cc) =
            __floats2half2_rn(o[nt][2] * i1, o[nt][3] * i1);
    }
}

// ---------------- launch ----------------
extern "C" void kernel_launch(void* const* d_in, const int* in_sizes, int n_in,
                              void* d_out, int out_size) {
    const float* x  = (const float*)d_in[0];
    const float* Wq = (const float*)d_in[1];
    const float* Wk = (const float*)d_in[2];
    const float* Wv = (const float*)d_in[3];
    const float* Wo = (const float*)d_in[4];
    const float* W1 = (const float*)d_in[5];
    const float* W2 = (const float*)d_in[6];
    const float* W3 = (const float*)d_in[7];
    const float* g1 = (const float*)d_in[8];
    const float* g2 = (const float*)d_in[9];
    float* out = (float*)d_out;

    float *xmid;
    __half *xnh, *ctxh, *ffh, *qh, *kh, *vh;
    __half *wqh, *wkh, *wvh, *woh, *w1h, *w2h, *w3h;
    cudaGetSymbolAddress((void**)&xmid, g_xmid);
    cudaGetSymbolAddress((void**)&xnh,  g_xn_h);
    cudaGetSymbolAddress((void**)&ctxh, g_ctx_h);
    cudaGetSymbolAddress((void**)&ffh,  g_ff_h);
    cudaGetSymbolAddress((void**)&qh,   g_qh);
    cudaGetSymbolAddress((void**)&kh,   g_kh);
    cudaGetSymbolAddress((void**)&vh,   g_vh);
    cudaGetSymbolAddress((void**)&wqh,  g_wq);
    cudaGetSymbolAddress((void**)&wkh,  g_wk);
    cudaGetSymbolAddress((void**)&wvh,  g_wv);
    cudaGetSymbolAddress((void**)&woh,  g_wo);
    cudaGetSymbolAddress((void**)&w1h,  g_w1);
    cudaGetSymbolAddress((void**)&w2h,  g_w2);
    cudaGetSymbolAddress((void**)&w3h,  g_w3);

    cudaFuncSetAttribute(gemm_mma<1>, cudaFuncAttributeMaxDynamicSharedMemorySize, GEMM_SMEM);
    cudaFuncSetAttribute(gemm_mma<3>, cudaFuncAttributeMaxDynamicSharedMemorySize, GEMM_SMEM);
    cudaFuncSetAttribute(gemm_qkv,    cudaFuncAttributeMaxDynamicSharedMemorySize, GEMM_SMEM);
    cudaFuncSetAttribute(gemm_w13,    cudaFuncAttributeMaxDynamicSharedMemorySize, GEMM_SMEM);
    cudaFuncSetAttribute(attn_f16,    cudaFuncAttributeMaxDynamicSharedMemorySize, ATT_SMEM);

    // ---- side stream for weight conversion (graph-capture fork/join) ----
    cudaStream_t s2;
    cudaStreamCreateWithFlags(&s2, cudaStreamNonBlocking);
    cudaEvent_t evFork, evQKV, evW;
    cudaEventCreateWithFlags(&evFork, cudaEventDisableTiming);
    cudaEventCreateWithFlags(&evQKV,  cudaEventDisableTiming);
    cudaEventCreateWithFlags(&evW,    cudaEventDisableTiming);

    cudaEventRecord(evFork, 0);
    cudaStreamWaitEvent(s2, evFork, 0);

    const int CT = 256;
    int nDM = D_MODEL * D_MODEL / 4, nFF = DFF * D_MODEL / 4;
    f2h_kernel<<<(nDM + CT - 1) / CT, CT, 0, s2>>>((const float4*)Wq, (__half2*)wqh, nDM);
    f2h_kernel<<<(nDM + CT - 1) / CT, CT, 0, s2>>>((const float4*)Wk, (__half2*)wkh, nDM);
    f2h_kernel<<<(nDM + CT - 1) / CT, CT, 0, s2>>>((const float4*)Wv, (__half2*)wvh, nDM);
    cudaEventRecord(evQKV, s2);
    f2h_kernel<<<(nDM + CT - 1) / CT, CT, 0, s2>>>((const float4*)Wo, (__half2*)woh, nDM);
    f2h_kernel<<<(nFF + CT - 1) / CT, CT, 0, s2>>>((const float4*)W1, (__half2*)w1h, nFF);
    f2h_kernel<<<(nFF + CT - 1) / CT, CT, 0, s2>>>((const float4*)W3, (__half2*)w3h, nFF);
    f2h_kernel<<<(nFF + CT - 1) / CT, CT, 0, s2>>>((const float4*)W2, (__half2*)w2h, nFF);
    cudaEventRecord(evW, s2);

    dim3 blk(256);
    // main stream: rmsnorm + rope table overlap the weight conversions
    rmsnorm_kernel<<<M_TOK, 256>>>(x, g1, xnh);
    rope_table_kernel<<<(SEQ * 64 + 255) / 256, 256>>>();
    cudaStreamWaitEvent(0, evQKV, 0);
    dim3 gq(D_MODEL / GBN, M_TOK / GBM, 3);
    gemm_qkv<<<gq, blk, GEMM_SMEM>>>(xnh);
    dim3 gattn(SEQ / 128, BATCH * NHEAD);
    attn_f16<<<gattn, blk, ATT_SMEM>>>(qh, kh, vh, ctxh);
    cudaStreamWaitEvent(0, evW, 0);
    dim3 gdm(D_MODEL / GBN, M_TOK / GBM);
    gemm_mma<1><<<gdm, blk, GEMM_SMEM>>>(ctxh, woh, x, xmid, M_TOK, D_MODEL, D_MODEL);
    rmsnorm_kernel<<<M_TOK, 256>>>(xmid, g2, xnh);
    dim3 gw13(DFF / 64, M_TOK / 128);
    gemm_w13<<<gw13, blk, GEMM_SMEM>>>(xnh, ffh);
    gemm_mma<1><<<gdm, blk, GEMM_SMEM>>>(ffh, w2h, xmid, out, M_TOK, D_MODEL, DFF);
}

// round 15
// speedup vs baseline: 16.7504x; 1.0047x over previous
#include <cuda_runtime.h>
#include <cuda_fp16.h>
#include <math.h>
#include <stdint.h>

#define D_MODEL 2048
#define NHEAD   16
#define DKH     128
#define DFF     5632
#define SEQ     2048
#define BATCH   2
#define M_TOK   (BATCH*SEQ)   // 4096

// ---------------- scratch ----------------
__device__ float  g_xmid[(size_t)M_TOK*D_MODEL];
__device__ __half g_xn_h [(size_t)M_TOK*D_MODEL];
__device__ __half g_ctx_h[(size_t)M_TOK*D_MODEL];
__device__ __half g_ff_h [(size_t)M_TOK*DFF];
__device__ __half g_qh[(size_t)M_TOK*D_MODEL];
__device__ __half g_kh[(size_t)M_TOK*D_MODEL];
__device__ __half g_vh[(size_t)M_TOK*D_MODEL];
__device__ __half g_wq[(size_t)D_MODEL*D_MODEL];
__device__ __half g_wk[(size_t)D_MODEL*D_MODEL];
__device__ __half g_wv[(size_t)D_MODEL*D_MODEL];
__device__ __half g_wo[(size_t)D_MODEL*D_MODEL];
__device__ __half g_w1[(size_t)DFF*D_MODEL];
__device__ __half g_w2[(size_t)D_MODEL*DFF];
__device__ __half g_w3[(size_t)DFF*D_MODEL];
__device__ float  g_rsin[SEQ*64];
__device__ float  g_rcos[SEQ*64];

// ================= helpers =================
__device__ __forceinline__ void mma_f16(float* d, const uint32_t* a, const uint32_t* b) {
    asm volatile(
        "mma.sync.aligned.m16n8k16.row.col.f32.f16.f16.f32 "
        "{%0,%1,%2,%3}, {%4,%5,%6,%7}, {%8,%9}, {%0,%1,%2,%3};"
        : "+f"(d[0]), "+f"(d[1]), "+f"(d[2]), "+f"(d[3])
        : "r"(a[0]), "r"(a[1]), "r"(a[2]), "r"(a[3]),
          "r"(b[0]), "r"(b[1]));
}
__device__ __forceinline__ uint32_t smem_u32(const void* p) {
    uint32_t a;
    asm("{ .reg .u64 t; cvta.to.shared.u64 t, %1; cvt.u32.u64 %0, t; }"
        : "=r"(a) : "l"(p));
    return a;
}
__device__ __forceinline__ void cp_async16(uint32_t dst, const void* src) {
    asm volatile("cp.async.cg.shared.global [%0], [%1], 16;" :: "r"(dst), "l"(src));
}
#define CP_COMMIT()  asm volatile("cp.async.commit_group;" ::: "memory")
#define CP_WAIT(N)   asm volatile("cp.async.wait_group %0;" :: "n"(N) : "memory")

__device__ __forceinline__ void ldsm_x4(uint32_t* r, uint32_t a) {
    asm volatile("ldmatrix.sync.aligned.m8n8.x4.shared.b16 {%0,%1,%2,%3}, [%4];"
                 : "=r"(r[0]), "=r"(r[1]), "=r"(r[2]), "=r"(r[3]) : "r"(a));
}
__device__ __forceinline__ void ldsm_x4_t(uint32_t* r, uint32_t a) {
    asm volatile("ldmatrix.sync.aligned.m8n8.x4.trans.shared.b16 {%0,%1,%2,%3}, [%4];"
                 : "=r"(r[0]), "=r"(r[1]), "=r"(r[2]), "=r"(r[3]) : "r"(a));
}
__device__ __forceinline__ uint32_t f22u(float a, float b) {
    __half2 h = __floats2half2_rn(a, b);
    return *(uint32_t*)&h;
}

// ---------------- fp32 -> fp16 convert ----------------
__global__ void f2h_kernel(const float4* __restrict__ in, __half2* __restrict__ out, int n4) {
    int i = blockIdx.x * blockDim.x + threadIdx.x;
    if (i >= n4) return;
    float4 v = in[i];
    out[2 * i]     = __floats2half2_rn(v.x, v.y);
    out[2 * i + 1] = __floats2half2_rn(v.z, v.w);
}

// ================= fp16 GEMM, 128x128 tiles, BK=64, 3-stage, 2 CTAs/SM ======
#define GBM 128
#define GBN 128
#define LDH  72
#define GSTG 3
#define GEMM_SMEM (GSTG*(GBM+GBN)*LDH*2)

template<int EPI>
__device__ __forceinline__ void gemm_body(
        const __half* __restrict__ A,
        const __half* __restrict__ W,
        const void* __restrict__ res,
        void* __restrict__ CO,
        int M, int N, int K, int ropef) {
    extern __shared__ char smc[];
    __half* As = (__half*)smc;
    __half* Bs = As + GSTG * GBM * LDH;

    int tid  = threadIdx.x;
    int lane = tid & 31, wid = tid >> 5;
    int wmb = (wid >> 2) * 64, wnb = (wid & 3) * 32;
    int bm = blockIdx.y * GBM, bn = blockIdx.x * GBN;
    int m4 = lane >> 3, r8 = lane & 7;

    uint32_t as_base = smem_u32(As);
    uint32_t bs_base = smem_u32(Bs);

    auto issue_stage = [&](int tile, int stg) {
        uint32_t aoff = (uint32_t)stg * GBM * LDH * 2;
        uint32_t boff = (uint32_t)stg * GBN * LDH * 2;
        const __half* a2 = A + (size_t)bm * K + tile * 64;
        const __half* w2 = W + (size_t)bn * K + tile * 64;
#pragma unroll
        for (int i = 0; i < 4; i++) {
            int idx = tid + i * 256;
            int r = idx >> 3, c = (idx & 7) * 8;
            cp_async16(as_base + aoff + (uint32_t)(r * LDH + c) * 2,
                       a2 + (size_t)r * K + c);
            cp_async16(bs_base + boff + (uint32_t)(r * LDH + c) * 2,
                       w2 + (size_t)r * K + c);
        }
    };

    int nk = K >> 6;
    issue_stage(0, 0); CP_COMMIT();
    issue_stage(1, 1); CP_COMMIT();

    float acc[4][4][4] = {};
    int qr = lane >> 2, qc = lane & 3;

    int stg = 0;
    for (int kt = 0; kt < nk; kt++) {
        CP_WAIT(1);
        __syncthreads();
        uint32_t aS = as_base + (uint32_t)stg * GBM * LDH * 2;
        uint32_t bS = bs_base + (uint32_t)stg * GBN * LDH * 2;

#pragma unroll
        for (int kh = 0; kh < 2; kh++) {
            uint32_t bf[4][4];
#pragma unroll
            for (int nt = 0; nt < 4; nt++) {
                int n0 = wnb + nt * 8 + r8;
                ldsm_x4(bf[nt], bS + (uint32_t)(n0 * LDH + kh * 32 + m4 * 8) * 2);
            }
#pragma unroll
            for (int k2 = 0; k2 < 2; k2++) {
                int ks = kh * 2 + k2;
                uint32_t af[4][4];
#pragma unroll
                for (int mt = 0; mt < 4; mt++) {
                    int r0 = wmb + mt * 16 + (m4 & 1) * 8 + r8;
                    ldsm_x4(af[mt], aS + (uint32_t)(r0 * LDH + ks * 16 + (m4 >> 1) * 8) * 2);
                }
#pragma unroll
                for (int mt = 0; mt < 4; mt++)
#pragma unroll
                    for (int nt = 0; nt < 4; nt++)
                        mma_f16(acc[mt][nt], af[mt], &bf[nt][2 * k2]);
            }
        }
        int nstg = stg + 2; if (nstg >= GSTG) nstg -= GSTG;
        if (kt + 2 < nk) issue_stage(kt + 2, nstg);
        CP_COMMIT();
        stg = stg + 1 == GSTG ? 0 : stg + 1;
    }

#pragma unroll
    for (int mt = 0; mt < 4; mt++) {
        int r0 = bm + wmb + mt * 16 + qr;
#pragma unroll
        for (int nt = 0; nt < 4; nt++) {
            int cc = bn + wnb + nt * 8 + 2 * qc;
            size_t i0 = (size_t)r0 * N + cc;
            size_t i1 = (size_t)(r0 + 8) * N + cc;
            if (EPI == 1) {
                const float* rf = (const float*)res;
                float* C = (float*)CO;
                float2 rr0 = *(const float2*)(rf + i0);
                float2 rr1 = *(const float2*)(rf + i1);
                *(float2*)(C + i0) = make_float2(acc[mt][nt][0] + rr0.x,
                                                 acc[mt][nt][1] + rr0.y);
                *(float2*)(C + i1) = make_float2(acc[mt][nt][2] + rr1.x,
                                                 acc[mt][nt][3] + rr1.y);
            } else {
                __half* C = (__half*)CO;
                float a0 = acc[mt][nt][0], a1 = acc[mt][nt][1];
                float a2 = acc[mt][nt][2], a3 = acc[mt][nt][3];
                if (ropef) {
                    int s0 = r0 & (SEQ - 1), s1 = (r0 + 8) & (SEQ - 1);
                    int j  = (cc & 127) >> 1;
                    float sn0 = g_rsin[s0 * 64 + j], cs0 = g_rcos[s0 * 64 + j];
                    float sn1 = g_rsin[s1 * 64 + j], cs1 = g_rcos[s1 * 64 + j];
                    *(__half2*)(C + i0) = __floats2half2_rn(a0 * cs0 - a1 * sn0,
                                                            a0 * sn0 + a1 * cs0);
                    *(__half2*)(C + i1) = __floats2half2_rn(a2 * cs1 - a3 * sn1,
                                                            a2 * sn1 + a3 * cs1);
                } else {
                    *(__half2*)(C + i0) = __floats2half2_rn(a0, a1);
                    *(__half2*)(C + i1) = __floats2half2_rn(a2, a3);
                }
            }
        }
    }
}

template<int EPI>
__global__ __launch_bounds__(256, 2) void gemm_mma(
        const __half* __restrict__ A, const __half* __restrict__ W,
        const void* __restrict__ res, void* __restrict__ CO,
        int M, int N, int K) {
    gemm_body<EPI>(A, W, res, CO, M, N, K, 0);
}

__global__ __launch_bounds__(256, 2) void gemm_qkv(const __half* __restrict__ A) {
    int z = blockIdx.z;
    const __half* W = z == 0 ? g_wq : (z == 1 ? g_wk : g_wv);
    __half* C = z == 0 ? g_qh : (z == 1 ? g_kh : g_vh);
    gemm_body<3>(A, W, nullptr, C, M_TOK, D_MODEL, D_MODEL, z < 2);
}

// ========== fused W1+W3 GEMM: ff = silu(W1 xn) * (W3 xn), BK=64 =============
__global__ __launch_bounds__(256, 2) void gemm_w13(const __half* __restrict__ A,
                                                   __half* __restrict__ FF) {
    extern __shared__ char smc[];
    __half* As  = (__half*)smc;
    __half* B1s = As  + GSTG * 128 * LDH;
    __half* B3s = B1s + GSTG * 64 * LDH;

    const int K = D_MODEL, N = DFF;
    int tid  = threadIdx.x;
    int lane = tid & 31, wid = tid >> 5;
    int wmb = (wid >> 2) * 64, wnb = (wid & 3) * 16;
    int bm = blockIdx.y * 128, bn = blockIdx.x * 64;
    int m4 = lane >> 3, r8 = lane & 7;

    uint32_t as_base  = smem_u32(As);
    uint32_t b1_base  = smem_u32(B1s);
    uint32_t b3_base  = smem_u32(B3s);

    auto issue_stage = [&](int tile, int stg) {
        uint32_t aoff = (uint32_t)stg * 128 * LDH * 2;
        uint32_t boff = (uint32_t)stg * 64 * LDH * 2;
        const __half* a2 = A    + (size_t)bm * K + tile * 64;
        const __half* w1 = g_w1 + (size_t)bn * K + tile * 64;
        const __half* w3 = g_w3 + (size_t)bn * K + tile * 64;
#pragma unroll
        for (int i = 0; i < 4; i++) {
            int idx = tid + i * 256;
            int r = idx >> 3, c = (idx & 7) * 8;
            cp_async16(as_base + aoff + (uint32_t)(r * LDH + c) * 2,
                       a2 + (size_t)r * K + c);
        }
#pragma unroll
        for (int i = 0; i < 2; i++) {
            int idx = tid + i * 256;
            int r = idx >> 3, c = (idx & 7) * 8;
            uint32_t d = (uint32_t)(r * LDH + c) * 2;
            cp_async16(b1_base + boff + d, w1 + (size_t)r * K + c);
            cp_async16(b3_base + boff + d, w3 + (size_t)r * K + c);
        }
    };

    int nk = K >> 6;
    issue_stage(0, 0); CP_COMMIT();
    issue_stage(1, 1); CP_COMMIT();

    float acc1[4][2][4] = {}, acc3[4][2][4] = {};
    int qr = lane >> 2, qc = lane & 3;

    int stg = 0;
    for (int kt = 0; kt < nk; kt++) {
        CP_WAIT(1);
        __syncthreads();
        uint32_t aS  = as_base + (uint32_t)stg * 128 * LDH * 2;
        uint32_t b1S = b1_base + (uint32_t)stg * 64 * LDH * 2;
        uint32_t b3S = b3_base + (uint32_t)stg * 64 * LDH * 2;

#pragma unroll
        for (int kh = 0; kh < 2; kh++) {
            uint32_t b1f[2][4], b3f[2][4];
#pragma unroll
            for (int nt = 0; nt < 2; nt++) {
                int n0 = wnb + nt * 8 + r8;
                ldsm_x4(b1f[nt], b1S + (uint32_t)(n0 * LDH + kh * 32 + m4 * 8) * 2);
                ldsm_x4(b3f[nt], b3S + (uint32_t)(n0 * LDH + kh * 32 + m4 * 8) * 2);
            }
#pragma unroll
            for (int k2 = 0; k2 < 2; k2++) {
                int ks = kh * 2 + k2;
                uint32_t af[4][4];
#pragma unroll
                for (int mt = 0; mt < 4; mt++) {
                    int r0 = wmb + mt * 16 + (m4 & 1) * 8 + r8;
                    ldsm_x4(af[mt], aS + (uint32_t)(r0 * LDH + ks * 16 + (m4 >> 1) * 8) * 2);
                }
#pragma unroll
                for (int mt = 0; mt < 4; mt++)
#pragma unroll
                    for (int nt = 0; nt < 2; nt++) {
                        mma_f16(acc1[mt][nt], af[mt], &b1f[nt][2 * k2]);
                        mma_f16(acc3[mt][nt], af[mt], &b3f[nt][2 * k2]);
                    }
            }
        }
        int nstg = stg + 2; if (nstg >= GSTG) nstg -= GSTG;
        if (kt + 2 < nk) issue_stage(kt + 2, nstg);
        CP_COMMIT();
        stg = stg + 1 == GSTG ? 0 : stg + 1;
    }

#pragma unroll
    for (int mt = 0; mt < 4; mt++) {
        int r0 = bm + wmb + mt * 16 + qr;
#pragma unroll
        for (int nt = 0; nt < 2; nt++) {
            int cc = bn + wnb + nt * 8 + 2 * qc;
            size_t i0 = (size_t)r0 * N + cc;
            size_t i1 = (size_t)(r0 + 8) * N + cc;
            float a0 = acc1[mt][nt][0], a1 = acc1[mt][nt][1];
            float a2 = acc1[mt][nt][2], a3 = acc1[mt][nt][3];
            float v0 = acc3[mt][nt][0] * (a0 / (1.f + __expf(-a0)));
            float v1 = acc3[mt][nt][1] * (a1 / (1.f + __expf(-a1)));
            float v2 = acc3[mt][nt][2] * (a2 / (1.f + __expf(-a2)));
            float v3 = acc3[mt][nt][3] * (a3 / (1.f + __expf(-a3)));
            *(__half2*)(FF + i0) = __floats2half2_rn(v0, v1);
            *(__half2*)(FF + i1) = __floats2half2_rn(v2, v3);
        }
    }
}

// ---------------- RMSNorm (float4 loads, writes half) ----------------
__global__ void rmsnorm_kernel(const float* __restrict__ x,
                               const float* __restrict__ g,
                               __half* __restrict__ out) {
    int row = blockIdx.x;
    const float4* xr = (const float4*)(x + (size_t)row * D_MODEL);
    float4 v[2];
    v[0] = xr[threadIdx.x];
    v[1] = xr[threadIdx.x + 256];
    float s = v[0].x*v[0].x + v[0].y*v[0].y + v[0].z*v[0].z + v[0].w*v[0].w
            + v[1].x*v[1].x + v[1].y*v[1].y + v[1].z*v[1].z + v[1].w*v[1].w;
    __shared__ float red[32];
    for (int o = 16; o; o >>= 1) s += __shfl_down_sync(0xffffffffu, s, o);
    if ((threadIdx.x & 31) == 0) red[threadIdx.x >> 5] = s;
    __syncthreads();
    if (threadIdx.x < 32) {
        float t = (threadIdx.x < 8) ? red[threadIdx.x] : 0.f;
        for (int o = 4; o; o >>= 1) t += __shfl_down_sync(0xffffffffu, t, o);
        if (threadIdx.x == 0) red[0] = t;
    }
    __syncthreads();
    float rinv = rsqrtf(red[0] * (1.0f / D_MODEL) + 1e-5f);
    __half2* orow = (__half2*)(out + (size_t)row * D_MODEL);
    const float4* g4 = (const float4*)g;
#pragma unroll
    for (int i = 0; i < 2; i++) {
        float4 gv = g4[threadIdx.x + i * 256];
        orow[(threadIdx.x + i * 256) * 2]     =
            __floats2half2_rn(v[i].x * gv.x * rinv, v[i].y * gv.y * rinv);
        orow[(threadIdx.x + i * 256) * 2 + 1] =
            __floats2half2_rn(v[i].z * gv.z * rinv, v[i].w * gv.w * rinv);
    }
}

// ---------------- RoPE tables ----------------
__global__ void rope_table_kernel() {
    int idx = blockIdx.x * blockDim.x + threadIdx.x;
    if (idx >= SEQ * 64) return;
    int j = idx & 63, s = idx >> 6;
    double inv = exp(-(double)j * (9.210340371976184 / 64.0));
    double ang = fmod((double)s * inv, 6.283185307179586476925286766559);
    float fa = (float)ang;
    g_rsin[idx] = sinf(fa);
    g_rcos[idx] = cosf(fa);
}

// ---------------- fp16 flash attention: BQ=64, 128 threads, multi-CTA/SM ----
#define QLD 136
#define KLH 136
#define ATT_SMEM ((2*64*KLH + 2*64*KLH) * 2)

__global__ __launch_bounds__(128) void attn_f16(
        const __half* __restrict__ Q,
        const __half* __restrict__ K,
        const __half* __restrict__ V,
        __half* __restrict__ O) {
    extern __shared__ __half smh[];
    __half* Qst = smh;                    // staging, overlaps K stages
    __half* Ksm = smh;                    // 2 x 64 x KLH
    __half* Vsm = Ksm + 2 * 64 * KLH;     // 2 x 64 x KLH

    int tid = threadIdx.x;
    int lane = tid & 31, wid = tid >> 5;         // wid 0..3
    int qr = lane >> 2, qc = lane & 3;
    int bh = blockIdx.y;
    int b = bh >> 4, h = bh & 15;
    int qblk = gridDim.x - 1 - blockIdx.x;       // heavy-first
    int q0 = qblk * 64;
    int nkb = qblk + 1;
    int m4 = lane >> 3;
    int r8 = lane & 7;

    // ---- stage Q (64 rows), extract register A-fragments ----
    for (int i = tid; i < 64 * 16; i += 128) {
        int r = i >> 4, c8 = (i & 15) * 8;
        *(uint4*)(Qst + r * QLD + c8) =
            *(const uint4*)(Q + (size_t)(b * SEQ + q0 + r) * D_MODEL + h * DKH + c8);
    }
    __syncthreads();
    uint32_t afq[8][4];
    {
        uint32_t qb_ = smem_u32(Qst);
        int row = wid * 16 + (m4 & 1) * 8 + r8;
#pragma unroll
        for (int ks = 0; ks < 8; ks++)
            ldsm_x4(afq[ks], qb_ + (uint32_t)(row * QLD + ks * 16 + (m4 >> 1) * 8) * 2);
    }
    __syncthreads();

    uint32_t ks_base = smem_u32(Ksm);
    uint32_t vs_base = smem_u32(Vsm);
    auto issue_kv = [&](int kb, int stg) {
        uint32_t off = (uint32_t)stg * 64 * KLH * 2;
#pragma unroll
        for (int i = 0; i < 8; i++) {
            int idx = tid + i * 128;
            int r = idx >> 4, c8 = (idx & 15) * 8;
            size_t g = (size_t)(b * SEQ + kb * 64 + r) * D_MODEL + h * DKH + c8;
            uint32_t d = (uint32_t)(r * KLH + c8) * 2;
            cp_async16(ks_base + off + d, K + g);
            cp_async16(vs_base + off + d, V + g);
        }
    };

    issue_kv(0, 0); CP_COMMIT();

    float o[16][4] = {};
    float m0 = -1e30f, m1 = -1e30f, l0 = 0.f, l1 = 0.f;
    const float scale = 0.08838834764831845f;   // 1/sqrt(128)

    for (int kb = 0; kb < nkb; kb++) {
        CP_WAIT(0);
        __syncthreads();
        if (kb + 1 < nkb) issue_kv(kb + 1, (kb + 1) & 1);
        CP_COMMIT();
        uint32_t kst = ks_base + (uint32_t)(kb & 1) * 64 * KLH * 2;
        uint32_t vst = vs_base + (uint32_t)(kb & 1) * 64 * KLH * 2;

        // ---- S = Q K^T ----
        float s[8][4] = {};
#pragma unroll
        for (int c2 = 0; c2 < 4; c2++) {
#pragma unroll
            for (int n0 = 0; n0 < 8; n0++) {
                uint32_t kf[4];
                ldsm_x4(kf, kst + (uint32_t)((n0 * 8 + r8) * KLH + c2 * 32 + m4 * 8) * 2);
                mma_f16(s[n0], afq[2 * c2],     kf);
                mma_f16(s[n0], afq[2 * c2 + 1], kf + 2);
            }
        }

        // ---- mask + online softmax ----
        bool diag = (kb == qblk);
        int row0 = q0 + wid * 16 + qr, row1 = row0 + 8;
        float mt0 = -1e30f, mt1 = -1e30f;
#pragma unroll
        for (int nt = 0; nt < 8; nt++) {
            int col = kb * 64 + nt * 8 + 2 * qc;
            s[nt][0] *= scale; s[nt][1] *= scale;
            s[nt][2] *= scale; s[nt][3] *= scale;
            if (diag) {
                if (col > row0)     s[nt][0] = -1e30f;
                if (col + 1 > row0) s[nt][1] = -1e30f;
                if (col > row1)     s[nt][2] = -1e30f;
                if (col + 1 > row1) s[nt][3] = -1e30f;
            }
            mt0 = fmaxf(mt0, fmaxf(s[nt][0], s[nt][1]));
            mt1 = fmaxf(mt1, fmaxf(s[nt][2], s[nt][3]));
        }
#pragma unroll
        for (int off = 1; off < 4; off <<= 1) {
            mt0 = fmaxf(mt0, __shfl_xor_sync(0xffffffffu, mt0, off));
            mt1 = fmaxf(mt1, __shfl_xor_sync(0xffffffffu, mt1, off));
        }
        float mn0 = fmaxf(m0, mt0), mn1 = fmaxf(m1, mt1);
        float ls0 = 0.f, ls1 = 0.f;

        // exp -> pack DIRECTLY into A-fragments
        uint32_t afp[4][4];
#pragma unroll
        for (int nt = 0; nt < 8; nt++) {
            uint32_t h01 = f22u(__expf(s[nt][0] - mn0), __expf(s[nt][1] - mn0));
            uint32_t h23 = f22u(__expf(s[nt][2] - mn1), __expf(s[nt][3] - mn1));
            float2 f01 = __half22float2(*(__half2*)&h01);
            float2 f23 = __half22float2(*(__half2*)&h23);
            ls0 += f01.x + f01.y; ls1 += f23.x + f23.y;
            int ks = nt >> 1;
            if ((nt & 1) == 0) { afp[ks][0] = h01; afp[ks][1] = h23; }
            else               { afp[ks][2] = h01; afp[ks][3] = h23; }
        }
#pragma unroll
        for (int off = 1; off < 4; off <<= 1) {
            ls0 += __shfl_xor_sync(0xffffffffu, ls0, off);
            ls1 += __shfl_xor_sync(0xffffffffu, ls1, off);
        }
        float al0 = __expf(m0 - mn0), al1 = __expf(m1 - mn1);
        l0 = l0 * al0 + ls0; l1 = l1 * al1 + ls1;
        m0 = mn0; m1 = mn1;
#pragma unroll
        for (int nt = 0; nt < 16; nt++) {
            o[nt][0] *= al0; o[nt][1] *= al0;
            o[nt][2] *= al1; o[nt][3] *= al1;
        }

        // ---- O += P V ----
#pragma unroll
        for (int ks = 0; ks < 4; ks++) {
#pragma unroll
            for (int g = 0; g < 8; g++) {
                uint32_t vf[4];
                ldsm_x4_t(vf, vst + (uint32_t)((ks * 16 + (m4 & 1) * 8 + r8) * KLH
                                               + g * 16 + (m4 >> 1) * 8) * 2);
                mma_f16(o[2 * g],     afp[ks], vf);
                mma_f16(o[2 * g + 1], afp[ks], vf + 2);
            }
        }
    }

    float i0 = 1.f / l0, i1 = 1.f / l1;
    int r0 = b * SEQ + q0 + wid * 16 + qr;
#pragma unroll
    for (int nt = 0; nt < 16; nt++) {
        int cc = h * DKH + nt * 8 + 2 * qc;
        *(__half2*)(O + (size_t)r0 * D_MODEL + cc) =
            __floats2half2_rn(o[nt][0] * i0, o[nt][1] * i0);
        *(__half2*)(O + (size_t)(r0 + 8) * D_MODEL + cc) =
            __floats2half2_rn(o[nt][2] * i1, o[nt][3] * i1);
    }
}

// ---------------- launch ----------------
extern "C" void kernel_launch(void* const* d_in, const int* in_sizes, int n_in,
                              void* d_out, int out_size) {
    const float* x  = (const float*)d_in[0];
    const float* Wq = (const float*)d_in[1];
    const float* Wk = (const float*)d_in[2];
    const float* Wv = (const float*)d_in[3];
    const float* Wo = (const float*)d_in[4];
    const float* W1 = (const float*)d_in[5];
    const float* W2 = (const float*)d_in[6];
    const float* W3 = (const float*)d_in[7];
    const float* g1 = (const float*)d_in[8];
    const float* g2 = (const float*)d_in[9];
    float* out = (float*)d_out;

    float *xmid;
    __half *xnh, *ctxh, *ffh, *qh, *kh, *vh;
    __half *wqh, *wkh, *wvh, *woh, *w1h, *w2h, *w3h;
    cudaGetSymbolAddress((void**)&xmid, g_xmid);
    cudaGetSymbolAddress((void**)&xnh,  g_xn_h);
    cudaGetSymbolAddress((void**)&ctxh, g_ctx_h);
    cudaGetSymbolAddress((void**)&ffh,  g_ff_h);
    cudaGetSymbolAddress((void**)&qh,   g_qh);
    cudaGetSymbolAddress((void**)&kh,   g_kh);
    cudaGetSymbolAddress((void**)&vh,   g_vh);
    cudaGetSymbolAddress((void**)&wqh,  g_wq);
    cudaGetSymbolAddress((void**)&wkh,  g_wk);
    cudaGetSymbolAddress((void**)&wvh,  g_wv);
    cudaGetSymbolAddress((void**)&woh,  g_wo);
    cudaGetSymbolAddress((void**)&w1h,  g_w1);
    cudaGetSymbolAddress((void**)&w2h,  g_w2);
    cudaGetSymbolAddress((void**)&w3h,  g_w3);

    cudaFuncSetAttribute(gemm_mma<1>, cudaFuncAttributeMaxDynamicSharedMemorySize, GEMM_SMEM);
    cudaFuncSetAttribute(gemm_mma<3>, cudaFuncAttributeMaxDynamicSharedMemorySize, GEMM_SMEM);
    cudaFuncSetAttribute(gemm_qkv,    cudaFuncAttributeMaxDynamicSharedMemorySize, GEMM_SMEM);
    cudaFuncSetAttribute(gemm_w13,    cudaFuncAttributeMaxDynamicSharedMemorySize, GEMM_SMEM);
    cudaFuncSetAttribute(attn_f16,    cudaFuncAttributeMaxDynamicSharedMemorySize, ATT_SMEM);

    // ---- side stream for weight conversion (graph-capture fork/join) ----
    cudaStream_t s2;
    cudaStreamCreateWithFlags(&s2, cudaStreamNonBlocking);
    cudaEvent_t evFork, evQKV, evW;
    cudaEventCreateWithFlags(&evFork, cudaEventDisableTiming);
    cudaEventCreateWithFlags(&evQKV,  cudaEventDisableTiming);
    cudaEventCreateWithFlags(&evW,    cudaEventDisableTiming);

    cudaEventRecord(evFork, 0);
    cudaStreamWaitEvent(s2, evFork, 0);

    const int CT = 256;
    int nDM = D_MODEL * D_MODEL / 4, nFF = DFF * D_MODEL / 4;
    f2h_kernel<<<(nDM + CT - 1) / CT, CT, 0, s2>>>((const float4*)Wq, (__half2*)wqh, nDM);
    f2h_kernel<<<(nDM + CT - 1) / CT, CT, 0, s2>>>((const float4*)Wk, (__half2*)wkh, nDM);
    f2h_kernel<<<(nDM + CT - 1) / CT, CT, 0, s2>>>((const float4*)Wv, (__half2*)wvh, nDM);
    cudaEventRecord(evQKV, s2);
    f2h_kernel<<<(nDM + CT - 1) / CT, CT, 0, s2>>>((const float4*)Wo, (__half2*)woh, nDM);
    f2h_kernel<<<(nFF + CT - 1) / CT, CT, 0, s2>>>((const float4*)W1, (__half2*)w1h, nFF);
    f2h_kernel<<<(nFF + CT - 1) / CT, CT, 0, s2>>>((const float4*)W3, (__half2*)w3h, nFF);
    f2h_kernel<<<(nFF + CT - 1) / CT, CT, 0, s2>>>((const float4*)W2, (__half2*)w2h, nFF);
    cudaEventRecord(evW, s2);

    dim3 blk(256);
    rmsnorm_kernel<<<M_TOK, 256>>>(x, g1, xnh);
    rope_table_kernel<<<(SEQ * 64 + 255) / 256, 256>>>();
    cudaStreamWaitEvent(0, evQKV, 0);
    dim3 gq(D_MODEL / GBN, M_TOK / GBM, 3);
    gemm_qkv<<<gq, blk, GEMM_SMEM>>>(xnh);
    dim3 gattn(SEQ / 64, BATCH * NHEAD);
    attn_f16<<<gattn, 128, ATT_SMEM>>>(qh, kh, vh, ctxh);
    cudaStreamWaitEvent(0, evW, 0);
    dim3 gdm(D_MODEL / GBN, M_TOK / GBM);
    gemm_mma<1><<<gdm, blk, GEMM_SMEM>>>(ctxh, woh, x, xmid, M_TOK, D_MODEL, D_MODEL);
    rmsnorm_kernel<<<M_TOK, 256>>>(xmid, g2, xnh);
    dim3 gw13(DFF / 64, M_TOK / 128);
    gemm_w13<<<gw13, blk, GEMM_SMEM>>>(xnh, ffh);
    gemm_mma<1><<<gdm, blk, GEMM_SMEM>>>(ffh, w2h, xmid, out, M_TOK, D_MODEL, DFF);
}